// round 2
// baseline (speedup 1.0000x reference)
#include <cuda_runtime.h>
#include <math.h>

#define H    512
#define H3   1536
#define S    48
#define T    48
#define B    32
#define VOUT 32000

// ---------------- device scratch (no allocations allowed) ----------------
__device__ float g_Gx_f[S*B*H3];     // encoder fwd input gates  (x@Wih^T + bih)
__device__ float g_Gx_b[S*B*H3];     // encoder bwd input gates
__device__ float g_Gd  [T*B*H3];     // decoder input gates
__device__ float g_outs_f[S*B*H];    // encoder fwd hidden per t
__device__ float g_outs_b[S*B*H];    // encoder bwd hidden per t
__device__ float g_enc_out[S*B*H];   // outs_f + outs_b
__device__ float g_hbuf[2*B*H];      // decoder hidden ping-pong
__device__ float g_ctx[B*H];         // attention context
__device__ float g_C[T*B*H];         // attentional hidden c[t] (pre-vocab)
__device__ int   g_dectok[T*B];      // decoder input tokens (SOS, targets shifted)

// ---------------- generic NT GEMM: C[m,n] = sum_k A[m,k]*Bw[n,k] + bias[n] ---
// Optional row-gather on A (A row = A + gidx[m]*K). Requires M%128==0, N%64==0, K%16==0.
#define BM 128
#define BN 64
#define BK 16

__global__ __launch_bounds__(256, 4)
void gemm_nt_kernel(const float* __restrict__ A, const int* __restrict__ gidx,
                    const float* __restrict__ Bw, const float* __restrict__ bias,
                    float* __restrict__ C, int N, int K)
{
    __shared__ float As[BK][BM + 4];
    __shared__ float Bs[BK][BN + 4];
    __shared__ int idx_s[BM];

    const int tid = threadIdx.x;
    const int m0 = blockIdx.y * BM;
    const int n0 = blockIdx.x * BN;

    if (gidx) {
        if (tid < BM) idx_s[tid] = gidx[m0 + tid];
        __syncthreads();
    }

    const int tx = tid & 15;   // n dim (16 * 4 = 64)
    const int ty = tid >> 4;   // m dim (16 * 8 = 128)

    float acc[8][4];
#pragma unroll
    for (int i = 0; i < 8; i++)
#pragma unroll
        for (int j = 0; j < 4; j++) acc[i][j] = 0.f;

    const int nIter = K / BK;
    for (int kt = 0; kt < nIter; kt++) {
        const int k0 = kt * BK;
        __syncthreads();
        // load A tile (128x16), transposed into As[k][m]
#pragma unroll
        for (int j = 0; j < 2; j++) {
            int id  = tid + j * 256;
            int row = id >> 2;
            int c4  = (id & 3) * 4;
            size_t arow = (size_t)(gidx ? idx_s[row] : (m0 + row)) * (size_t)K;
            float4 v = *(const float4*)(A + arow + k0 + c4);
            As[c4 + 0][row] = v.x; As[c4 + 1][row] = v.y;
            As[c4 + 2][row] = v.z; As[c4 + 3][row] = v.w;
        }
        // load B tile (64x16), transposed into Bs[k][n]
        {
            int row = tid >> 2;
            int c4  = (tid & 3) * 4;
            float4 v = *(const float4*)(Bw + (size_t)(n0 + row) * (size_t)K + k0 + c4);
            Bs[c4 + 0][row] = v.x; Bs[c4 + 1][row] = v.y;
            Bs[c4 + 2][row] = v.z; Bs[c4 + 3][row] = v.w;
        }
        __syncthreads();
#pragma unroll
        for (int k = 0; k < BK; k++) {
            float4 a0 = *(const float4*)&As[k][ty * 8];
            float4 a1 = *(const float4*)&As[k][ty * 8 + 4];
            float4 b0 = *(const float4*)&Bs[k][tx * 4];
            float am[8] = {a0.x, a0.y, a0.z, a0.w, a1.x, a1.y, a1.z, a1.w};
            float bn[4] = {b0.x, b0.y, b0.z, b0.w};
#pragma unroll
            for (int i = 0; i < 8; i++)
#pragma unroll
                for (int j = 0; j < 4; j++)
                    acc[i][j] = fmaf(am[i], bn[j], acc[i][j]);
        }
    }

    float4 bv = *(const float4*)(bias + n0 + tx * 4);
    float bb[4] = {bv.x, bv.y, bv.z, bv.w};
#pragma unroll
    for (int i = 0; i < 8; i++) {
        int m = m0 + ty * 8 + i;
        float4 o;
        o.x = acc[i][0] + bb[0];
        o.y = acc[i][1] + bb[1];
        o.z = acc[i][2] + bb[2];
        o.w = acc[i][3] + bb[3];
        *(float4*)(C + (size_t)m * (size_t)N + n0 + tx * 4) = o;
    }
}

// ---------------- fused GRU step: Gh = h@Whh^T + bhh, gates, h_new ----------
// One block = 8 h-columns x all 32 batch rows x 3 gates. Grid packs up to two
// independent problems (encoder fwd + bwd run in the same launch).
struct GruParams {
    const float* gx;     // [B, 3H] input gates for this t (includes bih)
    const float* hprev;  // [B, H] or nullptr (== zeros)
    const float* whh;    // [3H, H]
    const float* bhh;    // [3H]
    float*       hout;   // [B, H]
};

__global__ __launch_bounds__(256)
void gru_step_kernel(GruParams pa, GruParams pb, int blocksPerProb)
{
    GruParams p = (blockIdx.x < blocksPerProb) ? pa : pb;
    const int blk = blockIdx.x % blocksPerProb;
    const int h0  = blk * 8;
    const int tid = threadIdx.x;
    const int b   = tid >> 3;
    const int hi  = tid & 7;

    __shared__ float h_s[32][132];
    __shared__ float w_s[24][132];

    float ar = 0.f, az = 0.f, an = 0.f;

    for (int kc = 0; kc < 4; kc++) {
        const int k0 = kc * 128;
        __syncthreads();
        // h chunk: 32 rows x 128 cols
#pragma unroll
        for (int j = 0; j < 4; j++) {
            int id  = tid + j * 256;
            int row = id >> 5;
            int c4  = (id & 31) * 4;
            float4 v = p.hprev ? *(const float4*)(p.hprev + row * H + k0 + c4)
                               : make_float4(0.f, 0.f, 0.f, 0.f);
            *(float4*)&h_s[row][c4] = v;
        }
        // Whh chunk: rows (gate*8 + hi) -> global row gate*H + (h0+hi)
#pragma unroll
        for (int j = 0; j < 3; j++) {
            int id  = tid + j * 256;
            int row = id >> 5;                  // 0..23
            int c4  = (id & 31) * 4;
            int g   = row >> 3;
            int hh  = h0 + (row & 7);
            float4 v = *(const float4*)(p.whh + (size_t)(g * H + hh) * H + k0 + c4);
            *(float4*)&w_s[row][c4] = v;
        }
        __syncthreads();
#pragma unroll
        for (int c4 = 0; c4 < 128; c4 += 4) {
            float4 hv = *(const float4*)&h_s[b][c4];
            float4 wr = *(const float4*)&w_s[hi][c4];
            float4 wz = *(const float4*)&w_s[8 + hi][c4];
            float4 wn = *(const float4*)&w_s[16 + hi][c4];
            ar = fmaf(hv.x, wr.x, ar); ar = fmaf(hv.y, wr.y, ar);
            ar = fmaf(hv.z, wr.z, ar); ar = fmaf(hv.w, wr.w, ar);
            az = fmaf(hv.x, wz.x, az); az = fmaf(hv.y, wz.y, az);
            az = fmaf(hv.z, wz.z, az); az = fmaf(hv.w, wz.w, az);
            an = fmaf(hv.x, wn.x, an); an = fmaf(hv.y, wn.y, an);
            an = fmaf(hv.z, wn.z, an); an = fmaf(hv.w, wn.w, an);
        }
    }

    const int h = h0 + hi;
    float hr = ar + p.bhh[h];
    float hz = az + p.bhh[H + h];
    float hn = an + p.bhh[2 * H + h];
    const float* gx = p.gx + b * H3;
    float ir = gx[h], iz = gx[H + h], in_ = gx[2 * H + h];
    float hp = p.hprev ? p.hprev[b * H + h] : 0.f;
    float r = 1.f / (1.f + expf(-(ir + hr)));
    float z = 1.f / (1.f + expf(-(iz + hz)));
    float n = tanhf(in_ + r * hn);
    p.hout[b * H + h] = (1.f - z) * n + z * hp;
}

// ---------------- attention: scores + softmax + ctx, one block per batch row --
__global__ __launch_bounds__(256)
void attn_kernel(const float* __restrict__ h2, const float* __restrict__ enc,
                 float* __restrict__ ctx)
{
    const int b = blockIdx.x;
    const int tid = threadIdx.x;
    const int lane = tid & 31, w = tid >> 5;
    __shared__ float h2_s[H];
    __shared__ float sc[S];

    h2_s[tid]       = h2[b * H + tid];
    h2_s[tid + 256] = h2[b * H + tid + 256];
    __syncthreads();

    // scores[s] = dot(h2[b], enc[s][b])
    for (int s = w; s < S; s += 8) {
        const float4* e  = (const float4*)(enc + (size_t)(s * B + b) * H);
        const float4* h4 = (const float4*)h2_s;
        float p = 0.f;
#pragma unroll
        for (int j = 0; j < 4; j++) {
            float4 ev = e[lane + j * 32];
            float4 hv = h4[lane + j * 32];
            p = fmaf(ev.x, hv.x, p); p = fmaf(ev.y, hv.y, p);
            p = fmaf(ev.z, hv.z, p); p = fmaf(ev.w, hv.w, p);
        }
#pragma unroll
        for (int o = 16; o > 0; o >>= 1) p += __shfl_xor_sync(0xffffffffu, p, o);
        if (lane == 0) sc[s] = p;
    }
    __syncthreads();

    // softmax over 48 (one warp)
    if (w == 0) {
        float a   = sc[lane];
        float b2  = (lane < 16) ? sc[32 + lane] : -1e30f;
        float m = fmaxf(a, b2);
#pragma unroll
        for (int o = 16; o > 0; o >>= 1) m = fmaxf(m, __shfl_xor_sync(0xffffffffu, m, o));
        float ea = expf(a - m);
        float eb = (lane < 16) ? expf(b2 - m) : 0.f;
        float ss = ea + eb;
#pragma unroll
        for (int o = 16; o > 0; o >>= 1) ss += __shfl_xor_sync(0xffffffffu, ss, o);
        float inv = 1.f / ss;
        sc[lane] = ea * inv;
        if (lane < 16) sc[32 + lane] = eb * inv;
    }
    __syncthreads();

    // ctx[h] = sum_s attn[s]*enc[s][b][h]
    float a0 = 0.f, a1 = 0.f;
    for (int s = 0; s < S; s++) {
        float at = sc[s];
        const float* e = enc + (size_t)(s * B + b) * H;
        a0 = fmaf(at, e[tid], a0);
        a1 = fmaf(at, e[tid + 256], a1);
    }
    ctx[b * H + tid]       = a0;
    ctx[b * H + tid + 256] = a1;
}

// ---------------- c = tanh([h2, ctx] @ Wc^T + bc) ---------------------------
__global__ __launch_bounds__(256)
void cstep_kernel(const float* __restrict__ h2, const float* __restrict__ ctx,
                  const float* __restrict__ Wc, const float* __restrict__ bc,
                  float* __restrict__ cout)
{
    const int h0 = blockIdx.x * 8;
    const int tid = threadIdx.x;
    const int b = tid >> 3, hi = tid & 7;
    __shared__ float cat_s[32][132];
    __shared__ float w_s[8][132];
    float acc = 0.f;

    for (int kc = 0; kc < 8; kc++) {
        const int k0 = kc * 128;
        const float* src = (kc < 4) ? (h2 + k0) : (ctx + k0 - 512);
        __syncthreads();
#pragma unroll
        for (int j = 0; j < 4; j++) {
            int id = tid + j * 256;
            int row = id >> 5, c4 = (id & 31) * 4;
            *(float4*)&cat_s[row][c4] = *(const float4*)(src + row * H + c4);
        }
        {
            int row = tid >> 5, c4 = (tid & 31) * 4;  // 8 rows x 32 float4
            *(float4*)&w_s[row][c4] =
                *(const float4*)(Wc + (size_t)(h0 + row) * (2 * H) + k0 + c4);
        }
        __syncthreads();
#pragma unroll
        for (int c4 = 0; c4 < 128; c4 += 4) {
            float4 cv = *(const float4*)&cat_s[b][c4];
            float4 wv = *(const float4*)&w_s[hi][c4];
            acc = fmaf(cv.x, wv.x, acc); acc = fmaf(cv.y, wv.y, acc);
            acc = fmaf(cv.z, wv.z, acc); acc = fmaf(cv.w, wv.w, acc);
        }
    }
    const int h = h0 + hi;
    cout[b * H + h] = tanhf(acc + bc[h]);
}

// ---------------- small utilities -------------------------------------------
__global__ void combine_kernel(float* __restrict__ out, const float* __restrict__ a,
                               const float* __restrict__ b, int n)
{
    int i = blockIdx.x * blockDim.x + threadIdx.x;
    if (i < n) out[i] = a[i] + b[i];
}

__global__ void dectok_kernel(int* __restrict__ out, const int* __restrict__ target)
{
    int i = blockIdx.x * blockDim.x + threadIdx.x;
    if (i < T * B) out[i] = (i < B) ? 1 /*SOS*/ : target[i - B];
}

// ---------------- launch ------------------------------------------------------
extern "C" void kernel_launch(void* const* d_in, const int* in_sizes, int n_in,
                              void* d_out, int out_size)
{
    const int*   input_batches  = (const int*)d_in[0];
    const int*   target_batches = (const int*)d_in[1];
    const float* enc_emb   = (const float*)d_in[2];
    const float* enc_Wih_f = (const float*)d_in[3];
    const float* enc_Whh_f = (const float*)d_in[4];
    const float* enc_bih_f = (const float*)d_in[5];
    const float* enc_bhh_f = (const float*)d_in[6];
    const float* enc_Wih_b = (const float*)d_in[7];
    const float* enc_Whh_b = (const float*)d_in[8];
    const float* enc_bih_b = (const float*)d_in[9];
    const float* enc_bhh_b = (const float*)d_in[10];
    const float* dec_emb   = (const float*)d_in[11];
    const float* dec_Wih   = (const float*)d_in[12];
    const float* dec_Whh   = (const float*)d_in[13];
    const float* dec_bih   = (const float*)d_in[14];
    const float* dec_bhh   = (const float*)d_in[15];
    const float* Wc        = (const float*)d_in[16];
    const float* bc        = (const float*)d_in[17];
    const float* Wo        = (const float*)d_in[18];
    const float* bo        = (const float*)d_in[19];
    float* out = (float*)d_out;

    float *Gx_f, *Gx_b, *Gd, *outs_f, *outs_b, *enc_out, *hbuf, *ctx, *Cbuf;
    int* dectok;
    cudaGetSymbolAddress((void**)&Gx_f,   g_Gx_f);
    cudaGetSymbolAddress((void**)&Gx_b,   g_Gx_b);
    cudaGetSymbolAddress((void**)&Gd,     g_Gd);
    cudaGetSymbolAddress((void**)&outs_f, g_outs_f);
    cudaGetSymbolAddress((void**)&outs_b, g_outs_b);
    cudaGetSymbolAddress((void**)&enc_out,g_enc_out);
    cudaGetSymbolAddress((void**)&hbuf,   g_hbuf);
    cudaGetSymbolAddress((void**)&ctx,    g_ctx);
    cudaGetSymbolAddress((void**)&Cbuf,   g_C);
    cudaGetSymbolAddress((void**)&dectok, g_dectok);

    // decoder input tokens
    dectok_kernel<<<(T * B + 255) / 256, 256>>>(dectok, target_batches);

    // batched input-gate GEMMs (embedding gather fused into A row indexing)
    dim3 g1(H3 / BN, (S * B) / BM);
    gemm_nt_kernel<<<g1, 256>>>(enc_emb, input_batches, enc_Wih_f, enc_bih_f, Gx_f, H3, H);
    gemm_nt_kernel<<<g1, 256>>>(enc_emb, input_batches, enc_Wih_b, enc_bih_b, Gx_b, H3, H);
    gemm_nt_kernel<<<g1, 256>>>(dec_emb, dectok,        dec_Wih,   dec_bih,   Gd,   H3, H);

    // encoder scan: fwd step i and bwd step (S-1-i) fused in one launch
    for (int i = 0; i < S; i++) {
        int tb = S - 1 - i;
        GruParams pf { Gx_f + (size_t)i * B * H3,
                       i ? outs_f + (size_t)(i - 1) * B * H : nullptr,
                       enc_Whh_f, enc_bhh_f,
                       outs_f + (size_t)i * B * H };
        GruParams pk { Gx_b + (size_t)tb * B * H3,
                       i ? outs_b + (size_t)(tb + 1) * B * H : nullptr,
                       enc_Whh_b, enc_bhh_b,
                       outs_b + (size_t)tb * B * H };
        gru_step_kernel<<<128, 256>>>(pf, pk, 64);
    }
    combine_kernel<<<(S * B * H + 255) / 256, 256>>>(enc_out, outs_f, outs_b, S * B * H);

    // decoder scan: GRU step -> attention -> Wc+tanh (c collected; vocab GEMM deferred)
    for (int t = 0; t < T; t++) {
        const float* hprev = (t == 0) ? (outs_f + (size_t)(S - 1) * B * H)
                                      : (hbuf + (size_t)((t - 1) & 1) * B * H);
        float* h2 = hbuf + (size_t)(t & 1) * B * H;
        GruParams pd { Gd + (size_t)t * B * H3, hprev, dec_Whh, dec_bhh, h2 };
        gru_step_kernel<<<64, 256>>>(pd, pd, 64);
        attn_kernel<<<B, 256>>>(h2, enc_out, ctx);
        cstep_kernel<<<H / 8, 256>>>(h2, ctx, Wc, bc, Cbuf + (size_t)t * B * H);
    }

    // the big one: logits[T*B, VOUT] = C @ Wo^T + bo
    dim3 g2(VOUT / BN, (T * B) / BM);
    gemm_nt_kernel<<<g2, 256>>>(Cbuf, nullptr, Wo, bo, out, VOUT, H);
}

// round 3
// speedup vs baseline: 1.2095x; 1.2095x over previous
#include <cuda_runtime.h>
#include <math.h>

#define H    512
#define H3   1536
#define S    48
#define T    48
#define B    32
#define VOUT 32000

typedef unsigned long long ull;

// ---------------- packed f32x2 helpers (sm_103a FFMA2 path) ----------------
__device__ __forceinline__ ull pk2(float x, float y) {
    ull r; asm("mov.b64 %0, {%1,%2};" : "=l"(r) : "f"(x), "f"(y)); return r;
}
__device__ __forceinline__ void fma2(ull& d, ull a, ull b) {
    asm("fma.rn.f32x2 %0, %1, %2, %0;" : "+l"(d) : "l"(a), "l"(b));
}
__device__ __forceinline__ float2 upk(ull v) {
    float lo, hi; asm("mov.b64 {%0,%1}, %2;" : "=f"(lo), "=f"(hi) : "l"(v));
    float2 f; f.x = lo; f.y = hi; return f;
}

// ---------------- device scratch ----------------
__device__ float g_Gx_f[S*B*H3];
__device__ float g_Gx_b[S*B*H3];
__device__ float g_Gd  [T*B*H3];
__device__ float g_outs_f[S*B*H];
__device__ float g_outs_b[S*B*H];
__device__ float g_enc_out[S*B*H];
__device__ float g_Hdec[T*B*H];
__device__ float g_Ctx [T*B*H];
__device__ float g_C   [T*B*H];
__device__ int   g_dectok[T*B];
__device__ unsigned g_bars[2];

// ---------------- grid barrier for persistent scan kernels ----------------
__device__ __forceinline__ void grid_bar(unsigned* bar, unsigned target) {
    __threadfence();
    __syncthreads();
    if (threadIdx.x == 0) {
        atomicAdd(bar, 1u);
        while (*(volatile unsigned*)bar < target) { __nanosleep(64); }
        __threadfence();
    }
    __syncthreads();
}

// ---------------- GEMM NT: C[m,n] = sum_k A[m,k]*Bw[n,k] + bias[n] ----------
// A row stride fixed at 512; k>=512 rows come from A2 (split-K concat).
// Optional row gather via gidx. Optional tanh epilogue. M%128==0, N%128==0, K%8==0.
#define BM 128
#define BN 128
#define BK 8

__global__ __launch_bounds__(256, 2)
void gemm_nt_kernel(const float* __restrict__ A, const float* __restrict__ A2,
                    const int* __restrict__ gidx,
                    const float* __restrict__ Bw, const float* __restrict__ bias,
                    float* __restrict__ C, int N, int K, int act)
{
    __shared__ float As[2][BK][BM + 4];
    __shared__ float Bs[2][BK][BN + 4];
    __shared__ int idx_s[BM];

    const int tid = threadIdx.x;
    const int m0 = blockIdx.y * BM;
    const int n0 = blockIdx.x * BN;

    if (gidx) {
        if (tid < BM) idx_s[tid] = gidx[m0 + tid];
        __syncthreads();
    }

    const int lrow = tid >> 1;
    const int lk   = (tid & 1) * 4;
    const size_t arowoff = (size_t)(gidx ? idx_s[lrow] : (m0 + lrow)) * 512;
    const float* bptr = Bw + (size_t)(n0 + lrow) * (size_t)K;

    const int tx = tid & 15;   // n
    const int ty = tid >> 4;   // m

    ull acc[8][4];
#pragma unroll
    for (int i = 0; i < 8; i++)
#pragma unroll
        for (int j = 0; j < 4; j++) acc[i][j] = 0ull;

    float4 va, vb;
    {   // tile 0
        const float* abase = A;  // k0=0 < 512 always
        va = *(const float4*)(abase + arowoff + lk);
        vb = *(const float4*)(bptr + lk);
        As[0][lk+0][lrow] = va.x; As[0][lk+1][lrow] = va.y;
        As[0][lk+2][lrow] = va.z; As[0][lk+3][lrow] = va.w;
        Bs[0][lk+0][lrow] = vb.x; Bs[0][lk+1][lrow] = vb.y;
        Bs[0][lk+2][lrow] = vb.z; Bs[0][lk+3][lrow] = vb.w;
    }
    __syncthreads();

    const int nkt = K / BK;
    for (int kt = 0; kt < nkt; kt++) {
        const int buf = kt & 1;
        if (kt + 1 < nkt) {
            int k0 = (kt + 1) * BK;
            const float* abase = (k0 < 512) ? A : A2;
            int kk = (k0 < 512) ? k0 : (k0 - 512);
            va = *(const float4*)(abase + arowoff + kk + lk);
            vb = *(const float4*)(bptr + k0 + lk);
        }
#pragma unroll
        for (int k = 0; k < BK; k++) {
            float4 a0 = *(const float4*)&As[buf][k][ty * 4];
            float4 a1 = *(const float4*)&As[buf][k][64 + ty * 4];
            float4 b0 = *(const float4*)&Bs[buf][k][tx * 4];
            float4 b1 = *(const float4*)&Bs[buf][k][64 + tx * 4];
            ull p0 = pk2(b0.x, b0.y), p1 = pk2(b0.z, b0.w);
            ull p2 = pk2(b1.x, b1.y), p3 = pk2(b1.z, b1.w);
            float am[8] = {a0.x, a0.y, a0.z, a0.w, a1.x, a1.y, a1.z, a1.w};
#pragma unroll
            for (int i = 0; i < 8; i++) {
                ull ad = pk2(am[i], am[i]);
                fma2(acc[i][0], ad, p0); fma2(acc[i][1], ad, p1);
                fma2(acc[i][2], ad, p2); fma2(acc[i][3], ad, p3);
            }
        }
        if (kt + 1 < nkt) {
            const int nb = (kt + 1) & 1;
            As[nb][lk+0][lrow] = va.x; As[nb][lk+1][lrow] = va.y;
            As[nb][lk+2][lrow] = va.z; As[nb][lk+3][lrow] = va.w;
            Bs[nb][lk+0][lrow] = vb.x; Bs[nb][lk+1][lrow] = vb.y;
            Bs[nb][lk+2][lrow] = vb.z; Bs[nb][lk+3][lrow] = vb.w;
        }
        __syncthreads();
    }

    float4 bb0 = *(const float4*)(bias + n0 + tx * 4);
    float4 bb1 = *(const float4*)(bias + n0 + 64 + tx * 4);
#pragma unroll
    for (int i = 0; i < 8; i++) {
        int m = (i < 4) ? (m0 + ty * 4 + i) : (m0 + 64 + ty * 4 + (i - 4));
        float2 c0 = upk(acc[i][0]), c1 = upk(acc[i][1]);
        float2 c2 = upk(acc[i][2]), c3 = upk(acc[i][3]);
        float4 o0, o1;
        o0.x = c0.x + bb0.x; o0.y = c0.y + bb0.y; o0.z = c1.x + bb0.z; o0.w = c1.y + bb0.w;
        o1.x = c2.x + bb1.x; o1.y = c2.y + bb1.y; o1.z = c3.x + bb1.z; o1.w = c3.y + bb1.w;
        if (act) {
            o0.x = tanhf(o0.x); o0.y = tanhf(o0.y); o0.z = tanhf(o0.z); o0.w = tanhf(o0.w);
            o1.x = tanhf(o1.x); o1.y = tanhf(o1.y); o1.z = tanhf(o1.z); o1.w = tanhf(o1.w);
        }
        *(float4*)(C + (size_t)m * (size_t)N + n0 + tx * 4) = o0;
        *(float4*)(C + (size_t)m * (size_t)N + n0 + 64 + tx * 4) = o1;
    }
}

// ---------------- persistent GRU scan (whole sequence, grid-barrier/step) ---
struct ScanProb {
    const float* gx;    // [nsteps][B][H3] (includes bih)
    const float* seed;  // initial hidden [B,H] or null (zeros)
    const float* whh;   // [3H, H]
    const float* bhh;   // [3H]
    float*       outs;  // [nsteps][B][H]
    int          dir;   // 0 fwd, 1 bwd
};

__global__ __launch_bounds__(256)
void gru_scan_kernel(ScanProb pa, ScanProb pb, int bpp, int nsteps,
                     unsigned nblocks, unsigned* bar)
{
    extern __shared__ float w_s[];   // [24][516]
    ScanProb p = (blockIdx.x < bpp) ? pa : pb;
    const int blk = blockIdx.x % bpp;
    const int h0  = blk * 8;
    const int tid = threadIdx.x;
    const int b   = tid >> 3;
    const int hi  = tid & 7;

    // cache this block's 24 Whh rows (3 gates x 8 h-cols) in SMEM once
    for (int id = tid; id < 24 * 128; id += 256) {
        int row = id >> 7, c4 = (id & 127) * 4;
        int g = row >> 3, hh = h0 + (row & 7);
        *(float4*)&w_s[row * 516 + c4] =
            *(const float4*)(p.whh + (size_t)(g * H + hh) * H + c4);
    }
    __syncthreads();

    const ull* wr2 = (const ull*)&w_s[hi * 516];
    const ull* wz2 = (const ull*)&w_s[(8 + hi) * 516];
    const ull* wn2 = (const ull*)&w_s[(16 + hi) * 516];

    const int h = h0 + hi;
    const float br = p.bhh[h], bz = p.bhh[H + h], bn = p.bhh[2 * H + h];

    for (int i = 0; i < nsteps; i++) {
        const int t = p.dir ? (nsteps - 1 - i) : i;
        const float* hprev = (i == 0) ? p.seed
                           : p.outs + (size_t)(p.dir ? t + 1 : t - 1) * B * H;
        ull ar2 = 0, az2 = 0, an2 = 0;
        float hp_val = 0.f;
        if (hprev) {
            const float4* hp4 = (const float4*)(hprev + b * H);
#pragma unroll 8
            for (int c = 0; c < 128; c++) {
                float4 hv = __ldg(&hp4[c]);
                ull h01 = pk2(hv.x, hv.y), h23 = pk2(hv.z, hv.w);
                fma2(ar2, h01, wr2[2*c]); fma2(ar2, h23, wr2[2*c+1]);
                fma2(az2, h01, wz2[2*c]); fma2(az2, h23, wz2[2*c+1]);
                fma2(an2, h01, wn2[2*c]); fma2(an2, h23, wn2[2*c+1]);
            }
            hp_val = __ldg(hprev + b * H + h);
        }
        float2 fr = upk(ar2), fz = upk(az2), fn = upk(an2);
        const float* gx = p.gx + ((size_t)t * B + b) * H3;
        float r = 1.f / (1.f + expf(-(gx[h]       + fr.x + fr.y + br)));
        float z = 1.f / (1.f + expf(-(gx[H + h]   + fz.x + fz.y + bz)));
        float n = tanhf(gx[2 * H + h] + r * (fn.x + fn.y + bn));
        p.outs[((size_t)t * B + b) * H + h] = (1.f - z) * n + z * hp_val;

        if (i < nsteps - 1) grid_bar(bar, nblocks * (unsigned)(i + 1));
    }
}

// ---------------- batched attention: all (t,b) in parallel ------------------
__global__ __launch_bounds__(256)
void attn_kernel(const float* __restrict__ Hdec, const float* __restrict__ enc,
                 float* __restrict__ Ctx)
{
    const int t = blockIdx.x / B;
    const int b = blockIdx.x % B;
    const float* h2 = Hdec + ((size_t)t * B + b) * H;
    const int tid = threadIdx.x;
    const int lane = tid & 31, w = tid >> 5;
    __shared__ float h2_s[H];
    __shared__ float sc[S];

    h2_s[tid]       = h2[tid];
    h2_s[tid + 256] = h2[tid + 256];
    __syncthreads();

    for (int s = w; s < S; s += 8) {
        const float4* e  = (const float4*)(enc + (size_t)(s * B + b) * H);
        const float4* h4 = (const float4*)h2_s;
        float p = 0.f;
#pragma unroll
        for (int j = 0; j < 4; j++) {
            float4 ev = e[lane + j * 32];
            float4 hv = h4[lane + j * 32];
            p = fmaf(ev.x, hv.x, p); p = fmaf(ev.y, hv.y, p);
            p = fmaf(ev.z, hv.z, p); p = fmaf(ev.w, hv.w, p);
        }
#pragma unroll
        for (int o = 16; o > 0; o >>= 1) p += __shfl_xor_sync(0xffffffffu, p, o);
        if (lane == 0) sc[s] = p;
    }
    __syncthreads();

    if (w == 0) {
        float a  = sc[lane];
        float b2 = (lane < 16) ? sc[32 + lane] : -1e30f;
        float m = fmaxf(a, b2);
#pragma unroll
        for (int o = 16; o > 0; o >>= 1) m = fmaxf(m, __shfl_xor_sync(0xffffffffu, m, o));
        float ea = expf(a - m);
        float eb = (lane < 16) ? expf(b2 - m) : 0.f;
        float ss = ea + eb;
#pragma unroll
        for (int o = 16; o > 0; o >>= 1) ss += __shfl_xor_sync(0xffffffffu, ss, o);
        float inv = 1.f / ss;
        sc[lane] = ea * inv;
        if (lane < 16) sc[32 + lane] = eb * inv;
    }
    __syncthreads();

    float a0 = 0.f, a1 = 0.f;
    for (int s = 0; s < S; s++) {
        float at = sc[s];
        const float* e = enc + (size_t)(s * B + b) * H;
        a0 = fmaf(at, e[tid], a0);
        a1 = fmaf(at, e[tid + 256], a1);
    }
    float* co = Ctx + ((size_t)t * B + b) * H;
    co[tid]       = a0;
    co[tid + 256] = a1;
}

// ---------------- small utilities -------------------------------------------
__global__ void combine_kernel(float* __restrict__ out, const float* __restrict__ a,
                               const float* __restrict__ b, int n)
{
    int i = blockIdx.x * blockDim.x + threadIdx.x;
    if (i < n) out[i] = a[i] + b[i];
}

__global__ void init_kernel(int* __restrict__ out, const int* __restrict__ target,
                            unsigned* __restrict__ bars)
{
    int i = blockIdx.x * blockDim.x + threadIdx.x;
    if (i < 2) bars[i] = 0u;
    if (i < T * B) out[i] = (i < B) ? 1 /*SOS*/ : target[i - B];
}

// ---------------- launch ------------------------------------------------------
extern "C" void kernel_launch(void* const* d_in, const int* in_sizes, int n_in,
                              void* d_out, int out_size)
{
    const int*   input_batches  = (const int*)d_in[0];
    const int*   target_batches = (const int*)d_in[1];
    const float* enc_emb   = (const float*)d_in[2];
    const float* enc_Wih_f = (const float*)d_in[3];
    const float* enc_Whh_f = (const float*)d_in[4];
    const float* enc_bih_f = (const float*)d_in[5];
    const float* enc_bhh_f = (const float*)d_in[6];
    const float* enc_Wih_b = (const float*)d_in[7];
    const float* enc_Whh_b = (const float*)d_in[8];
    const float* enc_bih_b = (const float*)d_in[9];
    const float* enc_bhh_b = (const float*)d_in[10];
    const float* dec_emb   = (const float*)d_in[11];
    const float* dec_Wih   = (const float*)d_in[12];
    const float* dec_Whh   = (const float*)d_in[13];
    const float* dec_bih   = (const float*)d_in[14];
    const float* dec_bhh   = (const float*)d_in[15];
    const float* Wc        = (const float*)d_in[16];
    const float* bc        = (const float*)d_in[17];
    const float* Wo        = (const float*)d_in[18];
    const float* bo        = (const float*)d_in[19];
    float* out = (float*)d_out;

    float *Gx_f, *Gx_b, *Gd, *outs_f, *outs_b, *enc_out, *Hdec, *Ctx, *Cbuf;
    int* dectok; unsigned* bars;
    cudaGetSymbolAddress((void**)&Gx_f,   g_Gx_f);
    cudaGetSymbolAddress((void**)&Gx_b,   g_Gx_b);
    cudaGetSymbolAddress((void**)&Gd,     g_Gd);
    cudaGetSymbolAddress((void**)&outs_f, g_outs_f);
    cudaGetSymbolAddress((void**)&outs_b, g_outs_b);
    cudaGetSymbolAddress((void**)&enc_out,g_enc_out);
    cudaGetSymbolAddress((void**)&Hdec,   g_Hdec);
    cudaGetSymbolAddress((void**)&Ctx,    g_Ctx);
    cudaGetSymbolAddress((void**)&Cbuf,   g_C);
    cudaGetSymbolAddress((void**)&dectok, g_dectok);
    cudaGetSymbolAddress((void**)&bars,   g_bars);

    const int WSMEM = 24 * 516 * 4;
    cudaFuncSetAttribute(gru_scan_kernel,
                         cudaFuncAttributeMaxDynamicSharedMemorySize, WSMEM);

    init_kernel<<<(T * B + 255) / 256, 256>>>(dectok, target_batches, bars);

    // input-gate GEMMs (embedding gather fused via row index)
    dim3 g1(H3 / BN, (S * B) / BM);
    gemm_nt_kernel<<<g1, 256>>>(enc_emb, enc_emb, input_batches, enc_Wih_f, enc_bih_f, Gx_f, H3, H, 0);
    gemm_nt_kernel<<<g1, 256>>>(enc_emb, enc_emb, input_batches, enc_Wih_b, enc_bih_b, Gx_b, H3, H, 0);
    gemm_nt_kernel<<<g1, 256>>>(dec_emb, dec_emb, dectok,        dec_Wih,   dec_bih,   Gd,   H3, H, 0);

    // encoder: fwd + bwd scans fused in one persistent kernel
    ScanProb pf { Gx_f, nullptr, enc_Whh_f, enc_bhh_f, outs_f, 0 };
    ScanProb pk { Gx_b, nullptr, enc_Whh_b, enc_bhh_b, outs_b, 1 };
    gru_scan_kernel<<<128, 256, WSMEM>>>(pf, pk, 64, S, 128u, bars + 0);

    combine_kernel<<<(S * B * H + 255) / 256, 256>>>(enc_out, outs_f, outs_b, S * B * H);

    // decoder GRU chain (only sequential dependency): persistent kernel
    ScanProb pd { Gd, outs_f + (size_t)(S - 1) * B * H, dec_Whh, dec_bhh, Hdec, 0 };
    gru_scan_kernel<<<64, 256, WSMEM>>>(pd, pd, 64, T, 64u, bars + 1);

    // batched attention over all (t, b)
    attn_kernel<<<T * B, 256>>>(Hdec, enc_out, Ctx);

    // c = tanh([h2, ctx] @ Wc^T + bc) as one batched GEMM (split-A concat)
    dim3 g2(H / BN, (T * B) / BM);
    gemm_nt_kernel<<<g2, 256>>>(Hdec, Ctx, nullptr, Wc, bc, Cbuf, H, 2 * H, 1);

    // vocab projection: logits = C @ Wo^T + bo
    dim3 g3(VOUT / BN, (T * B) / BM);
    gemm_nt_kernel<<<g3, 256>>>(Cbuf, Cbuf, nullptr, Wo, bo, out, VOUT, H, 0);
}

// round 5
// speedup vs baseline: 1.5276x; 1.2629x over previous
#include <cuda_runtime.h>
#include <cuda_bf16.h>
#include <math.h>
#include <stdint.h>

#define H    512
#define H3   1536
#define S    48
#define T    48
#define B    32
#define VOUT 32000

typedef unsigned long long ull;

// ---------------- packed f32x2 helpers ----------------
__device__ __forceinline__ ull pk2(float x, float y) {
    ull r; asm("mov.b64 %0, {%1,%2};" : "=l"(r) : "f"(x), "f"(y)); return r;
}
__device__ __forceinline__ void fma2(ull& d, ull a, ull b) {
    asm("fma.rn.f32x2 %0, %1, %2, %0;" : "+l"(d) : "l"(a), "l"(b));
}
__device__ __forceinline__ float2 upk(ull v) {
    float lo, hi; asm("mov.b64 {%0,%1}, %2;" : "=f"(lo), "=f"(hi) : "l"(v));
    float2 f; f.x = lo; f.y = hi; return f;
}

// ---------------- mma.sync helpers (arch-agnostic tensor path) --------------
__device__ __forceinline__ uint32_t smem_u32(const void* p) {
    uint32_t a;
    asm("{ .reg .u64 t; cvta.to.shared.u64 t, %1; cvt.u32.u64 %0, t; }" : "=r"(a) : "l"(p));
    return a;
}
#define LDSM4(r0, r1, r2, r3, addr) \
    asm volatile("ldmatrix.sync.aligned.m8n8.x4.shared.b16 {%0,%1,%2,%3}, [%4];" \
        : "=r"(r0), "=r"(r1), "=r"(r2), "=r"(r3) : "r"(addr))
#define MMA16816(d, a0, a1, a2, a3, b0, b1) \
    asm volatile("mma.sync.aligned.m16n8k16.row.col.f32.bf16.bf16.f32 " \
        "{%0,%1,%2,%3}, {%4,%5,%6,%7}, {%8,%9}, {%0,%1,%2,%3};" \
        : "+f"((d)[0]), "+f"((d)[1]), "+f"((d)[2]), "+f"((d)[3]) \
        : "r"(a0), "r"(a1), "r"(a2), "r"(a3), "r"(b0), "r"(b1))
__device__ __forceinline__ void cp16(uint32_t dst, const void* src) {
    asm volatile("cp.async.cg.shared.global [%0], [%1], 16;" :: "r"(dst), "l"(src));
}
#define CP_COMMIT() asm volatile("cp.async.commit_group;" ::: "memory")
#define CP_WAIT(n)  asm volatile("cp.async.wait_group %0;" :: "n"(n) : "memory")

// ---------------- device scratch ----------------
__device__ float g_Gx_f[S*B*H3];
__device__ float g_Gx_b[S*B*H3];
__device__ float g_Gd  [T*B*H3];
__device__ float g_outs_f[S*B*H];
__device__ float g_outs_b[S*B*H];
__device__ float g_enc_out[S*B*H];
__device__ float g_Hdec[T*B*H];
__device__ float g_Ctx [T*B*H];
__device__ float g_C   [T*B*H];
__device__ int   g_dectok[T*B];
__device__ unsigned g_bars[2];
__device__ __nv_bfloat16 g_A3[(size_t)T*B*H3];   // split C:  [hi, lo, hi]
__device__ __nv_bfloat16 g_B3[(size_t)VOUT*H3];  // split Wo: [hi, hi, lo]

// ---------------- grid barrier ----------------
__device__ __forceinline__ void grid_bar(unsigned* bar, unsigned target) {
    __threadfence();
    __syncthreads();
    if (threadIdx.x == 0) {
        atomicAdd(bar, 1u);
        while (*(volatile unsigned*)bar < target) { __nanosleep(64); }
        __threadfence();
    }
    __syncthreads();
}

// ---------------- FFMA2 GEMM (input gates, Wc) ------------------------------
#define BM 128
#define BN 128
#define BK 8

__global__ __launch_bounds__(256, 2)
void gemm_nt_kernel(const float* __restrict__ A, const float* __restrict__ A2,
                    const int* __restrict__ gidx,
                    const float* __restrict__ Bw, const float* __restrict__ bias,
                    float* __restrict__ C, int N, int K, int act)
{
    __shared__ float As[2][BK][BM + 4];
    __shared__ float Bs[2][BK][BN + 4];
    __shared__ int idx_s[BM];

    const int tid = threadIdx.x;
    const int m0 = blockIdx.y * BM;
    const int n0 = blockIdx.x * BN;

    if (gidx) {
        if (tid < BM) idx_s[tid] = gidx[m0 + tid];
        __syncthreads();
    }

    const int lrow = tid >> 1;
    const int lk   = (tid & 1) * 4;
    const size_t arowoff = (size_t)(gidx ? idx_s[lrow] : (m0 + lrow)) * 512;
    const float* bptr = Bw + (size_t)(n0 + lrow) * (size_t)K;

    const int tx = tid & 15;
    const int ty = tid >> 4;

    ull acc[8][4];
#pragma unroll
    for (int i = 0; i < 8; i++)
#pragma unroll
        for (int j = 0; j < 4; j++) acc[i][j] = 0ull;

    float4 va, vb;
    {
        va = *(const float4*)(A + arowoff + lk);
        vb = *(const float4*)(bptr + lk);
        As[0][lk+0][lrow] = va.x; As[0][lk+1][lrow] = va.y;
        As[0][lk+2][lrow] = va.z; As[0][lk+3][lrow] = va.w;
        Bs[0][lk+0][lrow] = vb.x; Bs[0][lk+1][lrow] = vb.y;
        Bs[0][lk+2][lrow] = vb.z; Bs[0][lk+3][lrow] = vb.w;
    }
    __syncthreads();

    const int nkt = K / BK;
    for (int kt = 0; kt < nkt; kt++) {
        const int buf = kt & 1;
        if (kt + 1 < nkt) {
            int k0 = (kt + 1) * BK;
            const float* abase = (k0 < 512) ? A : A2;
            int kk = (k0 < 512) ? k0 : (k0 - 512);
            va = *(const float4*)(abase + arowoff + kk + lk);
            vb = *(const float4*)(bptr + k0 + lk);
        }
#pragma unroll
        for (int k = 0; k < BK; k++) {
            float4 a0 = *(const float4*)&As[buf][k][ty * 4];
            float4 a1 = *(const float4*)&As[buf][k][64 + ty * 4];
            float4 b0 = *(const float4*)&Bs[buf][k][tx * 4];
            float4 b1 = *(const float4*)&Bs[buf][k][64 + tx * 4];
            ull p0 = pk2(b0.x, b0.y), p1 = pk2(b0.z, b0.w);
            ull p2 = pk2(b1.x, b1.y), p3 = pk2(b1.z, b1.w);
            float am[8] = {a0.x, a0.y, a0.z, a0.w, a1.x, a1.y, a1.z, a1.w};
#pragma unroll
            for (int i = 0; i < 8; i++) {
                ull ad = pk2(am[i], am[i]);
                fma2(acc[i][0], ad, p0); fma2(acc[i][1], ad, p1);
                fma2(acc[i][2], ad, p2); fma2(acc[i][3], ad, p3);
            }
        }
        if (kt + 1 < nkt) {
            const int nb = (kt + 1) & 1;
            As[nb][lk+0][lrow] = va.x; As[nb][lk+1][lrow] = va.y;
            As[nb][lk+2][lrow] = va.z; As[nb][lk+3][lrow] = va.w;
            Bs[nb][lk+0][lrow] = vb.x; Bs[nb][lk+1][lrow] = vb.y;
            Bs[nb][lk+2][lrow] = vb.z; Bs[nb][lk+3][lrow] = vb.w;
        }
        __syncthreads();
    }

    float4 bb0 = *(const float4*)(bias + n0 + tx * 4);
    float4 bb1 = *(const float4*)(bias + n0 + 64 + tx * 4);
#pragma unroll
    for (int i = 0; i < 8; i++) {
        int m = (i < 4) ? (m0 + ty * 4 + i) : (m0 + 64 + ty * 4 + (i - 4));
        float2 c0 = upk(acc[i][0]), c1 = upk(acc[i][1]);
        float2 c2 = upk(acc[i][2]), c3 = upk(acc[i][3]);
        float4 o0, o1;
        o0.x = c0.x + bb0.x; o0.y = c0.y + bb0.y; o0.z = c1.x + bb0.z; o0.w = c1.y + bb0.w;
        o1.x = c2.x + bb1.x; o1.y = c2.y + bb1.y; o1.z = c3.x + bb1.z; o1.w = c3.y + bb1.w;
        if (act) {
            o0.x = tanhf(o0.x); o0.y = tanhf(o0.y); o0.z = tanhf(o0.z); o0.w = tanhf(o0.w);
            o1.x = tanhf(o1.x); o1.y = tanhf(o1.y); o1.z = tanhf(o1.z); o1.w = tanhf(o1.w);
        }
        *(float4*)(C + (size_t)m * (size_t)N + n0 + tx * 4) = o0;
        *(float4*)(C + (size_t)m * (size_t)N + n0 + 64 + tx * 4) = o1;
    }
}

// ---------------- fp32 -> bf16 hi/lo split (3-rep layout) -------------------
// mode 0 (A): segments [hi, lo, hi] ; mode 1 (B): segments [hi, hi, lo]
__global__ __launch_bounds__(256)
void split_kernel(const float* __restrict__ src, __nv_bfloat16* __restrict__ dst,
                  int nrows, int mode)
{
    int idx = blockIdx.x * 256 + threadIdx.x;
    if (idx >= nrows * 128) return;
    int row = idx >> 7, c4 = (idx & 127) << 2;
    float4 v = *(const float4*)(src + (size_t)row * 512 + c4);
    float f[4] = {v.x, v.y, v.z, v.w};
    __nv_bfloat16 h[4], l[4];
#pragma unroll
    for (int i = 0; i < 4; i++) {
        h[i] = __float2bfloat16(f[i]);
        l[i] = __float2bfloat16(f[i] - __bfloat162float(h[i]));
    }
    __nv_bfloat162 h01, h23, l01, l23;
    h01.x = h[0]; h01.y = h[1]; h23.x = h[2]; h23.y = h[3];
    l01.x = l[0]; l01.y = l[1]; l23.x = l[2]; l23.y = l[3];
    __nv_bfloat162* d0 = (__nv_bfloat162*)(dst + (size_t)row * H3 + c4);
    __nv_bfloat162* d1 = (__nv_bfloat162*)(dst + (size_t)row * H3 + 512 + c4);
    __nv_bfloat162* d2 = (__nv_bfloat162*)(dst + (size_t)row * H3 + 1024 + c4);
    d0[0] = h01; d0[1] = h23;
    if (mode == 0) { d1[0] = l01; d1[1] = l23; d2[0] = h01; d2[1] = h23; }
    else           { d1[0] = h01; d1[1] = h23; d2[0] = l01; d2[1] = l23; }
}

// ---------------- mma.sync bf16 NT GEMM: out = A3 @ B3^T + bo ---------------
// Tile 128x128x64, cp.async double buffer, ldmatrix + mma.m16n8k16.
// SMEM: A0 @0, B0 @16384, A1 @32768, B1 @49152 (each tile 128 rows x 128B, SW128 xor)
#define MM_NKT (H3 / 64)   // 24

__global__ __launch_bounds__(256)
void gemm_mma_kernel(const __nv_bfloat16* __restrict__ A3,
                     const __nv_bfloat16* __restrict__ B3,
                     const float* __restrict__ bo, float* __restrict__ out)
{
    extern __shared__ __align__(1024) char smem[];
    const int tid  = threadIdx.x;
    const int wid  = tid >> 5;
    const int lane = tid & 31;
    const int m0 = blockIdx.x * 128;
    const int n0 = blockIdx.y * 128;
    const int warp_m = wid & 3;       // 4 warps over m (32 rows each)
    const int warp_n = wid >> 2;      // 2 warps over n (64 cols each)
    const uint32_t sb = smem_u32(smem);

    const char* Ag = (const char*)A3 + (size_t)m0 * 3072;
    const char* Bg = (const char*)B3 + (size_t)n0 * 3072;

    // loader coords: 1024 16B-chunks per tile, 4 per thread
    const int lr = tid >> 1;                 // used below via id decomposition
    (void)lr;

    float d[2][8][4];
#pragma unroll
    for (int i = 0; i < 2; i++)
#pragma unroll
        for (int j = 0; j < 8; j++)
#pragma unroll
            for (int q = 0; q < 4; q++) d[i][j][q] = 0.f;

    // ldmatrix per-lane row constants
    const int a_row0 = warp_m * 32 + (lane & 15);
    const int a_row1 = a_row0 + 16;
    const int a_cb   = lane >> 4;                              // 0/1
    const int b_rowb = warp_n * 64 + (lane & 7) + ((lane & 16) >> 1);
    const int b_cb   = (lane >> 3) & 1;

    auto issue_tile = [&](int kt, int buf) {
        uint32_t Ab = sb + (buf ? 32768u : 0u);
        uint32_t Bb = sb + (buf ? 49152u : 16384u);
#pragma unroll
        for (int j = 0; j < 4; j++) {
            int id = tid + j * 256;
            int r = id >> 3, c = id & 7;
            uint32_t dst = Ab + r * 128 + ((c ^ (r & 7)) << 4);
            cp16(dst, Ag + (size_t)r * 3072 + kt * 128 + c * 16);
        }
#pragma unroll
        for (int j = 0; j < 4; j++) {
            int id = tid + j * 256;
            int r = id >> 3, c = id & 7;
            uint32_t dst = Bb + r * 128 + ((c ^ (r & 7)) << 4);
            cp16(dst, Bg + (size_t)r * 3072 + kt * 128 + c * 16);
        }
        CP_COMMIT();
    };

    issue_tile(0, 0);

    for (int kt = 0; kt < MM_NKT; kt++) {
        const int buf = kt & 1;
        if (kt + 1 < MM_NKT) {
            issue_tile(kt + 1, buf ^ 1);
            CP_WAIT(1);
        } else {
            CP_WAIT(0);
        }
        __syncthreads();

        uint32_t Ab = sb + (buf ? 32768u : 0u);
        uint32_t Bb = sb + (buf ? 49152u : 16384u);
#pragma unroll
        for (int kk = 0; kk < 4; kk++) {
            uint32_t a0, a1, a2, a3, e0, e1, e2, e3;
            int ca = kk * 2 + a_cb;
            LDSM4(a0, a1, a2, a3, Ab + a_row0 * 128 + ((ca ^ (a_row0 & 7)) << 4));
            LDSM4(e0, e1, e2, e3, Ab + a_row1 * 128 + ((ca ^ (a_row1 & 7)) << 4));
            int cb = kk * 2 + b_cb;
#pragma unroll
            for (int nt = 0; nt < 4; nt++) {
                int br = b_rowb + nt * 16;
                uint32_t b0, b1, b2, b3;
                LDSM4(b0, b1, b2, b3, Bb + br * 128 + ((cb ^ (br & 7)) << 4));
                MMA16816(d[0][2*nt],   a0, a1, a2, a3, b0, b1);
                MMA16816(d[0][2*nt+1], a0, a1, a2, a3, b2, b3);
                MMA16816(d[1][2*nt],   e0, e1, e2, e3, b0, b1);
                MMA16816(d[1][2*nt+1], e0, e1, e2, e3, b2, b3);
            }
        }
        __syncthreads();
    }

    // epilogue: direct fp32 stores with bias
#pragma unroll
    for (int mi = 0; mi < 2; mi++) {
        int gm = m0 + warp_m * 32 + mi * 16 + (lane >> 2);
#pragma unroll
        for (int ni = 0; ni < 8; ni++) {
            int gn = n0 + warp_n * 64 + ni * 8 + (lane & 3) * 2;
            float2 bv = *(const float2*)(bo + gn);
            float2 o0, o1;
            o0.x = d[mi][ni][0] + bv.x; o0.y = d[mi][ni][1] + bv.y;
            o1.x = d[mi][ni][2] + bv.x; o1.y = d[mi][ni][3] + bv.y;
            *(float2*)(out + (size_t)gm * VOUT + gn) = o0;
            *(float2*)(out + (size_t)(gm + 8) * VOUT + gn) = o1;
        }
    }
}

// ---------------- persistent GRU scan ----------------
struct ScanProb {
    const float* gx;
    const float* seed;
    const float* whh;
    const float* bhh;
    float*       outs;
    int          dir;
};

__global__ __launch_bounds__(256)
void gru_scan_kernel(ScanProb pa, ScanProb pb, int bpp, int nsteps,
                     unsigned nblocks, unsigned* bar)
{
    extern __shared__ float w_s[];
    ScanProb p = (blockIdx.x < bpp) ? pa : pb;
    const int blk = blockIdx.x % bpp;
    const int h0  = blk * 8;
    const int tid = threadIdx.x;
    const int b   = tid >> 3;
    const int hi  = tid & 7;

    for (int id = tid; id < 24 * 128; id += 256) {
        int row = id >> 7, c4 = (id & 127) * 4;
        int g = row >> 3, hh = h0 + (row & 7);
        *(float4*)&w_s[row * 516 + c4] =
            *(const float4*)(p.whh + (size_t)(g * H + hh) * H + c4);
    }
    __syncthreads();

    const ull* wr2 = (const ull*)&w_s[hi * 516];
    const ull* wz2 = (const ull*)&w_s[(8 + hi) * 516];
    const ull* wn2 = (const ull*)&w_s[(16 + hi) * 516];

    const int h = h0 + hi;
    const float br = p.bhh[h], bz = p.bhh[H + h], bn = p.bhh[2 * H + h];

    for (int i = 0; i < nsteps; i++) {
        const int t = p.dir ? (nsteps - 1 - i) : i;
        const float* hprev = (i == 0) ? p.seed
                           : p.outs + (size_t)(p.dir ? t + 1 : t - 1) * B * H;
        ull ar2 = 0, az2 = 0, an2 = 0;
        float hp_val = 0.f;
        if (hprev) {
            const float4* hp4 = (const float4*)(hprev + b * H);
#pragma unroll 8
            for (int c = 0; c < 128; c++) {
                float4 hv = __ldg(&hp4[c]);
                ull h01 = pk2(hv.x, hv.y), h23 = pk2(hv.z, hv.w);
                fma2(ar2, h01, wr2[2*c]); fma2(ar2, h23, wr2[2*c+1]);
                fma2(az2, h01, wz2[2*c]); fma2(az2, h23, wz2[2*c+1]);
                fma2(an2, h01, wn2[2*c]); fma2(an2, h23, wn2[2*c+1]);
            }
            hp_val = __ldg(hprev + b * H + h);
        }
        float2 fr = upk(ar2), fz = upk(az2), fn = upk(an2);
        const float* gx = p.gx + ((size_t)t * B + b) * H3;
        float r = 1.f / (1.f + expf(-(gx[h]       + fr.x + fr.y + br)));
        float z = 1.f / (1.f + expf(-(gx[H + h]   + fz.x + fz.y + bz)));
        float n = tanhf(gx[2 * H + h] + r * (fn.x + fn.y + bn));
        p.outs[((size_t)t * B + b) * H + h] = (1.f - z) * n + z * hp_val;

        if (i < nsteps - 1) grid_bar(bar, nblocks * (unsigned)(i + 1));
    }
}

// ---------------- batched attention ----------------
__global__ __launch_bounds__(256)
void attn_kernel(const float* __restrict__ Hdec, const float* __restrict__ enc,
                 float* __restrict__ Ctx)
{
    const int t = blockIdx.x / B;
    const int b = blockIdx.x % B;
    const float* h2 = Hdec + ((size_t)t * B + b) * H;
    const int tid = threadIdx.x;
    const int lane = tid & 31, w = tid >> 5;
    __shared__ float h2_s[H];
    __shared__ float sc[S];

    h2_s[tid]       = h2[tid];
    h2_s[tid + 256] = h2[tid + 256];
    __syncthreads();

    for (int s = w; s < S; s += 8) {
        const float4* e  = (const float4*)(enc + (size_t)(s * B + b) * H);
        const float4* h4 = (const float4*)h2_s;
        float p = 0.f;
#pragma unroll
        for (int j = 0; j < 4; j++) {
            float4 ev = e[lane + j * 32];
            float4 hv = h4[lane + j * 32];
            p = fmaf(ev.x, hv.x, p); p = fmaf(ev.y, hv.y, p);
            p = fmaf(ev.z, hv.z, p); p = fmaf(ev.w, hv.w, p);
        }
#pragma unroll
        for (int o = 16; o > 0; o >>= 1) p += __shfl_xor_sync(0xffffffffu, p, o);
        if (lane == 0) sc[s] = p;
    }
    __syncthreads();

    if (w == 0) {
        float a  = sc[lane];
        float b2 = (lane < 16) ? sc[32 + lane] : -1e30f;
        float m = fmaxf(a, b2);
#pragma unroll
        for (int o = 16; o > 0; o >>= 1) m = fmaxf(m, __shfl_xor_sync(0xffffffffu, m, o));
        float ea = expf(a - m);
        float eb = (lane < 16) ? expf(b2 - m) : 0.f;
        float ss = ea + eb;
#pragma unroll
        for (int o = 16; o > 0; o >>= 1) ss += __shfl_xor_sync(0xffffffffu, ss, o);
        float inv = 1.f / ss;
        sc[lane] = ea * inv;
        if (lane < 16) sc[32 + lane] = eb * inv;
    }
    __syncthreads();

    float a0 = 0.f, a1 = 0.f;
    for (int s = 0; s < S; s++) {
        float at = sc[s];
        const float* e = enc + (size_t)(s * B + b) * H;
        a0 = fmaf(at, e[tid], a0);
        a1 = fmaf(at, e[tid + 256], a1);
    }
    float* co = Ctx + ((size_t)t * B + b) * H;
    co[tid]       = a0;
    co[tid + 256] = a1;
}

// ---------------- small utilities ----------------
__global__ void combine_kernel(float* __restrict__ out, const float* __restrict__ a,
                               const float* __restrict__ b, int n)
{
    int i = blockIdx.x * blockDim.x + threadIdx.x;
    if (i < n) out[i] = a[i] + b[i];
}

__global__ void init_kernel(int* __restrict__ out, const int* __restrict__ target,
                            unsigned* __restrict__ bars)
{
    int i = blockIdx.x * blockDim.x + threadIdx.x;
    if (i < 2) bars[i] = 0u;
    if (i < T * B) out[i] = (i < B) ? 1 /*SOS*/ : target[i - B];
}

// ---------------- launch ------------------------------------------------------
extern "C" void kernel_launch(void* const* d_in, const int* in_sizes, int n_in,
                              void* d_out, int out_size)
{
    const int*   input_batches  = (const int*)d_in[0];
    const int*   target_batches = (const int*)d_in[1];
    const float* enc_emb   = (const float*)d_in[2];
    const float* enc_Wih_f = (const float*)d_in[3];
    const float* enc_Whh_f = (const float*)d_in[4];
    const float* enc_bih_f = (const float*)d_in[5];
    const float* enc_bhh_f = (const float*)d_in[6];
    const float* enc_Wih_b = (const float*)d_in[7];
    const float* enc_Whh_b = (const float*)d_in[8];
    const float* enc_bih_b = (const float*)d_in[9];
    const float* enc_bhh_b = (const float*)d_in[10];
    const float* dec_emb   = (const float*)d_in[11];
    const float* dec_Wih   = (const float*)d_in[12];
    const float* dec_Whh   = (const float*)d_in[13];
    const float* dec_bih   = (const float*)d_in[14];
    const float* dec_bhh   = (const float*)d_in[15];
    const float* Wc        = (const float*)d_in[16];
    const float* bc        = (const float*)d_in[17];
    const float* Wo        = (const float*)d_in[18];
    const float* bo        = (const float*)d_in[19];
    float* out = (float*)d_out;

    float *Gx_f, *Gx_b, *Gd, *outs_f, *outs_b, *enc_out, *Hdec, *Ctx, *Cbuf;
    int* dectok; unsigned* bars;
    __nv_bfloat16 *A3, *B3;
    cudaGetSymbolAddress((void**)&Gx_f,   g_Gx_f);
    cudaGetSymbolAddress((void**)&Gx_b,   g_Gx_b);
    cudaGetSymbolAddress((void**)&Gd,     g_Gd);
    cudaGetSymbolAddress((void**)&outs_f, g_outs_f);
    cudaGetSymbolAddress((void**)&outs_b, g_outs_b);
    cudaGetSymbolAddress((void**)&enc_out,g_enc_out);
    cudaGetSymbolAddress((void**)&Hdec,   g_Hdec);
    cudaGetSymbolAddress((void**)&Ctx,    g_Ctx);
    cudaGetSymbolAddress((void**)&Cbuf,   g_C);
    cudaGetSymbolAddress((void**)&dectok, g_dectok);
    cudaGetSymbolAddress((void**)&bars,   g_bars);
    cudaGetSymbolAddress((void**)&A3,     g_A3);
    cudaGetSymbolAddress((void**)&B3,     g_B3);

    const int WSMEM = 24 * 516 * 4;
    cudaFuncSetAttribute(gru_scan_kernel,
                         cudaFuncAttributeMaxDynamicSharedMemorySize, WSMEM);
    cudaFuncSetAttribute(gemm_mma_kernel,
                         cudaFuncAttributeMaxDynamicSharedMemorySize, 65536);

    init_kernel<<<(T * B + 255) / 256, 256>>>(dectok, target_batches, bars);

    // split Wo into bf16 [hi, hi, lo] (independent of everything else)
    split_kernel<<<(VOUT * 128 + 255) / 256, 256>>>(Wo, B3, VOUT, 1);

    // input-gate GEMMs
    dim3 g1(H3 / BN, (S * B) / BM);
    gemm_nt_kernel<<<g1, 256>>>(enc_emb, enc_emb, input_batches, enc_Wih_f, enc_bih_f, Gx_f, H3, H, 0);
    gemm_nt_kernel<<<g1, 256>>>(enc_emb, enc_emb, input_batches, enc_Wih_b, enc_bih_b, Gx_b, H3, H, 0);
    gemm_nt_kernel<<<g1, 256>>>(dec_emb, dec_emb, dectok,        dec_Wih,   dec_bih,   Gd,   H3, H, 0);

    // encoder scans (fwd + bwd fused)
    ScanProb pf { Gx_f, nullptr, enc_Whh_f, enc_bhh_f, outs_f, 0 };
    ScanProb pk { Gx_b, nullptr, enc_Whh_b, enc_bhh_b, outs_b, 1 };
    gru_scan_kernel<<<128, 256, WSMEM>>>(pf, pk, 64, S, 128u, bars + 0);

    combine_kernel<<<(S * B * H + 255) / 256, 256>>>(enc_out, outs_f, outs_b, S * B * H);

    // decoder GRU chain
    ScanProb pd { Gd, outs_f + (size_t)(S - 1) * B * H, dec_Whh, dec_bhh, Hdec, 0 };
    gru_scan_kernel<<<64, 256, WSMEM>>>(pd, pd, 64, T, 64u, bars + 1);

    // batched attention
    attn_kernel<<<T * B, 256>>>(Hdec, enc_out, Ctx);

    // c = tanh([h2, ctx] @ Wc^T + bc)
    dim3 g2(H / BN, (T * B) / BM);
    gemm_nt_kernel<<<g2, 256>>>(Hdec, Ctx, nullptr, Wc, bc, Cbuf, H, 2 * H, 1);

    // split C into bf16 [hi, lo, hi]
    split_kernel<<<(T * B * 128 + 255) / 256, 256>>>(Cbuf, A3, T * B, 0);

    // vocab projection on tensor cores (mma.sync): out = A3 @ B3^T + bo
    dim3 g3((T * B) / 128, VOUT / 128);
    gemm_mma_kernel<<<g3, 256, 65536>>>(A3, B3, bo, out);
}

// round 6
// speedup vs baseline: 1.5510x; 1.0153x over previous
#include <cuda_runtime.h>
#include <cuda_bf16.h>
#include <math.h>
#include <stdint.h>

#define H    512
#define H3   1536
#define S    48
#define T    48
#define B    32
#define VOUT 32000

typedef unsigned long long ull;

// ---------------- packed f32x2 helpers (scan kernel) ----------------
__device__ __forceinline__ ull pk2(float x, float y) {
    ull r; asm("mov.b64 %0, {%1,%2};" : "=l"(r) : "f"(x), "f"(y)); return r;
}
__device__ __forceinline__ void fma2(ull& d, ull a, ull b) {
    asm("fma.rn.f32x2 %0, %1, %2, %0;" : "+l"(d) : "l"(a), "l"(b));
}
__device__ __forceinline__ float2 upk(ull v) {
    float lo, hi; asm("mov.b64 {%0,%1}, %2;" : "=f"(lo), "=f"(hi) : "l"(v));
    float2 f; f.x = lo; f.y = hi; return f;
}

// ---------------- mma.sync helpers ----------------
__device__ __forceinline__ uint32_t smem_u32(const void* p) {
    uint32_t a;
    asm("{ .reg .u64 t; cvta.to.shared.u64 t, %1; cvt.u32.u64 %0, t; }" : "=r"(a) : "l"(p));
    return a;
}
#define LDSM4(r0, r1, r2, r3, addr) \
    asm volatile("ldmatrix.sync.aligned.m8n8.x4.shared.b16 {%0,%1,%2,%3}, [%4];" \
        : "=r"(r0), "=r"(r1), "=r"(r2), "=r"(r3) : "r"(addr))
#define MMA16816(d, a0, a1, a2, a3, b0, b1) \
    asm volatile("mma.sync.aligned.m16n8k16.row.col.f32.bf16.bf16.f32 " \
        "{%0,%1,%2,%3}, {%4,%5,%6,%7}, {%8,%9}, {%0,%1,%2,%3};" \
        : "+f"((d)[0]), "+f"((d)[1]), "+f"((d)[2]), "+f"((d)[3]) \
        : "r"(a0), "r"(a1), "r"(a2), "r"(a3), "r"(b0), "r"(b1))
__device__ __forceinline__ void cp16(uint32_t dst, const void* src) {
    asm volatile("cp.async.cg.shared.global [%0], [%1], 16;" :: "r"(dst), "l"(src));
}
#define CP_COMMIT() asm volatile("cp.async.commit_group;" ::: "memory")
#define CP_WAIT(n)  asm volatile("cp.async.wait_group %0;" :: "n"(n) : "memory")

// ---------------- device scratch ----------------
__device__ float g_Gall[3*S*B*H3];      // Gx_f | Gx_b | Gd (contiguous)
__device__ float g_outs_f[S*B*H];
__device__ float g_outs_b[S*B*H];
__device__ float g_enc_out[S*B*H];
__device__ float g_Hdec[T*B*H];
__device__ float g_Ctx [T*B*H];
__device__ int   g_dectok[T*B];
__device__ unsigned g_bars[2];
__device__ __nv_bfloat16 g_B3o[(size_t)VOUT*H3];  // split Wo   [hi,hi,lo]
__device__ __nv_bfloat16 g_A3e[S*B*H3];           // split enc emb (gathered)
__device__ __nv_bfloat16 g_A3d[T*B*H3];           // split dec emb (gathered)
__device__ __nv_bfloat16 g_B3f[H3*H3];            // split enc_Wih_f
__device__ __nv_bfloat16 g_B3b[H3*H3];            // split enc_Wih_b
__device__ __nv_bfloat16 g_B3d[H3*H3];            // split dec_Wih
__device__ __nv_bfloat16 g_B3c[H*3*1024];         // split Wc (K=1024)
__device__ __nv_bfloat16 g_A3c[T*B*3*1024];       // split [Hdec|Ctx]
__device__ __nv_bfloat16 g_A3v[T*B*H3];           // split c (written by Wc epi)

// ---------------- grid barrier ----------------
__device__ __forceinline__ void grid_bar(unsigned* bar, unsigned target) {
    __threadfence();
    __syncthreads();
    if (threadIdx.x == 0) {
        atomicAdd(bar, 1u);
        while (*(volatile unsigned*)bar < target) { __nanosleep(64); }
        __threadfence();
    }
    __syncthreads();
}

// ---------------- fp32 -> bf16 3-term split ---------------------------------
// mode 0 (A): segments [hi, lo, hi] ; mode 1 (B): segments [hi, hi, lo]
// optional row gather (gidx); optional src2 (cols >= 512 come from src2, K=1024 cat)
__global__ __launch_bounds__(256)
void split3_kernel(const float* __restrict__ src, const float* __restrict__ src2,
                   const int* __restrict__ gidx, __nv_bfloat16* __restrict__ dst,
                   int nrows, int K, int mode)
{
    int perrow = K >> 2;
    int idx = blockIdx.x * 256 + threadIdx.x;
    if (idx >= nrows * perrow) return;
    int row = idx / perrow, cc = (idx - row * perrow) * 4;
    const float* s;
    if (src2 && cc >= 512)      s = src2 + (size_t)row * 512 + (cc - 512);
    else if (src2)              s = src  + (size_t)row * 512 + cc;
    else if (gidx)              s = src  + (size_t)gidx[row] * K + cc;
    else                        s = src  + (size_t)row * K + cc;
    float4 v = *(const float4*)s;
    float f[4] = {v.x, v.y, v.z, v.w};
    __nv_bfloat16 h[4], l[4];
#pragma unroll
    for (int i = 0; i < 4; i++) {
        h[i] = __float2bfloat16(f[i]);
        l[i] = __float2bfloat16(f[i] - __bfloat162float(h[i]));
    }
    __nv_bfloat162 h01, h23, l01, l23;
    h01.x = h[0]; h01.y = h[1]; h23.x = h[2]; h23.y = h[3];
    l01.x = l[0]; l01.y = l[1]; l23.x = l[2]; l23.y = l[3];
    __nv_bfloat16* base = dst + (size_t)row * (3 * K);
    __nv_bfloat162* d0 = (__nv_bfloat162*)(base + cc);
    __nv_bfloat162* d1 = (__nv_bfloat162*)(base + K + cc);
    __nv_bfloat162* d2 = (__nv_bfloat162*)(base + 2 * K + cc);
    d0[0] = h01; d0[1] = h23;
    if (mode == 0) { d1[0] = l01; d1[1] = l23; d2[0] = h01; d2[1] = h23; }
    else           { d1[0] = h01; d1[1] = h23; d2[0] = l01; d2[1] = l23; }
}

// ---------------- mma.sync bf16 NT GEMM (3-stage cp.async pipeline) ---------
// C[m,n] = A3[m,:] . B3[n,:] + bias[n]   (K3 = 3*K bf16 columns)
// TM = 128 (warp tile 32x64) or 256 (warp tile 64x64). N tile = 128.
// grid = (M/TM, N/128, nprob); z selects {A,B,bias,out}.
// act 0: fp32 out (ldc stride). act 2: tanh + 3-term split store to outsplit
// (row stride 1536, K=512 layout) for the Wc GEMM.
template<int TM>
__global__ __launch_bounds__(256)
void gemm_mma_kernel(const __nv_bfloat16* __restrict__ A3a,
                     const __nv_bfloat16* __restrict__ A3b,
                     const __nv_bfloat16* __restrict__ B3_0,
                     const __nv_bfloat16* __restrict__ B3_1,
                     const __nv_bfloat16* __restrict__ B3_2,
                     const float* __restrict__ bias0,
                     const float* __restrict__ bias1,
                     const float* __restrict__ bias2,
                     float* __restrict__ out0, float* __restrict__ out1,
                     float* __restrict__ out2,
                     __nv_bfloat16* __restrict__ outsplit,
                     int K3, int N, int ldc, int act)
{
    constexpr int MI = TM / 64;                 // m16 frags per warp
    constexpr int ABYTES = TM * 128;            // A stage bytes (64 k-cols bf16)
    constexpr int BBYTES = 128 * 128;
    constexpr int STAGE = ABYTES + BBYTES;
    extern __shared__ __align__(1024) char smem[];

    const int z = blockIdx.z;
    const __nv_bfloat16* A3 = (z == 2) ? A3b : A3a;
    const __nv_bfloat16* B3 = (z == 0) ? B3_0 : ((z == 1) ? B3_1 : B3_2);
    const float* bias = (z == 0) ? bias0 : ((z == 1) ? bias1 : bias2);
    float* out = (z == 0) ? out0 : ((z == 1) ? out1 : out2);

    const int tid  = threadIdx.x;
    const int wid  = tid >> 5;
    const int lane = tid & 31;
    const int m0 = blockIdx.x * TM;
    const int n0 = blockIdx.y * 128;
    const int warp_m = wid & 3;
    const int warp_n = wid >> 2;
    const uint32_t sb = smem_u32(smem);

    const size_t K3b = (size_t)K3 * 2;
    const char* Ag = (const char*)A3 + (size_t)m0 * K3b;
    const char* Bg = (const char*)B3 + (size_t)n0 * K3b;
    const int nkt = K3 / 64;

    float d[MI][8][4];
#pragma unroll
    for (int i = 0; i < MI; i++)
#pragma unroll
        for (int j = 0; j < 8; j++)
#pragma unroll
            for (int q = 0; q < 4; q++) d[i][j][q] = 0.f;

    const int a_rowl = lane & 15;
    const int a_cb   = lane >> 4;
    const int b_rowb = warp_n * 64 + (lane & 7) + ((lane & 16) >> 1);
    const int b_cb   = (lane >> 3) & 1;

    auto issue = [&](int kt, int slot) {
        uint32_t Ab = sb + slot * STAGE;
        uint32_t Bb = Ab + ABYTES;
#pragma unroll
        for (int j = 0; j < ABYTES / 16 / 256; j++) {
            int id = tid + j * 256;
            int r = id >> 3, c = id & 7;
            cp16(Ab + r * 128 + ((c ^ (r & 7)) << 4), Ag + (size_t)r * K3b + kt * 128 + c * 16);
        }
#pragma unroll
        for (int j = 0; j < BBYTES / 16 / 256; j++) {
            int id = tid + j * 256;
            int r = id >> 3, c = id & 7;
            cp16(Bb + r * 128 + ((c ^ (r & 7)) << 4), Bg + (size_t)r * K3b + kt * 128 + c * 16);
        }
        CP_COMMIT();
    };

    issue(0, 0);
    issue(1, 1);

    int slot = 0, slot2 = 2;
    for (int kt = 0; kt < nkt; kt++) {
        if (kt + 1 < nkt) { CP_WAIT(1); } else { CP_WAIT(0); }
        __syncthreads();
        if (kt + 2 < nkt) {
            issue(kt + 2, slot2);
            if (++slot2 == 3) slot2 = 0;
        }
        uint32_t Ab = sb + slot * STAGE;
        uint32_t Bb = Ab + ABYTES;
        if (++slot == 3) slot = 0;
#pragma unroll
        for (int kk = 0; kk < 4; kk++) {
            uint32_t af[MI][4];
            int ca = kk * 2 + a_cb;
#pragma unroll
            for (int mi = 0; mi < MI; mi++) {
                int ar = warp_m * (MI * 16) + mi * 16 + a_rowl;
                LDSM4(af[mi][0], af[mi][1], af[mi][2], af[mi][3],
                      Ab + ar * 128 + ((ca ^ (ar & 7)) << 4));
            }
            int cb = kk * 2 + b_cb;
#pragma unroll
            for (int nt = 0; nt < 4; nt++) {
                int br = b_rowb + nt * 16;
                uint32_t b0, b1, b2, b3;
                LDSM4(b0, b1, b2, b3, Bb + br * 128 + ((cb ^ (br & 7)) << 4));
#pragma unroll
                for (int mi = 0; mi < MI; mi++) {
                    MMA16816(d[mi][2 * nt],     af[mi][0], af[mi][1], af[mi][2], af[mi][3], b0, b1);
                    MMA16816(d[mi][2 * nt + 1], af[mi][0], af[mi][1], af[mi][2], af[mi][3], b2, b3);
                }
            }
        }
        __syncthreads();
    }

    // epilogue
#pragma unroll
    for (int mi = 0; mi < MI; mi++) {
        int gm = m0 + warp_m * (MI * 16) + mi * 16 + (lane >> 2);
#pragma unroll
        for (int ni = 0; ni < 8; ni++) {
            int gn = n0 + warp_n * 64 + ni * 8 + (lane & 3) * 2;
            float2 bv = *(const float2*)(bias + gn);
            float v0 = d[mi][ni][0] + bv.x, v1 = d[mi][ni][1] + bv.y;
            float v2 = d[mi][ni][2] + bv.x, v3 = d[mi][ni][3] + bv.y;
            if (act == 2) {
                v0 = tanhf(v0); v1 = tanhf(v1); v2 = tanhf(v2); v3 = tanhf(v3);
                __nv_bfloat16 h0 = __float2bfloat16(v0), h1 = __float2bfloat16(v1);
                __nv_bfloat16 h2 = __float2bfloat16(v2), h3 = __float2bfloat16(v3);
                __nv_bfloat162 ph0; ph0.x = h0; ph0.y = h1;
                __nv_bfloat162 pl0;
                pl0.x = __float2bfloat16(v0 - __bfloat162float(h0));
                pl0.y = __float2bfloat16(v1 - __bfloat162float(h1));
                __nv_bfloat162 ph1; ph1.x = h2; ph1.y = h3;
                __nv_bfloat162 pl1;
                pl1.x = __float2bfloat16(v2 - __bfloat162float(h2));
                pl1.y = __float2bfloat16(v3 - __bfloat162float(h3));
                __nv_bfloat16* r0 = outsplit + (size_t)gm * H3;
                __nv_bfloat16* r1 = outsplit + (size_t)(gm + 8) * H3;
                *(__nv_bfloat162*)(r0 + gn) = ph0;
                *(__nv_bfloat162*)(r0 + 512 + gn) = pl0;
                *(__nv_bfloat162*)(r0 + 1024 + gn) = ph0;
                *(__nv_bfloat162*)(r1 + gn) = ph1;
                *(__nv_bfloat162*)(r1 + 512 + gn) = pl1;
                *(__nv_bfloat162*)(r1 + 1024 + gn) = ph1;
            } else {
                float2 o0, o1;
                o0.x = v0; o0.y = v1; o1.x = v2; o1.y = v3;
                *(float2*)(out + (size_t)gm * ldc + gn) = o0;
                *(float2*)(out + (size_t)(gm + 8) * ldc + gn) = o1;
            }
        }
    }
}

// ---------------- persistent GRU scan ----------------
struct ScanProb {
    const float* gx;
    const float* seed;
    const float* whh;
    const float* bhh;
    float*       outs;
    int          dir;
};

__global__ __launch_bounds__(256)
void gru_scan_kernel(ScanProb pa, ScanProb pb, int bpp, int nsteps,
                     unsigned nblocks, unsigned* bar)
{
    extern __shared__ float w_s[];
    ScanProb p = (blockIdx.x < bpp) ? pa : pb;
    const int blk = blockIdx.x % bpp;
    const int h0  = blk * 8;
    const int tid = threadIdx.x;
    const int b   = tid >> 3;
    const int hi  = tid & 7;

    for (int id = tid; id < 24 * 128; id += 256) {
        int row = id >> 7, c4 = (id & 127) * 4;
        int g = row >> 3, hh = h0 + (row & 7);
        *(float4*)&w_s[row * 516 + c4] =
            *(const float4*)(p.whh + (size_t)(g * H + hh) * H + c4);
    }
    __syncthreads();

    const ull* wr2 = (const ull*)&w_s[hi * 516];
    const ull* wz2 = (const ull*)&w_s[(8 + hi) * 516];
    const ull* wn2 = (const ull*)&w_s[(16 + hi) * 516];

    const int h = h0 + hi;
    const float br = p.bhh[h], bz = p.bhh[H + h], bn = p.bhh[2 * H + h];

    for (int i = 0; i < nsteps; i++) {
        const int t = p.dir ? (nsteps - 1 - i) : i;
        const float* hprev = (i == 0) ? p.seed
                           : p.outs + (size_t)(p.dir ? t + 1 : t - 1) * B * H;
        ull ar2 = 0, az2 = 0, an2 = 0;
        float hp_val = 0.f;
        if (hprev) {
            const float4* hp4 = (const float4*)(hprev + b * H);
#pragma unroll 8
            for (int c = 0; c < 128; c++) {
                float4 hv = __ldg(&hp4[c]);
                ull h01 = pk2(hv.x, hv.y), h23 = pk2(hv.z, hv.w);
                fma2(ar2, h01, wr2[2*c]); fma2(ar2, h23, wr2[2*c+1]);
                fma2(az2, h01, wz2[2*c]); fma2(az2, h23, wz2[2*c+1]);
                fma2(an2, h01, wn2[2*c]); fma2(an2, h23, wn2[2*c+1]);
            }
            hp_val = __ldg(hprev + b * H + h);
        }
        float2 fr = upk(ar2), fz = upk(az2), fn = upk(an2);
        const float* gx = p.gx + ((size_t)t * B + b) * H3;
        float r = 1.f / (1.f + expf(-(gx[h]       + fr.x + fr.y + br)));
        float z = 1.f / (1.f + expf(-(gx[H + h]   + fz.x + fz.y + bz)));
        float n = tanhf(gx[2 * H + h] + r * (fn.x + fn.y + bn));
        p.outs[((size_t)t * B + b) * H + h] = (1.f - z) * n + z * hp_val;

        if (i < nsteps - 1) grid_bar(bar, nblocks * (unsigned)(i + 1));
    }
}

// ---------------- batched attention ----------------
__global__ __launch_bounds__(256)
void attn_kernel(const float* __restrict__ Hdec, const float* __restrict__ enc,
                 float* __restrict__ Ctx)
{
    const int t = blockIdx.x / B;
    const int b = blockIdx.x % B;
    const float* h2 = Hdec + ((size_t)t * B + b) * H;
    const int tid = threadIdx.x;
    const int lane = tid & 31, w = tid >> 5;
    __shared__ float h2_s[H];
    __shared__ float sc[S];

    h2_s[tid]       = h2[tid];
    h2_s[tid + 256] = h2[tid + 256];
    __syncthreads();

    for (int s = w; s < S; s += 8) {
        const float4* e  = (const float4*)(enc + (size_t)(s * B + b) * H);
        const float4* h4 = (const float4*)h2_s;
        float p = 0.f;
#pragma unroll
        for (int j = 0; j < 4; j++) {
            float4 ev = e[lane + j * 32];
            float4 hv = h4[lane + j * 32];
            p = fmaf(ev.x, hv.x, p); p = fmaf(ev.y, hv.y, p);
            p = fmaf(ev.z, hv.z, p); p = fmaf(ev.w, hv.w, p);
        }
#pragma unroll
        for (int o = 16; o > 0; o >>= 1) p += __shfl_xor_sync(0xffffffffu, p, o);
        if (lane == 0) sc[s] = p;
    }
    __syncthreads();

    if (w == 0) {
        float a  = sc[lane];
        float b2 = (lane < 16) ? sc[32 + lane] : -1e30f;
        float m = fmaxf(a, b2);
#pragma unroll
        for (int o = 16; o > 0; o >>= 1) m = fmaxf(m, __shfl_xor_sync(0xffffffffu, m, o));
        float ea = expf(a - m);
        float eb = (lane < 16) ? expf(b2 - m) : 0.f;
        float ss = ea + eb;
#pragma unroll
        for (int o = 16; o > 0; o >>= 1) ss += __shfl_xor_sync(0xffffffffu, ss, o);
        float inv = 1.f / ss;
        sc[lane] = ea * inv;
        if (lane < 16) sc[32 + lane] = eb * inv;
    }
    __syncthreads();

    float a0 = 0.f, a1 = 0.f;
    for (int s = 0; s < S; s++) {
        float at = sc[s];
        const float* e = enc + (size_t)(s * B + b) * H;
        a0 = fmaf(at, e[tid], a0);
        a1 = fmaf(at, e[tid + 256], a1);
    }
    float* co = Ctx + ((size_t)t * B + b) * H;
    co[tid]       = a0;
    co[tid + 256] = a1;
}

// ---------------- small utilities ----------------
__global__ void combine_kernel(float* __restrict__ out, const float* __restrict__ a,
                               const float* __restrict__ b, int n)
{
    int i = blockIdx.x * blockDim.x + threadIdx.x;
    if (i < n) out[i] = a[i] + b[i];
}

__global__ void init_kernel(int* __restrict__ out, const int* __restrict__ target,
                            unsigned* __restrict__ bars)
{
    int i = blockIdx.x * blockDim.x + threadIdx.x;
    if (i < 2) bars[i] = 0u;
    if (i < T * B) out[i] = (i < B) ? 1 /*SOS*/ : target[i - B];
}

// ---------------- launch ------------------------------------------------------
extern "C" void kernel_launch(void* const* d_in, const int* in_sizes, int n_in,
                              void* d_out, int out_size)
{
    const int*   input_batches  = (const int*)d_in[0];
    const int*   target_batches = (const int*)d_in[1];
    const float* enc_emb   = (const float*)d_in[2];
    const float* enc_Wih_f = (const float*)d_in[3];
    const float* enc_Whh_f = (const float*)d_in[4];
    const float* enc_bih_f = (const float*)d_in[5];
    const float* enc_bhh_f = (const float*)d_in[6];
    const float* enc_Wih_b = (const float*)d_in[7];
    const float* enc_Whh_b = (const float*)d_in[8];
    const float* enc_bih_b = (const float*)d_in[9];
    const float* enc_bhh_b = (const float*)d_in[10];
    const float* dec_emb   = (const float*)d_in[11];
    const float* dec_Wih   = (const float*)d_in[12];
    const float* dec_Whh   = (const float*)d_in[13];
    const float* dec_bih   = (const float*)d_in[14];
    const float* dec_bhh   = (const float*)d_in[15];
    const float* Wc        = (const float*)d_in[16];
    const float* bc        = (const float*)d_in[17];
    const float* Wo        = (const float*)d_in[18];
    const float* bo        = (const float*)d_in[19];
    float* out = (float*)d_out;

    float *Gall, *outs_f, *outs_b, *enc_out, *Hdec, *Ctx;
    int* dectok; unsigned* bars;
    __nv_bfloat16 *B3o, *A3e, *A3d, *B3f, *B3b_, *B3d_, *B3c, *A3c, *A3v;
    cudaGetSymbolAddress((void**)&Gall,   g_Gall);
    cudaGetSymbolAddress((void**)&outs_f, g_outs_f);
    cudaGetSymbolAddress((void**)&outs_b, g_outs_b);
    cudaGetSymbolAddress((void**)&enc_out,g_enc_out);
    cudaGetSymbolAddress((void**)&Hdec,   g_Hdec);
    cudaGetSymbolAddress((void**)&Ctx,    g_Ctx);
    cudaGetSymbolAddress((void**)&dectok, g_dectok);
    cudaGetSymbolAddress((void**)&bars,   g_bars);
    cudaGetSymbolAddress((void**)&B3o,    g_B3o);
    cudaGetSymbolAddress((void**)&A3e,    g_A3e);
    cudaGetSymbolAddress((void**)&A3d,    g_A3d);
    cudaGetSymbolAddress((void**)&B3f,    g_B3f);
    cudaGetSymbolAddress((void**)&B3b_,   g_B3b);
    cudaGetSymbolAddress((void**)&B3d_,   g_B3d);
    cudaGetSymbolAddress((void**)&B3c,    g_B3c);
    cudaGetSymbolAddress((void**)&A3c,    g_A3c);
    cudaGetSymbolAddress((void**)&A3v,    g_A3v);

    float* Gx_f = Gall;
    float* Gx_b = Gall + (size_t)S * B * H3;
    float* Gd   = Gall + (size_t)2 * S * B * H3;

    const int WSMEM = 24 * 516 * 4;
    cudaFuncSetAttribute(gru_scan_kernel,
                         cudaFuncAttributeMaxDynamicSharedMemorySize, WSMEM);
    cudaFuncSetAttribute(gemm_mma_kernel<128>,
                         cudaFuncAttributeMaxDynamicSharedMemorySize, 98304);
    cudaFuncSetAttribute(gemm_mma_kernel<256>,
                         cudaFuncAttributeMaxDynamicSharedMemorySize, 147456);

    init_kernel<<<(T * B + 255) / 256, 256>>>(dectok, target_batches, bars);

    // splits (bf16 3-term)
    split3_kernel<<<(S*B*128 + 255)/256, 256>>>(enc_emb, nullptr, input_batches, A3e, S*B, 512, 0);
    split3_kernel<<<(T*B*128 + 255)/256, 256>>>(dec_emb, nullptr, dectok,        A3d, T*B, 512, 0);
    split3_kernel<<<(H3*128 + 255)/256, 256>>>(enc_Wih_f, nullptr, nullptr, B3f,  H3, 512, 1);
    split3_kernel<<<(H3*128 + 255)/256, 256>>>(enc_Wih_b, nullptr, nullptr, B3b_, H3, 512, 1);
    split3_kernel<<<(H3*128 + 255)/256, 256>>>(dec_Wih,   nullptr, nullptr, B3d_, H3, 512, 1);
    split3_kernel<<<(VOUT*128 + 255)/256, 256>>>(Wo, nullptr, nullptr, B3o, VOUT, 512, 1);
    split3_kernel<<<(H*256 + 255)/256, 256>>>(Wc, nullptr, nullptr, B3c, H, 1024, 1);

    // all three input-gate GEMMs in one launch (z selects)
    gemm_mma_kernel<128><<<dim3(S*B/128, H3/128, 3), 256, 98304>>>(
        A3e, A3d, B3f, B3b_, B3d_, enc_bih_f, enc_bih_b, dec_bih,
        Gx_f, Gx_b, Gd, nullptr, H3, H3, H3, 0);

    // encoder scans (fwd + bwd fused)
    ScanProb pf { Gx_f, nullptr, enc_Whh_f, enc_bhh_f, outs_f, 0 };
    ScanProb pk { Gx_b, nullptr, enc_Whh_b, enc_bhh_b, outs_b, 1 };
    gru_scan_kernel<<<128, 256, WSMEM>>>(pf, pk, 64, S, 128u, bars + 0);

    combine_kernel<<<(S * B * H + 255) / 256, 256>>>(enc_out, outs_f, outs_b, S * B * H);

    // decoder GRU chain
    ScanProb pd { Gd, outs_f + (size_t)(S - 1) * B * H, dec_Whh, dec_bhh, Hdec, 0 };
    gru_scan_kernel<<<64, 256, WSMEM>>>(pd, pd, 64, T, 64u, bars + 1);

    // batched attention
    attn_kernel<<<T * B, 256>>>(Hdec, enc_out, Ctx);

    // split [Hdec | Ctx] for the Wc GEMM
    split3_kernel<<<(T*B*256 + 255)/256, 256>>>(Hdec, Ctx, nullptr, A3c, T*B, 1024, 0);

    // c = tanh([h2,ctx] @ Wc^T + bc), fused split-store into A3v
    gemm_mma_kernel<128><<<dim3(T*B/128, H/128, 1), 256, 98304>>>(
        A3c, A3c, B3c, B3c, B3c, bc, bc, bc,
        nullptr, nullptr, nullptr, A3v, 3*1024, H, H, 2);

    // vocab projection: out = A3v @ B3o^T + bo  (256x128 tiles)
    gemm_mma_kernel<256><<<dim3(T*B/256, VOUT/128, 1), 256, 147456>>>(
        A3v, A3v, B3o, B3o, B3o, bo, bo, bo,
        out, out, out, nullptr, H3, VOUT, VOUT, 0);
}

// round 7
// speedup vs baseline: 1.6028x; 1.0334x over previous
#include <cuda_runtime.h>
#include <cuda_bf16.h>
#include <math.h>
#include <stdint.h>

#define H    512
#define H3   1536
#define S    48
#define T    48
#define B    32
#define VOUT 32000

typedef unsigned long long ull;

// ---------------- packed f32x2 helpers (scan kernel) ----------------
__device__ __forceinline__ ull pk2(float x, float y) {
    ull r; asm("mov.b64 %0, {%1,%2};" : "=l"(r) : "f"(x), "f"(y)); return r;
}
__device__ __forceinline__ void fma2(ull& d, ull a, ull b) {
    asm("fma.rn.f32x2 %0, %1, %2, %0;" : "+l"(d) : "l"(a), "l"(b));
}
__device__ __forceinline__ float2 upk(ull v) {
    float lo, hi; asm("mov.b64 {%0,%1}, %2;" : "=f"(lo), "=f"(hi) : "l"(v));
    float2 f; f.x = lo; f.y = hi; return f;
}

// ---------------- mma.sync helpers ----------------
__device__ __forceinline__ uint32_t smem_u32(const void* p) {
    uint32_t a;
    asm("{ .reg .u64 t; cvta.to.shared.u64 t, %1; cvt.u32.u64 %0, t; }" : "=r"(a) : "l"(p));
    return a;
}
#define LDSM4(r0, r1, r2, r3, addr) \
    asm volatile("ldmatrix.sync.aligned.m8n8.x4.shared.b16 {%0,%1,%2,%3}, [%4];" \
        : "=r"(r0), "=r"(r1), "=r"(r2), "=r"(r3) : "r"(addr))
#define MMA16816(d, a0, a1, a2, a3, b0, b1) \
    asm volatile("mma.sync.aligned.m16n8k16.row.col.f32.bf16.bf16.f32 " \
        "{%0,%1,%2,%3}, {%4,%5,%6,%7}, {%8,%9}, {%0,%1,%2,%3};" \
        : "+f"((d)[0]), "+f"((d)[1]), "+f"((d)[2]), "+f"((d)[3]) \
        : "r"(a0), "r"(a1), "r"(a2), "r"(a3), "r"(b0), "r"(b1))
__device__ __forceinline__ void cp16(uint32_t dst, const void* src) {
    asm volatile("cp.async.cg.shared.global [%0], [%1], 16;" :: "r"(dst), "l"(src));
}
#define CP_COMMIT() asm volatile("cp.async.commit_group;" ::: "memory")
#define CP_WAIT(n)  asm volatile("cp.async.wait_group %0;" :: "n"(n) : "memory")

// ---------------- device scratch ----------------
__device__ float g_Gall[3*S*B*H3];      // Gx_f | Gx_b | Gd (contiguous)
__device__ float g_outs_f[S*B*H];
__device__ float g_outs_b[S*B*H];
__device__ float g_enc_out[S*B*H];
__device__ float g_Hdec[T*B*H];
__device__ float g_Ctx [T*B*H];
__device__ int   g_dectok[T*B];
__device__ unsigned g_bars[2];
__device__ __nv_bfloat16 g_B3o[(size_t)VOUT*H3];  // split Wo   [hi,hi,lo]
__device__ __nv_bfloat16 g_A3e[S*B*H3];           // split enc emb (gathered)
__device__ __nv_bfloat16 g_A3d[T*B*H3];           // split dec emb (gathered)
__device__ __nv_bfloat16 g_B3f[H3*H3];            // split enc_Wih_f
__device__ __nv_bfloat16 g_B3b[H3*H3];            // split enc_Wih_b
__device__ __nv_bfloat16 g_B3d[H3*H3];            // split dec_Wih
__device__ __nv_bfloat16 g_B3c[H*3*1024];         // split Wc (K=1024)
__device__ __nv_bfloat16 g_A3c[T*B*3*1024];       // split [Hdec|Ctx]
__device__ __nv_bfloat16 g_A3v[T*B*H3];           // split c (written by Wc epi)

// ---------------- grid barrier ----------------
__device__ __forceinline__ void grid_bar(unsigned* bar, unsigned target) {
    __threadfence();
    __syncthreads();
    if (threadIdx.x == 0) {
        atomicAdd(bar, 1u);
        while (*(volatile unsigned*)bar < target) { __nanosleep(64); }
        __threadfence();
    }
    __syncthreads();
}

// ---------------- fp32 -> bf16 3-term split ---------------------------------
// mode 0 (A): segments [hi, lo, hi] ; mode 1 (B): segments [hi, hi, lo]
// optional row gather (gidx); optional src2 (cols >= 512 come from src2, K=1024 cat)
__global__ __launch_bounds__(256)
void split3_kernel(const float* __restrict__ src, const float* __restrict__ src2,
                   const int* __restrict__ gidx, __nv_bfloat16* __restrict__ dst,
                   int nrows, int K, int mode)
{
    int perrow = K >> 2;
    int idx = blockIdx.x * 256 + threadIdx.x;
    if (idx >= nrows * perrow) return;
    int row = idx / perrow, cc = (idx - row * perrow) * 4;
    const float* s;
    if (src2 && cc >= 512)      s = src2 + (size_t)row * 512 + (cc - 512);
    else if (src2)              s = src  + (size_t)row * 512 + cc;
    else if (gidx)              s = src  + (size_t)gidx[row] * K + cc;
    else                        s = src  + (size_t)row * K + cc;
    float4 v = *(const float4*)s;
    float f[4] = {v.x, v.y, v.z, v.w};
    __nv_bfloat16 h[4], l[4];
#pragma unroll
    for (int i = 0; i < 4; i++) {
        h[i] = __float2bfloat16(f[i]);
        l[i] = __float2bfloat16(f[i] - __bfloat162float(h[i]));
    }
    __nv_bfloat162 h01, h23, l01, l23;
    h01.x = h[0]; h01.y = h[1]; h23.x = h[2]; h23.y = h[3];
    l01.x = l[0]; l01.y = l[1]; l23.x = l[2]; l23.y = l[3];
    __nv_bfloat16* base = dst + (size_t)row * (3 * K);
    __nv_bfloat162* d0 = (__nv_bfloat162*)(base + cc);
    __nv_bfloat162* d1 = (__nv_bfloat162*)(base + K + cc);
    __nv_bfloat162* d2 = (__nv_bfloat162*)(base + 2 * K + cc);
    d0[0] = h01; d0[1] = h23;
    if (mode == 0) { d1[0] = l01; d1[1] = l23; d2[0] = h01; d2[1] = h23; }
    else           { d1[0] = h01; d1[1] = h23; d2[0] = l01; d2[1] = l23; }
}

// ---------------- mma.sync bf16 NT GEMM (3-stage cp.async pipeline) ---------
// C[m,n] = A3[m,:] . B3[n,:] + bias[n]   (K3 = 3*K bf16 columns)
// TM = 128 (warp tile 32x64) or 256 (warp tile 64x64). N tile = 128.
// grid = (M/TM, N/128, nprob); z selects {A,B,bias,out}.
// act 0: fp32 out (ldc stride). act 2: tanh + 3-term split store to outsplit
// (row stride 1536, K=512 layout) for the Wc GEMM.
template<int TM>
__global__ __launch_bounds__(256)
void gemm_mma_kernel(const __nv_bfloat16* __restrict__ A3a,
                     const __nv_bfloat16* __restrict__ A3b,
                     const __nv_bfloat16* __restrict__ B3_0,
                     const __nv_bfloat16* __restrict__ B3_1,
                     const __nv_bfloat16* __restrict__ B3_2,
                     const float* __restrict__ bias0,
                     const float* __restrict__ bias1,
                     const float* __restrict__ bias2,
                     float* __restrict__ out0, float* __restrict__ out1,
                     float* __restrict__ out2,
                     __nv_bfloat16* __restrict__ outsplit,
                     int K3, int N, int ldc, int act)
{
    constexpr int MI = TM / 64;                 // m16 frags per warp
    constexpr int ABYTES = TM * 128;            // A stage bytes (64 k-cols bf16)
    constexpr int BBYTES = 128 * 128;
    constexpr int STAGE = ABYTES + BBYTES;
    extern __shared__ __align__(1024) char smem[];

    const int z = blockIdx.z;
    const __nv_bfloat16* A3 = (z == 2) ? A3b : A3a;
    const __nv_bfloat16* B3 = (z == 0) ? B3_0 : ((z == 1) ? B3_1 : B3_2);
    const float* bias = (z == 0) ? bias0 : ((z == 1) ? bias1 : bias2);
    float* out = (z == 0) ? out0 : ((z == 1) ? out1 : out2);

    const int tid  = threadIdx.x;
    const int wid  = tid >> 5;
    const int lane = tid & 31;
    const int m0 = blockIdx.x * TM;
    const int n0 = blockIdx.y * 128;
    const int warp_m = wid & 3;
    const int warp_n = wid >> 2;
    const uint32_t sb = smem_u32(smem);

    const size_t K3b = (size_t)K3 * 2;
    const char* Ag = (const char*)A3 + (size_t)m0 * K3b;
    const char* Bg = (const char*)B3 + (size_t)n0 * K3b;
    const int nkt = K3 / 64;

    float d[MI][8][4];
#pragma unroll
    for (int i = 0; i < MI; i++)
#pragma unroll
        for (int j = 0; j < 8; j++)
#pragma unroll
            for (int q = 0; q < 4; q++) d[i][j][q] = 0.f;

    const int a_rowl = lane & 15;
    const int a_cb   = lane >> 4;
    const int b_rowb = warp_n * 64 + (lane & 7) + ((lane & 16) >> 1);
    const int b_cb   = (lane >> 3) & 1;

    auto issue = [&](int kt, int slot) {
        uint32_t Ab = sb + slot * STAGE;
        uint32_t Bb = Ab + ABYTES;
#pragma unroll
        for (int j = 0; j < ABYTES / 16 / 256; j++) {
            int id = tid + j * 256;
            int r = id >> 3, c = id & 7;
            cp16(Ab + r * 128 + ((c ^ (r & 7)) << 4), Ag + (size_t)r * K3b + kt * 128 + c * 16);
        }
#pragma unroll
        for (int j = 0; j < BBYTES / 16 / 256; j++) {
            int id = tid + j * 256;
            int r = id >> 3, c = id & 7;
            cp16(Bb + r * 128 + ((c ^ (r & 7)) << 4), Bg + (size_t)r * K3b + kt * 128 + c * 16);
        }
        CP_COMMIT();
    };

    issue(0, 0);
    issue(1, 1);

    int slot = 0, slot2 = 2;
    for (int kt = 0; kt < nkt; kt++) {
        if (kt + 1 < nkt) { CP_WAIT(1); } else { CP_WAIT(0); }
        __syncthreads();
        if (kt + 2 < nkt) {
            issue(kt + 2, slot2);
            if (++slot2 == 3) slot2 = 0;
        }
        uint32_t Ab = sb + slot * STAGE;
        uint32_t Bb = Ab + ABYTES;
        if (++slot == 3) slot = 0;
#pragma unroll
        for (int kk = 0; kk < 4; kk++) {
            uint32_t af[MI][4];
            int ca = kk * 2 + a_cb;
#pragma unroll
            for (int mi = 0; mi < MI; mi++) {
                int ar = warp_m * (MI * 16) + mi * 16 + a_rowl;
                LDSM4(af[mi][0], af[mi][1], af[mi][2], af[mi][3],
                      Ab + ar * 128 + ((ca ^ (ar & 7)) << 4));
            }
            int cb = kk * 2 + b_cb;
#pragma unroll
            for (int nt = 0; nt < 4; nt++) {
                int br = b_rowb + nt * 16;
                uint32_t b0, b1, b2, b3;
                LDSM4(b0, b1, b2, b3, Bb + br * 128 + ((cb ^ (br & 7)) << 4));
#pragma unroll
                for (int mi = 0; mi < MI; mi++) {
                    MMA16816(d[mi][2 * nt],     af[mi][0], af[mi][1], af[mi][2], af[mi][3], b0, b1);
                    MMA16816(d[mi][2 * nt + 1], af[mi][0], af[mi][1], af[mi][2], af[mi][3], b2, b3);
                }
            }
        }
        __syncthreads();
    }

    // epilogue
#pragma unroll
    for (int mi = 0; mi < MI; mi++) {
        int gm = m0 + warp_m * (MI * 16) + mi * 16 + (lane >> 2);
#pragma unroll
        for (int ni = 0; ni < 8; ni++) {
            int gn = n0 + warp_n * 64 + ni * 8 + (lane & 3) * 2;
            float2 bv = *(const float2*)(bias + gn);
            float v0 = d[mi][ni][0] + bv.x, v1 = d[mi][ni][1] + bv.y;
            float v2 = d[mi][ni][2] + bv.x, v3 = d[mi][ni][3] + bv.y;
            if (act == 2) {
                v0 = tanhf(v0); v1 = tanhf(v1); v2 = tanhf(v2); v3 = tanhf(v3);
                __nv_bfloat16 h0 = __float2bfloat16(v0), h1 = __float2bfloat16(v1);
                __nv_bfloat16 h2 = __float2bfloat16(v2), h3 = __float2bfloat16(v3);
                __nv_bfloat162 ph0; ph0.x = h0; ph0.y = h1;
                __nv_bfloat162 pl0;
                pl0.x = __float2bfloat16(v0 - __bfloat162float(h0));
                pl0.y = __float2bfloat16(v1 - __bfloat162float(h1));
                __nv_bfloat162 ph1; ph1.x = h2; ph1.y = h3;
                __nv_bfloat162 pl1;
                pl1.x = __float2bfloat16(v2 - __bfloat162float(h2));
                pl1.y = __float2bfloat16(v3 - __bfloat162float(h3));
                __nv_bfloat16* r0 = outsplit + (size_t)gm * H3;
                __nv_bfloat16* r1 = outsplit + (size_t)(gm + 8) * H3;
                *(__nv_bfloat162*)(r0 + gn) = ph0;
                *(__nv_bfloat162*)(r0 + 512 + gn) = pl0;
                *(__nv_bfloat162*)(r0 + 1024 + gn) = ph0;
                *(__nv_bfloat162*)(r1 + gn) = ph1;
                *(__nv_bfloat162*)(r1 + 512 + gn) = pl1;
                *(__nv_bfloat162*)(r1 + 1024 + gn) = ph1;
            } else {
                float2 o0, o1;
                o0.x = v0; o0.y = v1; o1.x = v2; o1.y = v3;
                *(float2*)(out + (size_t)gm * ldc + gn) = o0;
                *(float2*)(out + (size_t)(gm + 8) * ldc + gn) = o1;
            }
        }
    }
}

// ---------------- persistent GRU scan ----------------
struct ScanProb {
    const float* gx;
    const float* seed;
    const float* whh;
    const float* bhh;
    float*       outs;
    int          dir;
};

__global__ __launch_bounds__(256)
void gru_scan_kernel(ScanProb pa, ScanProb pb, int bpp, int nsteps,
                     unsigned nblocks, unsigned* bar)
{
    extern __shared__ float w_s[];
    ScanProb p = (blockIdx.x < bpp) ? pa : pb;
    const int blk = blockIdx.x % bpp;
    const int h0  = blk * 8;
    const int tid = threadIdx.x;
    const int b   = tid >> 3;
    const int hi  = tid & 7;

    for (int id = tid; id < 24 * 128; id += 256) {
        int row = id >> 7, c4 = (id & 127) * 4;
        int g = row >> 3, hh = h0 + (row & 7);
        *(float4*)&w_s[row * 516 + c4] =
            *(const float4*)(p.whh + (size_t)(g * H + hh) * H + c4);
    }
    __syncthreads();

    const ull* wr2 = (const ull*)&w_s[hi * 516];
    const ull* wz2 = (const ull*)&w_s[(8 + hi) * 516];
    const ull* wn2 = (const ull*)&w_s[(16 + hi) * 516];

    const int h = h0 + hi;
    const float br = p.bhh[h], bz = p.bhh[H + h], bn = p.bhh[2 * H + h];

    for (int i = 0; i < nsteps; i++) {
        const int t = p.dir ? (nsteps - 1 - i) : i;
        const float* hprev = (i == 0) ? p.seed
                           : p.outs + (size_t)(p.dir ? t + 1 : t - 1) * B * H;
        ull ar2 = 0, az2 = 0, an2 = 0;
        float hp_val = 0.f;
        if (hprev) {
            const float4* hp4 = (const float4*)(hprev + b * H);
#pragma unroll 8
            for (int c = 0; c < 128; c++) {
                float4 hv = __ldg(&hp4[c]);
                ull h01 = pk2(hv.x, hv.y), h23 = pk2(hv.z, hv.w);
                fma2(ar2, h01, wr2[2*c]); fma2(ar2, h23, wr2[2*c+1]);
                fma2(az2, h01, wz2[2*c]); fma2(az2, h23, wz2[2*c+1]);
                fma2(an2, h01, wn2[2*c]); fma2(an2, h23, wn2[2*c+1]);
            }
            hp_val = __ldg(hprev + b * H + h);
        }
        float2 fr = upk(ar2), fz = upk(az2), fn = upk(an2);
        const float* gx = p.gx + ((size_t)t * B + b) * H3;
        float r = 1.f / (1.f + expf(-(gx[h]       + fr.x + fr.y + br)));
        float z = 1.f / (1.f + expf(-(gx[H + h]   + fz.x + fz.y + bz)));
        float n = tanhf(gx[2 * H + h] + r * (fn.x + fn.y + bn));
        p.outs[((size_t)t * B + b) * H + h] = (1.f - z) * n + z * hp_val;

        if (i < nsteps - 1) grid_bar(bar, nblocks * (unsigned)(i + 1));
    }
}

// ---------------- batched attention ----------------
__global__ __launch_bounds__(256)
void attn_kernel(const float* __restrict__ Hdec, const float* __restrict__ enc,
                 float* __restrict__ Ctx)
{
    const int t = blockIdx.x / B;
    const int b = blockIdx.x % B;
    const float* h2 = Hdec + ((size_t)t * B + b) * H;
    const int tid = threadIdx.x;
    const int lane = tid & 31, w = tid >> 5;
    __shared__ float h2_s[H];
    __shared__ float sc[S];

    h2_s[tid]       = h2[tid];
    h2_s[tid + 256] = h2[tid + 256];
    __syncthreads();

    for (int s = w; s < S; s += 8) {
        const float4* e  = (const float4*)(enc + (size_t)(s * B + b) * H);
        const float4* h4 = (const float4*)h2_s;
        float p = 0.f;
#pragma unroll
        for (int j = 0; j < 4; j++) {
            float4 ev = e[lane + j * 32];
            float4 hv = h4[lane + j * 32];
            p = fmaf(ev.x, hv.x, p); p = fmaf(ev.y, hv.y, p);
            p = fmaf(ev.z, hv.z, p); p = fmaf(ev.w, hv.w, p);
        }
#pragma unroll
        for (int o = 16; o > 0; o >>= 1) p += __shfl_xor_sync(0xffffffffu, p, o);
        if (lane == 0) sc[s] = p;
    }
    __syncthreads();

    if (w == 0) {
        float a  = sc[lane];
        float b2 = (lane < 16) ? sc[32 + lane] : -1e30f;
        float m = fmaxf(a, b2);
#pragma unroll
        for (int o = 16; o > 0; o >>= 1) m = fmaxf(m, __shfl_xor_sync(0xffffffffu, m, o));
        float ea = expf(a - m);
        float eb = (lane < 16) ? expf(b2 - m) : 0.f;
        float ss = ea + eb;
#pragma unroll
        for (int o = 16; o > 0; o >>= 1) ss += __shfl_xor_sync(0xffffffffu, ss, o);
        float inv = 1.f / ss;
        sc[lane] = ea * inv;
        if (lane < 16) sc[32 + lane] = eb * inv;
    }
    __syncthreads();

    float a0 = 0.f, a1 = 0.f;
    for (int s = 0; s < S; s++) {
        float at = sc[s];
        const float* e = enc + (size_t)(s * B + b) * H;
        a0 = fmaf(at, e[tid], a0);
        a1 = fmaf(at, e[tid + 256], a1);
    }
    float* co = Ctx + ((size_t)t * B + b) * H;
    co[tid]       = a0;
    co[tid + 256] = a1;
}

// ---------------- small utilities ----------------
__global__ void combine_kernel(float* __restrict__ out, const float* __restrict__ a,
                               const float* __restrict__ b, int n)
{
    int i = blockIdx.x * blockDim.x + threadIdx.x;
    if (i < n) out[i] = a[i] + b[i];
}

__global__ void init_kernel(int* __restrict__ out, const int* __restrict__ target,
                            unsigned* __restrict__ bars)
{
    int i = blockIdx.x * blockDim.x + threadIdx.x;
    if (i < 2) bars[i] = 0u;
    if (i < T * B) out[i] = (i < B) ? 1 /*SOS*/ : target[i - B];
}

// ---------------- launch ------------------------------------------------------
extern "C" void kernel_launch(void* const* d_in, const int* in_sizes, int n_in,
                              void* d_out, int out_size)
{
    const int*   input_batches  = (const int*)d_in[0];
    const int*   target_batches = (const int*)d_in[1];
    const float* enc_emb   = (const float*)d_in[2];
    const float* enc_Wih_f = (const float*)d_in[3];
    const float* enc_Whh_f = (const float*)d_in[4];
    const float* enc_bih_f = (const float*)d_in[5];
    const float* enc_bhh_f = (const float*)d_in[6];
    const float* enc_Wih_b = (const float*)d_in[7];
    const float* enc_Whh_b = (const float*)d_in[8];
    const float* enc_bih_b = (const float*)d_in[9];
    const float* enc_bhh_b = (const float*)d_in[10];
    const float* dec_emb   = (const float*)d_in[11];
    const float* dec_Wih   = (const float*)d_in[12];
    const float* dec_Whh   = (const float*)d_in[13];
    const float* dec_bih   = (const float*)d_in[14];
    const float* dec_bhh   = (const float*)d_in[15];
    const float* Wc        = (const float*)d_in[16];
    const float* bc        = (const float*)d_in[17];
    const float* Wo        = (const float*)d_in[18];
    const float* bo        = (const float*)d_in[19];
    float* out = (float*)d_out;

    float *Gall, *outs_f, *outs_b, *enc_out, *Hdec, *Ctx;
    int* dectok; unsigned* bars;
    __nv_bfloat16 *B3o, *A3e, *A3d, *B3f, *B3b_, *B3d_, *B3c, *A3c, *A3v;
    cudaGetSymbolAddress((void**)&Gall,   g_Gall);
    cudaGetSymbolAddress((void**)&outs_f, g_outs_f);
    cudaGetSymbolAddress((void**)&outs_b, g_outs_b);
    cudaGetSymbolAddress((void**)&enc_out,g_enc_out);
    cudaGetSymbolAddress((void**)&Hdec,   g_Hdec);
    cudaGetSymbolAddress((void**)&Ctx,    g_Ctx);
    cudaGetSymbolAddress((void**)&dectok, g_dectok);
    cudaGetSymbolAddress((void**)&bars,   g_bars);
    cudaGetSymbolAddress((void**)&B3o,    g_B3o);
    cudaGetSymbolAddress((void**)&A3e,    g_A3e);
    cudaGetSymbolAddress((void**)&A3d,    g_A3d);
    cudaGetSymbolAddress((void**)&B3f,    g_B3f);
    cudaGetSymbolAddress((void**)&B3b_,   g_B3b);
    cudaGetSymbolAddress((void**)&B3d_,   g_B3d);
    cudaGetSymbolAddress((void**)&B3c,    g_B3c);
    cudaGetSymbolAddress((void**)&A3c,    g_A3c);
    cudaGetSymbolAddress((void**)&A3v,    g_A3v);

    float* Gx_f = Gall;
    float* Gx_b = Gall + (size_t)S * B * H3;
    float* Gd   = Gall + (size_t)2 * S * B * H3;

    const int WSMEM = 24 * 516 * 4;
    cudaFuncSetAttribute(gru_scan_kernel,
                         cudaFuncAttributeMaxDynamicSharedMemorySize, WSMEM);
    cudaFuncSetAttribute(gemm_mma_kernel<128>,
                         cudaFuncAttributeMaxDynamicSharedMemorySize, 98304);
    cudaFuncSetAttribute(gemm_mma_kernel<256>,
                         cudaFuncAttributeMaxDynamicSharedMemorySize, 147456);

    init_kernel<<<(T * B + 255) / 256, 256>>>(dectok, target_batches, bars);

    // splits (bf16 3-term)
    split3_kernel<<<(S*B*128 + 255)/256, 256>>>(enc_emb, nullptr, input_batches, A3e, S*B, 512, 0);
    split3_kernel<<<(T*B*128 + 255)/256, 256>>>(dec_emb, nullptr, dectok,        A3d, T*B, 512, 0);
    split3_kernel<<<(H3*128 + 255)/256, 256>>>(enc_Wih_f, nullptr, nullptr, B3f,  H3, 512, 1);
    split3_kernel<<<(H3*128 + 255)/256, 256>>>(enc_Wih_b, nullptr, nullptr, B3b_, H3, 512, 1);
    split3_kernel<<<(H3*128 + 255)/256, 256>>>(dec_Wih,   nullptr, nullptr, B3d_, H3, 512, 1);
    split3_kernel<<<(VOUT*128 + 255)/256, 256>>>(Wo, nullptr, nullptr, B3o, VOUT, 512, 1);
    split3_kernel<<<(H*256 + 255)/256, 256>>>(Wc, nullptr, nullptr, B3c, H, 1024, 1);

    // all three input-gate GEMMs in one launch (z selects)
    gemm_mma_kernel<128><<<dim3(S*B/128, H3/128, 3), 256, 98304>>>(
        A3e, A3d, B3f, B3b_, B3d_, enc_bih_f, enc_bih_b, dec_bih,
        Gx_f, Gx_b, Gd, nullptr, H3, H3, H3, 0);

    // encoder scans (fwd + bwd fused)
    ScanProb pf { Gx_f, nullptr, enc_Whh_f, enc_bhh_f, outs_f, 0 };
    ScanProb pk { Gx_b, nullptr, enc_Whh_b, enc_bhh_b, outs_b, 1 };
    gru_scan_kernel<<<128, 256, WSMEM>>>(pf, pk, 64, S, 128u, bars + 0);

    combine_kernel<<<(S * B * H + 255) / 256, 256>>>(enc_out, outs_f, outs_b, S * B * H);

    // decoder GRU chain
    ScanProb pd { Gd, outs_f + (size_t)(S - 1) * B * H, dec_Whh, dec_bhh, Hdec, 0 };
    gru_scan_kernel<<<64, 256, WSMEM>>>(pd, pd, 64, T, 64u, bars + 1);

    // batched attention
    attn_kernel<<<T * B, 256>>>(Hdec, enc_out, Ctx);

    // split [Hdec | Ctx] for the Wc GEMM
    split3_kernel<<<(T*B*256 + 255)/256, 256>>>(Hdec, Ctx, nullptr, A3c, T*B, 1024, 0);

    // c = tanh([h2,ctx] @ Wc^T + bc), fused split-store into A3v
    gemm_mma_kernel<128><<<dim3(T*B/128, H/128, 1), 256, 98304>>>(
        A3c, A3c, B3c, B3c, B3c, bc, bc, bc,
        nullptr, nullptr, nullptr, A3v, 3*1024, H, H, 2);

    // vocab projection: out = A3v @ B3o^T + bo  (256x128 tiles)
    gemm_mma_kernel<256><<<dim3(T*B/256, VOUT/128, 1), 256, 147456>>>(
        A3v, A3v, B3o, B3o, B3o, bo, bo, bo,
        out, out, out, nullptr, H3, VOUT, VOUT, 0);
}

// round 10
// speedup vs baseline: 1.8554x; 1.1576x over previous
#include <cuda_runtime.h>
#include <cuda_bf16.h>
#include <cuda_fp16.h>
#include <math.h>
#include <stdint.h>

#define H    512
#define H3   1536
#define S    48
#define T    48
#define B    32
#define VOUT 32000

typedef unsigned long long ull;

// ---------------- packed f32x2 helpers (scan kernel) ----------------
__device__ __forceinline__ ull pk2(float x, float y) {
    ull r; asm("mov.b64 %0, {%1,%2};" : "=l"(r) : "f"(x), "f"(y)); return r;
}
__device__ __forceinline__ void fma2(ull& d, ull a, ull b) {
    asm("fma.rn.f32x2 %0, %1, %2, %0;" : "+l"(d) : "l"(a), "l"(b));
}
__device__ __forceinline__ float2 upk(ull v) {
    float lo, hi; asm("mov.b64 {%0,%1}, %2;" : "=f"(lo), "=f"(hi) : "l"(v));
    float2 f; f.x = lo; f.y = hi; return f;
}

// ---------------- mma.sync helpers ----------------
__device__ __forceinline__ uint32_t smem_u32(const void* p) {
    uint32_t a;
    asm("{ .reg .u64 t; cvta.to.shared.u64 t, %1; cvt.u32.u64 %0, t; }" : "=r"(a) : "l"(p));
    return a;
}
#define LDSM4(r0, r1, r2, r3, addr) \
    asm volatile("ldmatrix.sync.aligned.m8n8.x4.shared.b16 {%0,%1,%2,%3}, [%4];" \
        : "=r"(r0), "=r"(r1), "=r"(r2), "=r"(r3) : "r"(addr))
__device__ __forceinline__ void mma_bf16_(float* d, uint32_t a0, uint32_t a1,
                                          uint32_t a2, uint32_t a3,
                                          uint32_t b0, uint32_t b1) {
    asm volatile("mma.sync.aligned.m16n8k16.row.col.f32.bf16.bf16.f32 "
        "{%0,%1,%2,%3}, {%4,%5,%6,%7}, {%8,%9}, {%0,%1,%2,%3};"
        : "+f"(d[0]), "+f"(d[1]), "+f"(d[2]), "+f"(d[3])
        : "r"(a0), "r"(a1), "r"(a2), "r"(a3), "r"(b0), "r"(b1));
}
__device__ __forceinline__ void mma_f16_(float* d, uint32_t a0, uint32_t a1,
                                         uint32_t a2, uint32_t a3,
                                         uint32_t b0, uint32_t b1) {
    asm volatile("mma.sync.aligned.m16n8k16.row.col.f32.f16.f16.f32 "
        "{%0,%1,%2,%3}, {%4,%5,%6,%7}, {%8,%9}, {%0,%1,%2,%3};"
        : "+f"(d[0]), "+f"(d[1]), "+f"(d[2]), "+f"(d[3])
        : "r"(a0), "r"(a1), "r"(a2), "r"(a3), "r"(b0), "r"(b1));
}
__device__ __forceinline__ void cp16(uint32_t dst, const void* src) {
    asm volatile("cp.async.cg.shared.global [%0], [%1], 16;" :: "r"(dst), "l"(src));
}
#define CP_COMMIT() asm volatile("cp.async.commit_group;" ::: "memory")
#define CP_WAIT(n)  asm volatile("cp.async.wait_group %0;" :: "n"(n) : "memory")

// ---------------- device scratch ----------------
__device__ float g_Gall[3*S*B*H3];      // Gx_f | Gx_b | Gd
__device__ float g_outs_f[S*B*H];
__device__ float g_outs_b[S*B*H];
__device__ float g_enc_out[S*B*H];
__device__ float g_Hdec[T*B*H];
__device__ float g_Ctx [T*B*H];
__device__ int   g_dectok[T*B];
__device__ unsigned g_bars[2];
__device__ __half g_B2o[(size_t)VOUT*1024];       // Wo fp16 [hi, hi]
__device__ __half g_A2v[(size_t)T*B*1024];        // c  fp16 [hi, lo]
__device__ __nv_bfloat16 g_A3e[S*B*H3];           // split enc emb (gathered)
__device__ __nv_bfloat16 g_A3d[T*B*H3];           // split dec emb (gathered)
__device__ __nv_bfloat16 g_B3f[H3*H3];            // split enc_Wih_f
__device__ __nv_bfloat16 g_B3b[H3*H3];            // split enc_Wih_b
__device__ __nv_bfloat16 g_B3d[H3*H3];            // split dec_Wih
__device__ __nv_bfloat16 g_B3c[H*3*1024];         // split Wc (K=1024)
__device__ __nv_bfloat16 g_A3c[T*B*3*1024];       // split [Hdec|Ctx]

// ---------------- grid barrier ----------------
__device__ __forceinline__ void grid_bar(unsigned* bar, unsigned target) {
    __threadfence();
    __syncthreads();
    if (threadIdx.x == 0) {
        atomicAdd(bar, 1u);
        while (*(volatile unsigned*)bar < target) { __nanosleep(64); }
        __threadfence();
    }
    __syncthreads();
}

// ---------------- fp32 -> 16-bit splits --------------------------------------
// mode 0 (A,bf16): [hi, lo, hi]  mode 1 (B,bf16): [hi, hi, lo]  (stride 3K)
// mode 2 (B,fp16): [hi, hi]                                     (stride 2K)
__global__ __launch_bounds__(256)
void split3_kernel(const float* __restrict__ src, const float* __restrict__ src2,
                   const int* __restrict__ gidx, __nv_bfloat16* __restrict__ dst,
                   int nrows, int K, int mode)
{
    int perrow = K >> 2;
    int idx = blockIdx.x * 256 + threadIdx.x;
    if (idx >= nrows * perrow) return;
    int row = idx / perrow, cc = (idx - row * perrow) * 4;
    const float* s;
    if (src2 && cc >= 512)      s = src2 + (size_t)row * 512 + (cc - 512);
    else if (src2)              s = src  + (size_t)row * 512 + cc;
    else if (gidx)              s = src  + (size_t)gidx[row] * K + cc;
    else                        s = src  + (size_t)row * K + cc;
    float4 v = *(const float4*)s;
    float f[4] = {v.x, v.y, v.z, v.w};

    if (mode == 2) {
        __half hh[4];
#pragma unroll
        for (int i = 0; i < 4; i++) hh[i] = __float2half_rn(f[i]);
        __half2 p01 = __halves2half2(hh[0], hh[1]);
        __half2 p23 = __halves2half2(hh[2], hh[3]);
        __half* base = ((__half*)dst) + (size_t)row * (2 * K);
        *(__half2*)(base + cc) = p01;      *(__half2*)(base + cc + 2) = p23;
        *(__half2*)(base + K + cc) = p01;  *(__half2*)(base + K + cc + 2) = p23;
        return;
    }

    __nv_bfloat16 h[4], l[4];
#pragma unroll
    for (int i = 0; i < 4; i++) {
        h[i] = __float2bfloat16(f[i]);
        l[i] = __float2bfloat16(f[i] - __bfloat162float(h[i]));
    }
    __nv_bfloat162 h01, h23, l01, l23;
    h01.x = h[0]; h01.y = h[1]; h23.x = h[2]; h23.y = h[3];
    l01.x = l[0]; l01.y = l[1]; l23.x = l[2]; l23.y = l[3];
    __nv_bfloat16* base = dst + (size_t)row * (3 * K);
    __nv_bfloat162* d0 = (__nv_bfloat162*)(base + cc);
    __nv_bfloat162* d1 = (__nv_bfloat162*)(base + K + cc);
    __nv_bfloat162* d2 = (__nv_bfloat162*)(base + 2 * K + cc);
    d0[0] = h01; d0[1] = h23;
    if (mode == 0) { d1[0] = l01; d1[1] = l23; d2[0] = h01; d2[1] = h23; }
    else           { d1[0] = h01; d1[1] = h23; d2[0] = l01; d2[1] = l23; }
}

// ---------------- mma.sync 16-bit NT GEMM (3-stage cp.async pipeline) -------
// C[m,n] = A[m,:] . B[n,:] + bias[n]   (Kx = total 16-bit K columns)
// grid = (M/128, N/128, nprob); z selects {A,B,bias,out}.
// act 0: fp32 out. act 2: tanh + fp16 [hi,lo] split store (stride 1024).
template<int TM, bool FP16>
__global__ __launch_bounds__(256, 2)
void gemm_mma_kernel(const __nv_bfloat16* __restrict__ A3a,
                     const __nv_bfloat16* __restrict__ A3b,
                     const __nv_bfloat16* __restrict__ B3_0,
                     const __nv_bfloat16* __restrict__ B3_1,
                     const __nv_bfloat16* __restrict__ B3_2,
                     const float* __restrict__ bias0,
                     const float* __restrict__ bias1,
                     const float* __restrict__ bias2,
                     float* __restrict__ out0, float* __restrict__ out1,
                     float* __restrict__ out2,
                     __half* __restrict__ outsplit,
                     int K3, int N, int ldc, int act)
{
    constexpr int MI = TM / 64;
    constexpr int ABYTES = TM * 128;
    constexpr int BBYTES = 128 * 128;
    constexpr int STAGE = ABYTES + BBYTES;
    extern __shared__ __align__(1024) char smem[];

    const int z = blockIdx.z;
    const __nv_bfloat16* A3 = (z == 2) ? A3b : A3a;
    const __nv_bfloat16* B3 = (z == 0) ? B3_0 : ((z == 1) ? B3_1 : B3_2);
    const float* bias = (z == 0) ? bias0 : ((z == 1) ? bias1 : bias2);
    float* out = (z == 0) ? out0 : ((z == 1) ? out1 : out2);

    const int tid  = threadIdx.x;
    const int wid  = tid >> 5;
    const int lane = tid & 31;
    const int m0 = blockIdx.x * TM;
    const int n0 = blockIdx.y * 128;
    const int warp_m = wid & 3;
    const int warp_n = wid >> 2;
    const uint32_t sb = smem_u32(smem);

    const size_t K3b = (size_t)K3 * 2;
    const char* Ag = (const char*)A3 + (size_t)m0 * K3b;
    const char* Bg = (const char*)B3 + (size_t)n0 * K3b;
    const int nkt = K3 / 64;

    float d[MI][8][4];
#pragma unroll
    for (int i = 0; i < MI; i++)
#pragma unroll
        for (int j = 0; j < 8; j++)
#pragma unroll
            for (int q = 0; q < 4; q++) d[i][j][q] = 0.f;

    const int a_rowl = lane & 15;
    const int a_cb   = lane >> 4;
    const int b_rowb = warp_n * 64 + (lane & 7) + ((lane & 16) >> 1);
    const int b_cb   = (lane >> 3) & 1;

    auto issue = [&](int kt, int slot) {
        uint32_t Ab = sb + slot * STAGE;
        uint32_t Bb = Ab + ABYTES;
#pragma unroll
        for (int j = 0; j < ABYTES / 16 / 256; j++) {
            int id = tid + j * 256;
            int r = id >> 3, c = id & 7;
            cp16(Ab + r * 128 + ((c ^ (r & 7)) << 4), Ag + (size_t)r * K3b + kt * 128 + c * 16);
        }
#pragma unroll
        for (int j = 0; j < BBYTES / 16 / 256; j++) {
            int id = tid + j * 256;
            int r = id >> 3, c = id & 7;
            cp16(Bb + r * 128 + ((c ^ (r & 7)) << 4), Bg + (size_t)r * K3b + kt * 128 + c * 16);
        }
        CP_COMMIT();
    };

    issue(0, 0);
    issue(1, 1);

    int slot = 0, slot2 = 2;
    for (int kt = 0; kt < nkt; kt++) {
        if (kt + 1 < nkt) { CP_WAIT(1); } else { CP_WAIT(0); }
        __syncthreads();
        if (kt + 2 < nkt) {
            issue(kt + 2, slot2);
            if (++slot2 == 3) slot2 = 0;
        }
        uint32_t Ab = sb + slot * STAGE;
        uint32_t Bb = Ab + ABYTES;
        if (++slot == 3) slot = 0;
#pragma unroll
        for (int kk = 0; kk < 4; kk++) {
            uint32_t af[MI][4];
            int ca = kk * 2 + a_cb;
#pragma unroll
            for (int mi = 0; mi < MI; mi++) {
                int ar = warp_m * (MI * 16) + mi * 16 + a_rowl;
                LDSM4(af[mi][0], af[mi][1], af[mi][2], af[mi][3],
                      Ab + ar * 128 + ((ca ^ (ar & 7)) << 4));
            }
            int cb = kk * 2 + b_cb;
#pragma unroll
            for (int nt = 0; nt < 4; nt++) {
                int br = b_rowb + nt * 16;
                uint32_t b0, b1, b2, b3;
                LDSM4(b0, b1, b2, b3, Bb + br * 128 + ((cb ^ (br & 7)) << 4));
#pragma unroll
                for (int mi = 0; mi < MI; mi++) {
                    if (FP16) {
                        mma_f16_(d[mi][2*nt],   af[mi][0], af[mi][1], af[mi][2], af[mi][3], b0, b1);
                        mma_f16_(d[mi][2*nt+1], af[mi][0], af[mi][1], af[mi][2], af[mi][3], b2, b3);
                    } else {
                        mma_bf16_(d[mi][2*nt],   af[mi][0], af[mi][1], af[mi][2], af[mi][3], b0, b1);
                        mma_bf16_(d[mi][2*nt+1], af[mi][0], af[mi][1], af[mi][2], af[mi][3], b2, b3);
                    }
                }
            }
        }
        __syncthreads();
    }

    // epilogue
#pragma unroll
    for (int mi = 0; mi < MI; mi++) {
        int gm = m0 + warp_m * (MI * 16) + mi * 16 + (lane >> 2);
#pragma unroll
        for (int ni = 0; ni < 8; ni++) {
            int gn = n0 + warp_n * 64 + ni * 8 + (lane & 3) * 2;
            float2 bv = *(const float2*)(bias + gn);
            float v0 = d[mi][ni][0] + bv.x, v1 = d[mi][ni][1] + bv.y;
            float v2 = d[mi][ni][2] + bv.x, v3 = d[mi][ni][3] + bv.y;
            if (act == 2) {
                v0 = tanhf(v0); v1 = tanhf(v1); v2 = tanhf(v2); v3 = tanhf(v3);
                __half h0 = __float2half_rn(v0), h1 = __float2half_rn(v1);
                __half h2 = __float2half_rn(v2), h3 = __float2half_rn(v3);
                __half2 ph0 = __halves2half2(h0, h1);
                __half2 pl0 = __halves2half2(__float2half_rn(v0 - __half2float(h0)),
                                             __float2half_rn(v1 - __half2float(h1)));
                __half2 ph1 = __halves2half2(h2, h3);
                __half2 pl1 = __halves2half2(__float2half_rn(v2 - __half2float(h2)),
                                             __float2half_rn(v3 - __half2float(h3)));
                __half* r0 = outsplit + (size_t)gm * 1024;
                __half* r1 = outsplit + (size_t)(gm + 8) * 1024;
                *(__half2*)(r0 + gn) = ph0;
                *(__half2*)(r0 + 512 + gn) = pl0;
                *(__half2*)(r1 + gn) = ph1;
                *(__half2*)(r1 + 512 + gn) = pl1;
            } else {
                float2 o0, o1;
                o0.x = v0; o0.y = v1; o1.x = v2; o1.y = v3;
                *(float2*)(out + (size_t)gm * ldc + gn) = o0;
                *(float2*)(out + (size_t)(gm + 8) * ldc + gn) = o1;
            }
        }
    }
}

// ---------------- persistent GRU scan (COLS h-cols per block) ---------------
struct ScanProb {
    const float* gx;
    const float* seed;
    const float* whh;
    const float* bhh;
    float*       outs;
    int          dir;
};

template<int COLS>   // 8: 1 K-seg per thread; 4: 2-way K split + shfl combine
__global__ __launch_bounds__(256)
void gru_scan_kernel(ScanProb pa, ScanProb pb, int bpp, int nsteps,
                     unsigned nblocks, unsigned* bar)
{
    constexpr int KSEG = 64 * COLS;     // 512 or 256
    constexpr int NW = 3 * COLS;
    extern __shared__ float w_s[];
    ScanProb p = (blockIdx.x < bpp) ? pa : pb;
    const int blk = blockIdx.x % bpp;
    const int h0  = blk * COLS;
    const int tid = threadIdx.x;
    const int b    = tid >> 3;
    const int slot = tid & 7;
    const int col  = slot % COLS;
    const int kh   = slot / COLS;       // 0 (COLS=8) or 0/1 (COLS=4)
    const int koff = kh * KSEG;

    for (int id = tid; id < NW * 128; id += 256) {
        int row = id >> 7, c4 = (id & 127) * 4;
        int g = row / COLS, cc = row % COLS;
        *(float4*)&w_s[row * 516 + c4] =
            *(const float4*)(p.whh + (size_t)(g * H + h0 + cc) * H + c4);
    }
    __syncthreads();

    const ull* wr2 = (const ull*)&w_s[col * 516 + koff];
    const ull* wz2 = (const ull*)&w_s[(COLS + col) * 516 + koff];
    const ull* wn2 = (const ull*)&w_s[(2 * COLS + col) * 516 + koff];

    const int h = h0 + col;
    const float br = p.bhh[h], bz = p.bhh[H + h], bn = p.bhh[2 * H + h];

    for (int i = 0; i < nsteps; i++) {
        const int t = p.dir ? (nsteps - 1 - i) : i;
        const float* hprev = (i == 0) ? p.seed
                           : p.outs + (size_t)(p.dir ? t + 1 : t - 1) * B * H;
        ull ar2 = 0, az2 = 0, an2 = 0;
        if (hprev) {
            const float4* hp4 = (const float4*)(hprev + b * H + koff);
#pragma unroll 8
            for (int c = 0; c < KSEG / 4; c++) {
                float4 hv = __ldg(&hp4[c]);
                ull h01 = pk2(hv.x, hv.y), h23 = pk2(hv.z, hv.w);
                fma2(ar2, h01, wr2[2*c]); fma2(ar2, h23, wr2[2*c+1]);
                fma2(az2, h01, wz2[2*c]); fma2(az2, h23, wz2[2*c+1]);
                fma2(an2, h01, wn2[2*c]); fma2(an2, h23, wn2[2*c+1]);
            }
        }
        float2 fr = upk(ar2), fz = upk(az2), fn = upk(an2);
        float ar = fr.x + fr.y, az = fz.x + fz.y, an = fn.x + fn.y;
        if (COLS == 4) {
            ar += __shfl_xor_sync(0xffffffffu, ar, 4);
            az += __shfl_xor_sync(0xffffffffu, az, 4);
            an += __shfl_xor_sync(0xffffffffu, an, 4);
        }
        if (kh == 0) {
            float hp_val = hprev ? __ldg(hprev + b * H + h) : 0.f;
            const float* gx = p.gx + ((size_t)t * B + b) * H3;
            float r = 1.f / (1.f + expf(-(gx[h]       + ar + br)));
            float z = 1.f / (1.f + expf(-(gx[H + h]   + az + bz)));
            float n = tanhf(gx[2 * H + h] + r * (an + bn));
            p.outs[((size_t)t * B + b) * H + h] = (1.f - z) * n + z * hp_val;
        }
        if (i < nsteps - 1) grid_bar(bar, nblocks * (unsigned)(i + 1));
    }
}

// ---------------- batched attention ----------------
__global__ __launch_bounds__(256)
void attn_kernel(const float* __restrict__ Hdec, const float* __restrict__ enc,
                 float* __restrict__ Ctx)
{
    const int t = blockIdx.x / B;
    const int b = blockIdx.x % B;
    const float* h2 = Hdec + ((size_t)t * B + b) * H;
    const int tid = threadIdx.x;
    const int lane = tid & 31, w = tid >> 5;
    __shared__ float h2_s[H];
    __shared__ float sc[S];

    h2_s[tid]       = h2[tid];
    h2_s[tid + 256] = h2[tid + 256];
    __syncthreads();

    for (int s = w; s < S; s += 8) {
        const float4* e  = (const float4*)(enc + (size_t)(s * B + b) * H);
        const float4* h4 = (const float4*)h2_s;
        float p = 0.f;
#pragma unroll
        for (int j = 0; j < 4; j++) {
            float4 ev = e[lane + j * 32];
            float4 hv = h4[lane + j * 32];
            p = fmaf(ev.x, hv.x, p); p = fmaf(ev.y, hv.y, p);
            p = fmaf(ev.z, hv.z, p); p = fmaf(ev.w, hv.w, p);
        }
#pragma unroll
        for (int o = 16; o > 0; o >>= 1) p += __shfl_xor_sync(0xffffffffu, p, o);
        if (lane == 0) sc[s] = p;
    }
    __syncthreads();

    if (w == 0) {
        float a  = sc[lane];
        float b2 = (lane < 16) ? sc[32 + lane] : -1e30f;
        float m = fmaxf(a, b2);
#pragma unroll
        for (int o = 16; o > 0; o >>= 1) m = fmaxf(m, __shfl_xor_sync(0xffffffffu, m, o));
        float ea = expf(a - m);
        float eb = (lane < 16) ? expf(b2 - m) : 0.f;
        float ss = ea + eb;
#pragma unroll
        for (int o = 16; o > 0; o >>= 1) ss += __shfl_xor_sync(0xffffffffu, ss, o);
        float inv = 1.f / ss;
        sc[lane] = ea * inv;
        if (lane < 16) sc[32 + lane] = eb * inv;
    }
    __syncthreads();

    float a0 = 0.f, a1 = 0.f;
    for (int s = 0; s < S; s++) {
        float at = sc[s];
        const float* e = enc + (size_t)(s * B + b) * H;
        a0 = fmaf(at, e[tid], a0);
        a1 = fmaf(at, e[tid + 256], a1);
    }
    float* co = Ctx + ((size_t)t * B + b) * H;
    co[tid]       = a0;
    co[tid + 256] = a1;
}

// ---------------- small utilities ----------------
__global__ void combine_kernel(float* __restrict__ out, const float* __restrict__ a,
                               const float* __restrict__ b, int n)
{
    int i = blockIdx.x * blockDim.x + threadIdx.x;
    if (i < n) out[i] = a[i] + b[i];
}

__global__ void init_kernel(int* __restrict__ out, const int* __restrict__ target,
                            unsigned* __restrict__ bars)
{
    int i = blockIdx.x * blockDim.x + threadIdx.x;
    if (i < 2) bars[i] = 0u;
    if (i < T * B) out[i] = (i < B) ? 1 /*SOS*/ : target[i - B];
}

// ---------------- launch ------------------------------------------------------
extern "C" void kernel_launch(void* const* d_in, const int* in_sizes, int n_in,
                              void* d_out, int out_size)
{
    const int*   input_batches  = (const int*)d_in[0];
    const int*   target_batches = (const int*)d_in[1];
    const float* enc_emb   = (const float*)d_in[2];
    const float* enc_Wih_f = (const float*)d_in[3];
    const float* enc_Whh_f = (const float*)d_in[4];
    const float* enc_bih_f = (const float*)d_in[5];
    const float* enc_bhh_f = (const float*)d_in[6];
    const float* enc_Wih_b = (const float*)d_in[7];
    const float* enc_Whh_b = (const float*)d_in[8];
    const float* enc_bih_b = (const float*)d_in[9];
    const float* enc_bhh_b = (const float*)d_in[10];
    const float* dec_emb   = (const float*)d_in[11];
    const float* dec_Wih   = (const float*)d_in[12];
    const float* dec_Whh   = (const float*)d_in[13];
    const float* dec_bih   = (const float*)d_in[14];
    const float* dec_bhh   = (const float*)d_in[15];
    const float* Wc        = (const float*)d_in[16];
    const float* bc        = (const float*)d_in[17];
    const float* Wo        = (const float*)d_in[18];
    const float* bo        = (const float*)d_in[19];
    float* out = (float*)d_out;

    float *Gall, *outs_f, *outs_b, *enc_out, *Hdec, *Ctx;
    int* dectok; unsigned* bars;
    __nv_bfloat16 *A3e, *A3d, *B3f, *B3b_, *B3d_, *B3c, *A3c;
    __half *A2v, *B2o;
    cudaGetSymbolAddress((void**)&Gall,   g_Gall);
    cudaGetSymbolAddress((void**)&outs_f, g_outs_f);
    cudaGetSymbolAddress((void**)&outs_b, g_outs_b);
    cudaGetSymbolAddress((void**)&enc_out,g_enc_out);
    cudaGetSymbolAddress((void**)&Hdec,   g_Hdec);
    cudaGetSymbolAddress((void**)&Ctx,    g_Ctx);
    cudaGetSymbolAddress((void**)&dectok, g_dectok);
    cudaGetSymbolAddress((void**)&bars,   g_bars);
    cudaGetSymbolAddress((void**)&A3e,    g_A3e);
    cudaGetSymbolAddress((void**)&A3d,    g_A3d);
    cudaGetSymbolAddress((void**)&B3f,    g_B3f);
    cudaGetSymbolAddress((void**)&B3b_,   g_B3b);
    cudaGetSymbolAddress((void**)&B3d_,   g_B3d);
    cudaGetSymbolAddress((void**)&B3c,    g_B3c);
    cudaGetSymbolAddress((void**)&A3c,    g_A3c);
    cudaGetSymbolAddress((void**)&A2v,    g_A2v);
    cudaGetSymbolAddress((void**)&B2o,    g_B2o);

    float* Gx_f = Gall;
    float* Gx_b = Gall + (size_t)S * B * H3;
    float* Gd   = Gall + (size_t)2 * S * B * H3;

    const int WSMEM8 = 24 * 516 * 4;
    const int WSMEM4 = 12 * 516 * 4;
    cudaFuncSetAttribute(gru_scan_kernel<8>,
                         cudaFuncAttributeMaxDynamicSharedMemorySize, WSMEM8);
    cudaFuncSetAttribute(gru_scan_kernel<4>,
                         cudaFuncAttributeMaxDynamicSharedMemorySize, WSMEM4);
    cudaFuncSetAttribute((const void*)gemm_mma_kernel<128,false>,
                         cudaFuncAttributeMaxDynamicSharedMemorySize, 98304);
    cudaFuncSetAttribute((const void*)gemm_mma_kernel<128,true>,
                         cudaFuncAttributeMaxDynamicSharedMemorySize, 98304);

    init_kernel<<<(T * B + 255) / 256, 256>>>(dectok, target_batches, bars);

    // splits
    split3_kernel<<<(S*B*128 + 255)/256, 256>>>(enc_emb, nullptr, input_batches, A3e, S*B, 512, 0);
    split3_kernel<<<(T*B*128 + 255)/256, 256>>>(dec_emb, nullptr, dectok,        A3d, T*B, 512, 0);
    split3_kernel<<<(H3*128 + 255)/256, 256>>>(enc_Wih_f, nullptr, nullptr, B3f,  H3, 512, 1);
    split3_kernel<<<(H3*128 + 255)/256, 256>>>(enc_Wih_b, nullptr, nullptr, B3b_, H3, 512, 1);
    split3_kernel<<<(H3*128 + 255)/256, 256>>>(dec_Wih,   nullptr, nullptr, B3d_, H3, 512, 1);
    split3_kernel<<<(VOUT*128 + 255)/256, 256>>>(Wo, nullptr, nullptr,
                                                 (__nv_bfloat16*)B2o, VOUT, 512, 2);
    split3_kernel<<<(H*256 + 255)/256, 256>>>(Wc, nullptr, nullptr, B3c, H, 1024, 1);

    // all three input-gate GEMMs in one launch (z selects)
    gemm_mma_kernel<128,false><<<dim3(S*B/128, H3/128, 3), 256, 98304>>>(
        A3e, A3d, B3f, B3b_, B3d_, enc_bih_f, enc_bih_b, dec_bih,
        Gx_f, Gx_b, Gd, nullptr, H3, H3, H3, 0);

    // encoder scans (fwd + bwd fused), 8 cols/block
    ScanProb pf { Gx_f, nullptr, enc_Whh_f, enc_bhh_f, outs_f, 0 };
    ScanProb pk { Gx_b, nullptr, enc_Whh_b, enc_bhh_b, outs_b, 1 };
    gru_scan_kernel<8><<<128, 256, WSMEM8>>>(pf, pk, 64, S, 128u, bars + 0);

    combine_kernel<<<(S * B * H + 255) / 256, 256>>>(enc_out, outs_f, outs_b, S * B * H);

    // decoder GRU chain, 4 cols/block + 2-way K split (128 CTAs)
    ScanProb pd { Gd, outs_f + (size_t)(S - 1) * B * H, dec_Whh, dec_bhh, Hdec, 0 };
    gru_scan_kernel<4><<<128, 256, WSMEM4>>>(pd, pd, 128, T, 128u, bars + 1);

    // batched attention
    attn_kernel<<<T * B, 256>>>(Hdec, enc_out, Ctx);

    // split [Hdec | Ctx] for the Wc GEMM
    split3_kernel<<<(T*B*256 + 255)/256, 256>>>(Hdec, Ctx, nullptr, A3c, T*B, 1024, 0);

    // c = tanh([h2,ctx] @ Wc^T + bc), fused fp16 [hi,lo] split-store into A2v
    gemm_mma_kernel<128,false><<<dim3(T*B/128, H/128, 1), 256, 98304>>>(
        A3c, A3c, B3c, B3c, B3c, bc, bc, bc,
        nullptr, nullptr, nullptr, A2v, 3*1024, H, H, 2);

    // vocab projection fp16 2-term: out = A2v @ B2o^T + bo
    gemm_mma_kernel<128,true><<<dim3(T*B/128, VOUT/128, 1), 256, 98304>>>(
        (const __nv_bfloat16*)A2v, (const __nv_bfloat16*)A2v,
        (const __nv_bfloat16*)B2o, (const __nv_bfloat16*)B2o, (const __nv_bfloat16*)B2o,
        bo, bo, bo, out, out, out, nullptr, 1024, VOUT, VOUT, 0);
}

// round 12
// speedup vs baseline: 1.9196x; 1.0346x over previous
#include <cuda_runtime.h>
#include <cuda_bf16.h>
#include <cuda_fp16.h>
#include <math.h>
#include <stdint.h>

#define H    512
#define H3   1536
#define S    48
#define T    48
#define B    32
#define VOUT 32000

typedef unsigned long long ull;

// ---------------- packed f32x2 helpers (scan kernel) ----------------
__device__ __forceinline__ ull pk2(float x, float y) {
    ull r; asm("mov.b64 %0, {%1,%2};" : "=l"(r) : "f"(x), "f"(y)); return r;
}
__device__ __forceinline__ void fma2(ull& d, ull a, ull b) {
    asm("fma.rn.f32x2 %0, %1, %2, %0;" : "+l"(d) : "l"(a), "l"(b));
}
__device__ __forceinline__ float2 upk(ull v) {
    float lo, hi; asm("mov.b64 {%0,%1}, %2;" : "=f"(lo), "=f"(hi) : "l"(v));
    float2 f; f.x = lo; f.y = hi; return f;
}

// ---------------- mma.sync helpers ----------------
__device__ __forceinline__ uint32_t smem_u32(const void* p) {
    uint32_t a;
    asm("{ .reg .u64 t; cvta.to.shared.u64 t, %1; cvt.u32.u64 %0, t; }" : "=r"(a) : "l"(p));
    return a;
}
#define LDSM4(r0, r1, r2, r3, addr) \
    asm volatile("ldmatrix.sync.aligned.m8n8.x4.shared.b16 {%0,%1,%2,%3}, [%4];" \
        : "=r"(r0), "=r"(r1), "=r"(r2), "=r"(r3) : "r"(addr))
__device__ __forceinline__ void mma_bf16_(float* d, uint32_t a0, uint32_t a1,
                                          uint32_t a2, uint32_t a3,
                                          uint32_t b0, uint32_t b1) {
    asm volatile("mma.sync.aligned.m16n8k16.row.col.f32.bf16.bf16.f32 "
        "{%0,%1,%2,%3}, {%4,%5,%6,%7}, {%8,%9}, {%0,%1,%2,%3};"
        : "+f"(d[0]), "+f"(d[1]), "+f"(d[2]), "+f"(d[3])
        : "r"(a0), "r"(a1), "r"(a2), "r"(a3), "r"(b0), "r"(b1));
}
__device__ __forceinline__ void mma_f16_(float* d, uint32_t a0, uint32_t a1,
                                         uint32_t a2, uint32_t a3,
                                         uint32_t b0, uint32_t b1) {
    asm volatile("mma.sync.aligned.m16n8k16.row.col.f32.f16.f16.f32 "
        "{%0,%1,%2,%3}, {%4,%5,%6,%7}, {%8,%9}, {%0,%1,%2,%3};"
        : "+f"(d[0]), "+f"(d[1]), "+f"(d[2]), "+f"(d[3])
        : "r"(a0), "r"(a1), "r"(a2), "r"(a3), "r"(b0), "r"(b1));
}
__device__ __forceinline__ void cp16(uint32_t dst, const void* src) {
    asm volatile("cp.async.cg.shared.global [%0], [%1], 16;" :: "r"(dst), "l"(src));
}
#define CP_COMMIT() asm volatile("cp.async.commit_group;" ::: "memory")
#define CP_WAIT(n)  asm volatile("cp.async.wait_group %0;" :: "n"(n) : "memory")

// ---------------- device scratch ----------------
__device__ float g_Gall[3*S*B*H3];      // Gx_f | Gx_b | Gd
__device__ float g_outs_f[S*B*H];
__device__ float g_outs_b[S*B*H];
__device__ float g_enc_out[S*B*H];
__device__ float g_Hdec[T*B*H];
__device__ float g_Ctx [T*B*H];
__device__ int   g_dectok[T*B];
__device__ unsigned g_bars[4];
__device__ __half g_B2o[(size_t)VOUT*1024];       // Wo fp16 [hi, hi]
__device__ __half g_A2v[(size_t)T*B*1024];        // c  fp16 [hi, lo]
__device__ __nv_bfloat16 g_A3e[S*B*H3];           // split enc emb (gathered)
__device__ __nv_bfloat16 g_A3d[T*B*H3];           // split dec emb (gathered)
__device__ __nv_bfloat16 g_B3f[H3*H3];            // split enc_Wih_f
__device__ __nv_bfloat16 g_B3b[H3*H3];            // split enc_Wih_b
__device__ __nv_bfloat16 g_B3d[H3*H3];            // split dec_Wih
__device__ __nv_bfloat16 g_B3c[H*3*1024];         // split Wc (K=1024)
__device__ __nv_bfloat16 g_A3c[T*B*3*1024];       // split [Hdec|Ctx]

// ---------------- grid barrier (pure L2 spin — NO nanosleep) ----------------
__device__ __forceinline__ void grid_bar(unsigned* bar, unsigned target) {
    __threadfence();
    __syncthreads();
    if (threadIdx.x == 0) {
        atomicAdd(bar, 1u);
        while (*(volatile unsigned*)bar < target) { }
        __threadfence();
    }
    __syncthreads();
}

// ---------------- fp32 -> 16-bit splits --------------------------------------
// mode 0 (A,bf16): [hi, lo, hi]  mode 1 (B,bf16): [hi, hi, lo]  (stride 3K)
// mode 2 (B,fp16): [hi, hi]                                     (stride 2K)
__global__ __launch_bounds__(256)
void split3_kernel(const float* __restrict__ src, const float* __restrict__ src2,
                   const int* __restrict__ gidx, __nv_bfloat16* __restrict__ dst,
                   int nrows, int K, int mode)
{
    int perrow = K >> 2;
    int idx = blockIdx.x * 256 + threadIdx.x;
    if (idx >= nrows * perrow) return;
    int row = idx / perrow, cc = (idx - row * perrow) * 4;
    const float* s;
    if (src2 && cc >= 512)      s = src2 + (size_t)row * 512 + (cc - 512);
    else if (src2)              s = src  + (size_t)row * 512 + cc;
    else if (gidx)              s = src  + (size_t)gidx[row] * K + cc;
    else                        s = src  + (size_t)row * K + cc;
    float4 v = *(const float4*)s;
    float f[4] = {v.x, v.y, v.z, v.w};

    if (mode == 2) {
        __half hh[4];
#pragma unroll
        for (int i = 0; i < 4; i++) hh[i] = __float2half_rn(f[i]);
        __half2 p01 = __halves2half2(hh[0], hh[1]);
        __half2 p23 = __halves2half2(hh[2], hh[3]);
        __half* base = ((__half*)dst) + (size_t)row * (2 * K);
        *(__half2*)(base + cc) = p01;      *(__half2*)(base + cc + 2) = p23;
        *(__half2*)(base + K + cc) = p01;  *(__half2*)(base + K + cc + 2) = p23;
        return;
    }

    __nv_bfloat16 h[4], l[4];
#pragma unroll
    for (int i = 0; i < 4; i++) {
        h[i] = __float2bfloat16(f[i]);
        l[i] = __float2bfloat16(f[i] - __bfloat162float(h[i]));
    }
    __nv_bfloat162 h01, h23, l01, l23;
    h01.x = h[0]; h01.y = h[1]; h23.x = h[2]; h23.y = h[3];
    l01.x = l[0]; l01.y = l[1]; l23.x = l[2]; l23.y = l[3];
    __nv_bfloat16* base = dst + (size_t)row * (3 * K);
    __nv_bfloat162* d0 = (__nv_bfloat162*)(base + cc);
    __nv_bfloat162* d1 = (__nv_bfloat162*)(base + K + cc);
    __nv_bfloat162* d2 = (__nv_bfloat162*)(base + 2 * K + cc);
    d0[0] = h01; d0[1] = h23;
    if (mode == 0) { d1[0] = l01; d1[1] = l23; d2[0] = h01; d2[1] = h23; }
    else           { d1[0] = h01; d1[1] = h23; d2[0] = l01; d2[1] = l23; }
}

// ---------------- mma.sync 16-bit NT GEMM (3-stage cp.async pipeline) -------
template<int TM, bool FP16>
__global__ __launch_bounds__(256, 2)
void gemm_mma_kernel(const __nv_bfloat16* __restrict__ A3a,
                     const __nv_bfloat16* __restrict__ A3b,
                     const __nv_bfloat16* __restrict__ B3_0,
                     const __nv_bfloat16* __restrict__ B3_1,
                     const __nv_bfloat16* __restrict__ B3_2,
                     const float* __restrict__ bias0,
                     const float* __restrict__ bias1,
                     const float* __restrict__ bias2,
                     float* __restrict__ out0, float* __restrict__ out1,
                     float* __restrict__ out2,
                     __half* __restrict__ outsplit,
                     int K3, int N, int ldc, int act)
{
    constexpr int MI = TM / 64;
    constexpr int ABYTES = TM * 128;
    constexpr int BBYTES = 128 * 128;
    constexpr int STAGE = ABYTES + BBYTES;
    extern __shared__ __align__(1024) char smem[];

    const int z = blockIdx.z;
    const __nv_bfloat16* A3 = (z == 2) ? A3b : A3a;
    const __nv_bfloat16* B3 = (z == 0) ? B3_0 : ((z == 1) ? B3_1 : B3_2);
    const float* bias = (z == 0) ? bias0 : ((z == 1) ? bias1 : bias2);
    float* out = (z == 0) ? out0 : ((z == 1) ? out1 : out2);

    const int tid  = threadIdx.x;
    const int wid  = tid >> 5;
    const int lane = tid & 31;
    const int m0 = blockIdx.x * TM;
    const int n0 = blockIdx.y * 128;
    const int warp_m = wid & 3;
    const int warp_n = wid >> 2;
    const uint32_t sb = smem_u32(smem);

    const size_t K3b = (size_t)K3 * 2;
    const char* Ag = (const char*)A3 + (size_t)m0 * K3b;
    const char* Bg = (const char*)B3 + (size_t)n0 * K3b;
    const int nkt = K3 / 64;

    float d[MI][8][4];
#pragma unroll
    for (int i = 0; i < MI; i++)
#pragma unroll
        for (int j = 0; j < 8; j++)
#pragma unroll
            for (int q = 0; q < 4; q++) d[i][j][q] = 0.f;

    const int a_rowl = lane & 15;
    const int a_cb   = lane >> 4;
    const int b_rowb = warp_n * 64 + (lane & 7) + ((lane & 16) >> 1);
    const int b_cb   = (lane >> 3) & 1;

    auto issue = [&](int kt, int slot) {
        uint32_t Ab = sb + slot * STAGE;
        uint32_t Bb = Ab + ABYTES;
#pragma unroll
        for (int j = 0; j < ABYTES / 16 / 256; j++) {
            int id = tid + j * 256;
            int r = id >> 3, c = id & 7;
            cp16(Ab + r * 128 + ((c ^ (r & 7)) << 4), Ag + (size_t)r * K3b + kt * 128 + c * 16);
        }
#pragma unroll
        for (int j = 0; j < BBYTES / 16 / 256; j++) {
            int id = tid + j * 256;
            int r = id >> 3, c = id & 7;
            cp16(Bb + r * 128 + ((c ^ (r & 7)) << 4), Bg + (size_t)r * K3b + kt * 128 + c * 16);
        }
        CP_COMMIT();
    };

    issue(0, 0);
    issue(1, 1);

    int slot = 0, slot2 = 2;
    for (int kt = 0; kt < nkt; kt++) {
        if (kt + 1 < nkt) { CP_WAIT(1); } else { CP_WAIT(0); }
        __syncthreads();
        if (kt + 2 < nkt) {
            issue(kt + 2, slot2);
            if (++slot2 == 3) slot2 = 0;
        }
        uint32_t Ab = sb + slot * STAGE;
        uint32_t Bb = Ab + ABYTES;
        if (++slot == 3) slot = 0;
#pragma unroll
        for (int kk = 0; kk < 4; kk++) {
            uint32_t af[MI][4];
            int ca = kk * 2 + a_cb;
#pragma unroll
            for (int mi = 0; mi < MI; mi++) {
                int ar = warp_m * (MI * 16) + mi * 16 + a_rowl;
                LDSM4(af[mi][0], af[mi][1], af[mi][2], af[mi][3],
                      Ab + ar * 128 + ((ca ^ (ar & 7)) << 4));
            }
            int cb = kk * 2 + b_cb;
#pragma unroll
            for (int nt = 0; nt < 4; nt++) {
                int br = b_rowb + nt * 16;
                uint32_t b0, b1, b2, b3;
                LDSM4(b0, b1, b2, b3, Bb + br * 128 + ((cb ^ (br & 7)) << 4));
#pragma unroll
                for (int mi = 0; mi < MI; mi++) {
                    if (FP16) {
                        mma_f16_(d[mi][2*nt],   af[mi][0], af[mi][1], af[mi][2], af[mi][3], b0, b1);
                        mma_f16_(d[mi][2*nt+1], af[mi][0], af[mi][1], af[mi][2], af[mi][3], b2, b3);
                    } else {
                        mma_bf16_(d[mi][2*nt],   af[mi][0], af[mi][1], af[mi][2], af[mi][3], b0, b1);
                        mma_bf16_(d[mi][2*nt+1], af[mi][0], af[mi][1], af[mi][2], af[mi][3], b2, b3);
                    }
                }
            }
        }
        __syncthreads();
    }

    // epilogue
#pragma unroll
    for (int mi = 0; mi < MI; mi++) {
        int gm = m0 + warp_m * (MI * 16) + mi * 16 + (lane >> 2);
#pragma unroll
        for (int ni = 0; ni < 8; ni++) {
            int gn = n0 + warp_n * 64 + ni * 8 + (lane & 3) * 2;
            float2 bv = *(const float2*)(bias + gn);
            float v0 = d[mi][ni][0] + bv.x, v1 = d[mi][ni][1] + bv.y;
            float v2 = d[mi][ni][2] + bv.x, v3 = d[mi][ni][3] + bv.y;
            if (act == 2) {
                v0 = tanhf(v0); v1 = tanhf(v1); v2 = tanhf(v2); v3 = tanhf(v3);
                __half h0 = __float2half_rn(v0), h1 = __float2half_rn(v1);
                __half h2 = __float2half_rn(v2), h3 = __float2half_rn(v3);
                __half2 ph0 = __halves2half2(h0, h1);
                __half2 pl0 = __halves2half2(__float2half_rn(v0 - __half2float(h0)),
                                             __float2half_rn(v1 - __half2float(h1)));
                __half2 ph1 = __halves2half2(h2, h3);
                __half2 pl1 = __halves2half2(__float2half_rn(v2 - __half2float(h2)),
                                             __float2half_rn(v3 - __half2float(h3)));
                __half* r0 = outsplit + (size_t)gm * 1024;
                __half* r1 = outsplit + (size_t)(gm + 8) * 1024;
                *(__half2*)(r0 + gn) = ph0;
                *(__half2*)(r0 + 512 + gn) = pl0;
                *(__half2*)(r1 + gn) = ph1;
                *(__half2*)(r1 + 512 + gn) = pl1;
            } else {
                float2 o0, o1;
                o0.x = v0; o0.y = v1; o1.x = v2; o1.y = v3;
                *(float2*)(out + (size_t)gm * ldc + gn) = o0;
                *(float2*)(out + (size_t)(gm + 8) * ldc + gn) = o1;
            }
        }
    }
}

// ---------------- persistent GRU scan (COLS h-cols per block) ---------------
struct ScanProb {
    const float* gx;
    const float* seed;
    const float* whh;
    const float* bhh;
    float*       outs;
    int          dir;
};

template<int COLS>   // 8: 1 K-seg per thread; 4: 2-way K split + shfl combine
__global__ __launch_bounds__(256)
void gru_scan_kernel(ScanProb pa, ScanProb pb, int bpp, int nsteps,
                     unsigned* bar)
{
    constexpr int KSEG = 64 * COLS;     // 512 or 256
    constexpr int NW = 3 * COLS;
    extern __shared__ float w_s[];
    const int prob = (blockIdx.x < bpp) ? 0 : 1;
    ScanProb p = prob ? pb : pa;
    unsigned* mybar = bar + prob;       // independent barrier per problem
    const int blk = blockIdx.x % bpp;
    const int h0  = blk * COLS;
    const int tid = threadIdx.x;
    const int b    = tid >> 3;
    const int slot = tid & 7;
    const int col  = slot % COLS;
    const int kh   = slot / COLS;       // 0 (COLS=8) or 0/1 (COLS=4)
    const int koff = kh * KSEG;

    for (int id = tid; id < NW * 128; id += 256) {
        int row = id >> 7, c4 = (id & 127) * 4;
        int g = row / COLS, cc = row % COLS;
        *(float4*)&w_s[row * 516 + c4] =
            *(const float4*)(p.whh + (size_t)(g * H + h0 + cc) * H + c4);
    }
    __syncthreads();

    const ull* wr2 = (const ull*)&w_s[col * 516 + koff];
    const ull* wz2 = (const ull*)&w_s[(COLS + col) * 516 + koff];
    const ull* wn2 = (const ull*)&w_s[(2 * COLS + col) * 516 + koff];

    const int h = h0 + col;
    const float br = p.bhh[h], bz = p.bhh[H + h], bn = p.bhh[2 * H + h];

    for (int i = 0; i < nsteps; i++) {
        const int t = p.dir ? (nsteps - 1 - i) : i;
        const float* hprev = (i == 0) ? p.seed
                           : p.outs + (size_t)(p.dir ? t + 1 : t - 1) * B * H;
        ull ar2 = 0, az2 = 0, an2 = 0;
        if (hprev) {
            const float4* hp4 = (const float4*)(hprev + b * H + koff);
#pragma unroll 8
            for (int c = 0; c < KSEG / 4; c++) {
                float4 hv = __ldg(&hp4[c]);
                ull h01 = pk2(hv.x, hv.y), h23 = pk2(hv.z, hv.w);
                fma2(ar2, h01, wr2[2*c]); fma2(ar2, h23, wr2[2*c+1]);
                fma2(az2, h01, wz2[2*c]); fma2(az2, h23, wz2[2*c+1]);
                fma2(an2, h01, wn2[2*c]); fma2(an2, h23, wn2[2*c+1]);
            }
        }
        float2 fr = upk(ar2), fz = upk(az2), fn = upk(an2);
        float ar = fr.x + fr.y, az = fz.x + fz.y, an = fn.x + fn.y;
        if (COLS == 4) {
            ar += __shfl_xor_sync(0xffffffffu, ar, 4);
            az += __shfl_xor_sync(0xffffffffu, az, 4);
            an += __shfl_xor_sync(0xffffffffu, an, 4);
        }
        if (kh == 0) {
            float hp_val = hprev ? __ldg(hprev + b * H + h) : 0.f;
            const float* gx = p.gx + ((size_t)t * B + b) * H3;
            float r = 1.f / (1.f + expf(-(gx[h]       + ar + br)));
            float z = 1.f / (1.f + expf(-(gx[H + h]   + az + bz)));
            float n = tanhf(gx[2 * H + h] + r * (an + bn));
            p.outs[((size_t)t * B + b) * H + h] = (1.f - z) * n + z * hp_val;
        }
        if (i < nsteps - 1) grid_bar(mybar, (unsigned)bpp * (unsigned)(i + 1));
    }
}

// ---------------- batched attention ----------------
__global__ __launch_bounds__(256)
void attn_kernel(const float* __restrict__ Hdec, const float* __restrict__ enc,
                 float* __restrict__ Ctx)
{
    const int t = blockIdx.x / B;
    const int b = blockIdx.x % B;
    const float* h2 = Hdec + ((size_t)t * B + b) * H;
    const int tid = threadIdx.x;
    const int lane = tid & 31, w = tid >> 5;
    __shared__ float h2_s[H];
    __shared__ float sc[S];

    h2_s[tid]       = h2[tid];
    h2_s[tid + 256] = h2[tid + 256];
    __syncthreads();

    for (int s = w; s < S; s += 8) {
        const float4* e  = (const float4*)(enc + (size_t)(s * B + b) * H);
        const float4* h4 = (const float4*)h2_s;
        float p = 0.f;
#pragma unroll
        for (int j = 0; j < 4; j++) {
            float4 ev = e[lane + j * 32];
            float4 hv = h4[lane + j * 32];
            p = fmaf(ev.x, hv.x, p); p = fmaf(ev.y, hv.y, p);
            p = fmaf(ev.z, hv.z, p); p = fmaf(ev.w, hv.w, p);
        }
#pragma unroll
        for (int o = 16; o > 0; o >>= 1) p += __shfl_xor_sync(0xffffffffu, p, o);
        if (lane == 0) sc[s] = p;
    }
    __syncthreads();

    if (w == 0) {
        float a  = sc[lane];
        float b2 = (lane < 16) ? sc[32 + lane] : -1e30f;
        float m = fmaxf(a, b2);
#pragma unroll
        for (int o = 16; o > 0; o >>= 1) m = fmaxf(m, __shfl_xor_sync(0xffffffffu, m, o));
        float ea = expf(a - m);
        float eb = (lane < 16) ? expf(b2 - m) : 0.f;
        float ss = ea + eb;
#pragma unroll
        for (int o = 16; o > 0; o >>= 1) ss += __shfl_xor_sync(0xffffffffu, ss, o);
        float inv = 1.f / ss;
        sc[lane] = ea * inv;
        if (lane < 16) sc[32 + lane] = eb * inv;
    }
    __syncthreads();

    float a0 = 0.f, a1 = 0.f;
    for (int s = 0; s < S; s++) {
        float at = sc[s];
        const float* e = enc + (size_t)(s * B + b) * H;
        a0 = fmaf(at, e[tid], a0);
        a1 = fmaf(at, e[tid + 256], a1);
    }
    float* co = Ctx + ((size_t)t * B + b) * H;
    co[tid]       = a0;
    co[tid + 256] = a1;
}

// ---------------- small utilities ----------------
__global__ void combine_kernel(float* __restrict__ out, const float* __restrict__ a,
                               const float* __restrict__ b, int n)
{
    int i = blockIdx.x * blockDim.x + threadIdx.x;
    if (i < n) out[i] = a[i] + b[i];
}

__global__ void init_kernel(int* __restrict__ out, const int* __restrict__ target,
                            unsigned* __restrict__ bars)
{
    int i = blockIdx.x * blockDim.x + threadIdx.x;
    if (i < 4) bars[i] = 0u;
    if (i < T * B) out[i] = (i < B) ? 1 /*SOS*/ : target[i - B];
}

// ---------------- launch ------------------------------------------------------
extern "C" void kernel_launch(void* const* d_in, const int* in_sizes, int n_in,
                              void* d_out, int out_size)
{
    const int*   input_batches  = (const int*)d_in[0];
    const int*   target_batches = (const int*)d_in[1];
    const float* enc_emb   = (const float*)d_in[2];
    const float* enc_Wih_f = (const float*)d_in[3];
    const float* enc_Whh_f = (const float*)d_in[4];
    const float* enc_bih_f = (const float*)d_in[5];
    const float* enc_bhh_f = (const float*)d_in[6];
    const float* enc_Wih_b = (const float*)d_in[7];
    const float* enc_Whh_b = (const float*)d_in[8];
    const float* enc_bih_b = (const float*)d_in[9];
    const float* enc_bhh_b = (const float*)d_in[10];
    const float* dec_emb   = (const float*)d_in[11];
    const float* dec_Wih   = (const float*)d_in[12];
    const float* dec_Whh   = (const float*)d_in[13];
    const float* dec_bih   = (const float*)d_in[14];
    const float* dec_bhh   = (const float*)d_in[15];
    const float* Wc        = (const float*)d_in[16];
    const float* bc        = (const float*)d_in[17];
    const float* Wo        = (const float*)d_in[18];
    const float* bo        = (const float*)d_in[19];
    float* out = (float*)d_out;

    float *Gall, *outs_f, *outs_b, *enc_out, *Hdec, *Ctx;
    int* dectok; unsigned* bars;
    __nv_bfloat16 *A3e, *A3d, *B3f, *B3b_, *B3d_, *B3c, *A3c;
    __half *A2v, *B2o;
    cudaGetSymbolAddress((void**)&Gall,   g_Gall);
    cudaGetSymbolAddress((void**)&outs_f, g_outs_f);
    cudaGetSymbolAddress((void**)&outs_b, g_outs_b);
    cudaGetSymbolAddress((void**)&enc_out,g_enc_out);
    cudaGetSymbolAddress((void**)&Hdec,   g_Hdec);
    cudaGetSymbolAddress((void**)&Ctx,    g_Ctx);
    cudaGetSymbolAddress((void**)&dectok, g_dectok);
    cudaGetSymbolAddress((void**)&bars,   g_bars);
    cudaGetSymbolAddress((void**)&A3e,    g_A3e);
    cudaGetSymbolAddress((void**)&A3d,    g_A3d);
    cudaGetSymbolAddress((void**)&B3f,    g_B3f);
    cudaGetSymbolAddress((void**)&B3b_,   g_B3b);
    cudaGetSymbolAddress((void**)&B3d_,   g_B3d);
    cudaGetSymbolAddress((void**)&B3c,    g_B3c);
    cudaGetSymbolAddress((void**)&A3c,    g_A3c);
    cudaGetSymbolAddress((void**)&A2v,    g_A2v);
    cudaGetSymbolAddress((void**)&B2o,    g_B2o);

    float* Gx_f = Gall;
    float* Gx_b = Gall + (size_t)S * B * H3;
    float* Gd   = Gall + (size_t)2 * S * B * H3;

    const int WSMEM8 = 24 * 516 * 4;
    const int WSMEM4 = 12 * 516 * 4;
    cudaFuncSetAttribute(gru_scan_kernel<8>,
                         cudaFuncAttributeMaxDynamicSharedMemorySize, WSMEM8);
    cudaFuncSetAttribute(gru_scan_kernel<4>,
                         cudaFuncAttributeMaxDynamicSharedMemorySize, WSMEM4);
    cudaFuncSetAttribute((const void*)gemm_mma_kernel<128,false>,
                         cudaFuncAttributeMaxDynamicSharedMemorySize, 98304);
    cudaFuncSetAttribute((const void*)gemm_mma_kernel<128,true>,
                         cudaFuncAttributeMaxDynamicSharedMemorySize, 98304);

    init_kernel<<<(T * B + 255) / 256, 256>>>(dectok, target_batches, bars);

    // splits
    split3_kernel<<<(S*B*128 + 255)/256, 256>>>(enc_emb, nullptr, input_batches, A3e, S*B, 512, 0);
    split3_kernel<<<(T*B*128 + 255)/256, 256>>>(dec_emb, nullptr, dectok,        A3d, T*B, 512, 0);
    split3_kernel<<<(H3*128 + 255)/256, 256>>>(enc_Wih_f, nullptr, nullptr, B3f,  H3, 512, 1);
    split3_kernel<<<(H3*128 + 255)/256, 256>>>(enc_Wih_b, nullptr, nullptr, B3b_, H3, 512, 1);
    split3_kernel<<<(H3*128 + 255)/256, 256>>>(dec_Wih,   nullptr, nullptr, B3d_, H3, 512, 1);
    split3_kernel<<<(VOUT*128 + 255)/256, 256>>>(Wo, nullptr, nullptr,
                                                 (__nv_bfloat16*)B2o, VOUT, 512, 2);
    split3_kernel<<<(H*256 + 255)/256, 256>>>(Wc, nullptr, nullptr, B3c, H, 1024, 1);

    // all three input-gate GEMMs in one launch (z selects)
    gemm_mma_kernel<128,false><<<dim3(S*B/128, H3/128, 3), 256, 98304>>>(
        A3e, A3d, B3f, B3b_, B3d_, enc_bih_f, enc_bih_b, dec_bih,
        Gx_f, Gx_b, Gd, nullptr, H3, H3, H3, 0);

    // encoder scans (fwd + bwd fused), 8 cols/block, per-problem barriers
    ScanProb pf { Gx_f, nullptr, enc_Whh_f, enc_bhh_f, outs_f, 0 };
    ScanProb pk { Gx_b, nullptr, enc_Whh_b, enc_bhh_b, outs_b, 1 };
    gru_scan_kernel<8><<<128, 256, WSMEM8>>>(pf, pk, 64, S, bars + 0);

    combine_kernel<<<(S * B * H + 255) / 256, 256>>>(enc_out, outs_f, outs_b, S * B * H);

    // decoder GRU chain, 4 cols/block + 2-way K split (128 CTAs)
    ScanProb pd { Gd, outs_f + (size_t)(S - 1) * B * H, dec_Whh, dec_bhh, Hdec, 0 };
    gru_scan_kernel<4><<<128, 256, WSMEM4>>>(pd, pd, 128, T, bars + 2);

    // batched attention
    attn_kernel<<<T * B, 256>>>(Hdec, enc_out, Ctx);

    // split [Hdec | Ctx] for the Wc GEMM
    split3_kernel<<<(T*B*256 + 255)/256, 256>>>(Hdec, Ctx, nullptr, A3c, T*B, 1024, 0);

    // c = tanh([h2,ctx] @ Wc^T + bc), fused fp16 [hi,lo] split-store into A2v
    gemm_mma_kernel<128,false><<<dim3(T*B/128, H/128, 1), 256, 98304>>>(
        A3c, A3c, B3c, B3c, B3c, bc, bc, bc,
        nullptr, nullptr, nullptr, A2v, 3*1024, H, H, 2);

    // vocab projection fp16 2-term: out = A2v @ B2o^T + bo
    gemm_mma_kernel<128,true><<<dim3(T*B/128, VOUT/128, 1), 256, 98304>>>(
        (const __nv_bfloat16*)A2v, (const __nv_bfloat16*)A2v,
        (const __nv_bfloat16*)B2o, (const __nv_bfloat16*)B2o, (const __nv_bfloat16*)B2o,
        bo, bo, bo, out, out, out, nullptr, 1024, VOUT, VOUT, 0);
}

// round 13
// speedup vs baseline: 1.9575x; 1.0197x over previous
#include <cuda_runtime.h>
#include <cuda_bf16.h>
#include <cuda_fp16.h>
#include <math.h>
#include <stdint.h>

#define H    512
#define H3   1536
#define S    48
#define T    48
#define B    32
#define VOUT 32000

typedef unsigned long long ull;

// ---------------- packed f32x2 helpers (scan kernel) ----------------
__device__ __forceinline__ ull pk2(float x, float y) {
    ull r; asm("mov.b64 %0, {%1,%2};" : "=l"(r) : "f"(x), "f"(y)); return r;
}
__device__ __forceinline__ void fma2(ull& d, ull a, ull b) {
    asm("fma.rn.f32x2 %0, %1, %2, %0;" : "+l"(d) : "l"(a), "l"(b));
}
__device__ __forceinline__ float2 upk(ull v) {
    float lo, hi; asm("mov.b64 {%0,%1}, %2;" : "=f"(lo), "=f"(hi) : "l"(v));
    float2 f; f.x = lo; f.y = hi; return f;
}

// ---------------- mma.sync helpers ----------------
__device__ __forceinline__ uint32_t smem_u32(const void* p) {
    uint32_t a;
    asm("{ .reg .u64 t; cvta.to.shared.u64 t, %1; cvt.u32.u64 %0, t; }" : "=r"(a) : "l"(p));
    return a;
}
#define LDSM4(r0, r1, r2, r3, addr) \
    asm volatile("ldmatrix.sync.aligned.m8n8.x4.shared.b16 {%0,%1,%2,%3}, [%4];" \
        : "=r"(r0), "=r"(r1), "=r"(r2), "=r"(r3) : "r"(addr))
__device__ __forceinline__ void mma_bf16_(float* d, uint32_t a0, uint32_t a1,
                                          uint32_t a2, uint32_t a3,
                                          uint32_t b0, uint32_t b1) {
    asm volatile("mma.sync.aligned.m16n8k16.row.col.f32.bf16.bf16.f32 "
        "{%0,%1,%2,%3}, {%4,%5,%6,%7}, {%8,%9}, {%0,%1,%2,%3};"
        : "+f"(d[0]), "+f"(d[1]), "+f"(d[2]), "+f"(d[3])
        : "r"(a0), "r"(a1), "r"(a2), "r"(a3), "r"(b0), "r"(b1));
}
__device__ __forceinline__ void mma_f16_(float* d, uint32_t a0, uint32_t a1,
                                         uint32_t a2, uint32_t a3,
                                         uint32_t b0, uint32_t b1) {
    asm volatile("mma.sync.aligned.m16n8k16.row.col.f32.f16.f16.f32 "
        "{%0,%1,%2,%3}, {%4,%5,%6,%7}, {%8,%9}, {%0,%1,%2,%3};"
        : "+f"(d[0]), "+f"(d[1]), "+f"(d[2]), "+f"(d[3])
        : "r"(a0), "r"(a1), "r"(a2), "r"(a3), "r"(b0), "r"(b1));
}
__device__ __forceinline__ void cp16(uint32_t dst, const void* src) {
    asm volatile("cp.async.cg.shared.global [%0], [%1], 16;" :: "r"(dst), "l"(src));
}
#define CP_COMMIT() asm volatile("cp.async.commit_group;" ::: "memory")
#define CP_WAIT(n)  asm volatile("cp.async.wait_group %0;" :: "n"(n) : "memory")

// ---------------- device scratch ----------------
__device__ float g_Gall[3*S*B*H3];      // Gx_f | Gx_b | Gd
__device__ float g_outs_f[S*B*H];
__device__ float g_outs_b[S*B*H];
__device__ float g_enc_out[S*B*H];
__device__ float g_Hdec[T*B*H];
__device__ float g_Ctx [T*B*H];
__device__ int   g_dectok[T*B];
__device__ unsigned g_bars[4];
__device__ __half g_B2o[(size_t)VOUT*H];          // Wo fp16 (single copy, K=512)
__device__ __half g_A2v[(size_t)T*B*H];           // c  fp16 (single copy, K=512)
__device__ __nv_bfloat16 g_A3e[S*B*H3];           // split enc emb (gathered)
__device__ __nv_bfloat16 g_A3d[T*B*H3];           // split dec emb (gathered)
__device__ __nv_bfloat16 g_B3f[H3*H3];            // split enc_Wih_f
__device__ __nv_bfloat16 g_B3b[H3*H3];            // split enc_Wih_b
__device__ __nv_bfloat16 g_B3d[H3*H3];            // split dec_Wih
__device__ __nv_bfloat16 g_B3c[H*3*1024];         // split Wc (K=1024)
__device__ __nv_bfloat16 g_A3c[T*B*3*1024];       // split [Hdec|Ctx]

// ---------------- grid barrier (pure L2 spin) ----------------
__device__ __forceinline__ void grid_bar(unsigned* bar, unsigned target) {
    __threadfence();
    __syncthreads();
    if (threadIdx.x == 0) {
        atomicAdd(bar, 1u);
        while (*(volatile unsigned*)bar < target) { }
        __threadfence();
    }
    __syncthreads();
}

// ---------------- fp32 -> 16-bit splits --------------------------------------
// mode 0 (A,bf16): [hi, lo, hi]  mode 1 (B,bf16): [hi, hi, lo]  (stride 3K)
// mode 2 (fp16): plain fp16 hi, single copy (stride K)
__global__ __launch_bounds__(256)
void split3_kernel(const float* __restrict__ src, const float* __restrict__ src2,
                   const int* __restrict__ gidx, __nv_bfloat16* __restrict__ dst,
                   int nrows, int K, int mode)
{
    int perrow = K >> 2;
    int idx = blockIdx.x * 256 + threadIdx.x;
    if (idx >= nrows * perrow) return;
    int row = idx / perrow, cc = (idx - row * perrow) * 4;
    const float* s;
    if (src2 && cc >= 512)      s = src2 + (size_t)row * 512 + (cc - 512);
    else if (src2)              s = src  + (size_t)row * 512 + cc;
    else if (gidx)              s = src  + (size_t)gidx[row] * K + cc;
    else                        s = src  + (size_t)row * K + cc;
    float4 v = *(const float4*)s;
    float f[4] = {v.x, v.y, v.z, v.w};

    if (mode == 2) {
        __half hh[4];
#pragma unroll
        for (int i = 0; i < 4; i++) hh[i] = __float2half_rn(f[i]);
        __half* base = ((__half*)dst) + (size_t)row * K;
        *(__half2*)(base + cc)     = __halves2half2(hh[0], hh[1]);
        *(__half2*)(base + cc + 2) = __halves2half2(hh[2], hh[3]);
        return;
    }

    __nv_bfloat16 h[4], l[4];
#pragma unroll
    for (int i = 0; i < 4; i++) {
        h[i] = __float2bfloat16(f[i]);
        l[i] = __float2bfloat16(f[i] - __bfloat162float(h[i]));
    }
    __nv_bfloat162 h01, h23, l01, l23;
    h01.x = h[0]; h01.y = h[1]; h23.x = h[2]; h23.y = h[3];
    l01.x = l[0]; l01.y = l[1]; l23.x = l[2]; l23.y = l[3];
    __nv_bfloat16* base = dst + (size_t)row * (3 * K);
    __nv_bfloat162* d0 = (__nv_bfloat162*)(base + cc);
    __nv_bfloat162* d1 = (__nv_bfloat162*)(base + K + cc);
    __nv_bfloat162* d2 = (__nv_bfloat162*)(base + 2 * K + cc);
    d0[0] = h01; d0[1] = h23;
    if (mode == 0) { d1[0] = l01; d1[1] = l23; d2[0] = h01; d2[1] = h23; }
    else           { d1[0] = h01; d1[1] = h23; d2[0] = l01; d2[1] = l23; }
}

// ---------------- mma.sync 16-bit NT GEMM (3-stage cp.async pipeline) -------
// act 0: fp32 out. act 2: tanh + plain fp16 store to outsplit (stride 512).
template<int TM, bool FP16>
__global__ __launch_bounds__(256, 2)
void gemm_mma_kernel(const __nv_bfloat16* __restrict__ A3a,
                     const __nv_bfloat16* __restrict__ A3b,
                     const __nv_bfloat16* __restrict__ B3_0,
                     const __nv_bfloat16* __restrict__ B3_1,
                     const __nv_bfloat16* __restrict__ B3_2,
                     const float* __restrict__ bias0,
                     const float* __restrict__ bias1,
                     const float* __restrict__ bias2,
                     float* __restrict__ out0, float* __restrict__ out1,
                     float* __restrict__ out2,
                     __half* __restrict__ outsplit,
                     int K3, int N, int ldc, int act)
{
    constexpr int MI = TM / 64;
    constexpr int ABYTES = TM * 128;
    constexpr int BBYTES = 128 * 128;
    constexpr int STAGE = ABYTES + BBYTES;
    extern __shared__ __align__(1024) char smem[];

    const int z = blockIdx.z;
    const __nv_bfloat16* A3 = (z == 2) ? A3b : A3a;
    const __nv_bfloat16* B3 = (z == 0) ? B3_0 : ((z == 1) ? B3_1 : B3_2);
    const float* bias = (z == 0) ? bias0 : ((z == 1) ? bias1 : bias2);
    float* out = (z == 0) ? out0 : ((z == 1) ? out1 : out2);

    const int tid  = threadIdx.x;
    const int wid  = tid >> 5;
    const int lane = tid & 31;
    const int m0 = blockIdx.x * TM;
    const int n0 = blockIdx.y * 128;
    const int warp_m = wid & 3;
    const int warp_n = wid >> 2;
    const uint32_t sb = smem_u32(smem);

    const size_t K3b = (size_t)K3 * 2;
    const char* Ag = (const char*)A3 + (size_t)m0 * K3b;
    const char* Bg = (const char*)B3 + (size_t)n0 * K3b;
    const int nkt = K3 / 64;

    float d[MI][8][4];
#pragma unroll
    for (int i = 0; i < MI; i++)
#pragma unroll
        for (int j = 0; j < 8; j++)
#pragma unroll
            for (int q = 0; q < 4; q++) d[i][j][q] = 0.f;

    const int a_rowl = lane & 15;
    const int a_cb   = lane >> 4;
    const int b_rowb = warp_n * 64 + (lane & 7) + ((lane & 16) >> 1);
    const int b_cb   = (lane >> 3) & 1;

    auto issue = [&](int kt, int slot) {
        uint32_t Ab = sb + slot * STAGE;
        uint32_t Bb = Ab + ABYTES;
#pragma unroll
        for (int j = 0; j < ABYTES / 16 / 256; j++) {
            int id = tid + j * 256;
            int r = id >> 3, c = id & 7;
            cp16(Ab + r * 128 + ((c ^ (r & 7)) << 4), Ag + (size_t)r * K3b + kt * 128 + c * 16);
        }
#pragma unroll
        for (int j = 0; j < BBYTES / 16 / 256; j++) {
            int id = tid + j * 256;
            int r = id >> 3, c = id & 7;
            cp16(Bb + r * 128 + ((c ^ (r & 7)) << 4), Bg + (size_t)r * K3b + kt * 128 + c * 16);
        }
        CP_COMMIT();
    };

    issue(0, 0);
    issue(1, 1);

    int slot = 0, slot2 = 2;
    for (int kt = 0; kt < nkt; kt++) {
        if (kt + 1 < nkt) { CP_WAIT(1); } else { CP_WAIT(0); }
        __syncthreads();
        if (kt + 2 < nkt) {
            issue(kt + 2, slot2);
            if (++slot2 == 3) slot2 = 0;
        }
        uint32_t Ab = sb + slot * STAGE;
        uint32_t Bb = Ab + ABYTES;
        if (++slot == 3) slot = 0;
#pragma unroll
        for (int kk = 0; kk < 4; kk++) {
            uint32_t af[MI][4];
            int ca = kk * 2 + a_cb;
#pragma unroll
            for (int mi = 0; mi < MI; mi++) {
                int ar = warp_m * (MI * 16) + mi * 16 + a_rowl;
                LDSM4(af[mi][0], af[mi][1], af[mi][2], af[mi][3],
                      Ab + ar * 128 + ((ca ^ (ar & 7)) << 4));
            }
            int cb = kk * 2 + b_cb;
#pragma unroll
            for (int nt = 0; nt < 4; nt++) {
                int br = b_rowb + nt * 16;
                uint32_t b0, b1, b2, b3;
                LDSM4(b0, b1, b2, b3, Bb + br * 128 + ((cb ^ (br & 7)) << 4));
#pragma unroll
                for (int mi = 0; mi < MI; mi++) {
                    if (FP16) {
                        mma_f16_(d[mi][2*nt],   af[mi][0], af[mi][1], af[mi][2], af[mi][3], b0, b1);
                        mma_f16_(d[mi][2*nt+1], af[mi][0], af[mi][1], af[mi][2], af[mi][3], b2, b3);
                    } else {
                        mma_bf16_(d[mi][2*nt],   af[mi][0], af[mi][1], af[mi][2], af[mi][3], b0, b1);
                        mma_bf16_(d[mi][2*nt+1], af[mi][0], af[mi][1], af[mi][2], af[mi][3], b2, b3);
                    }
                }
            }
        }
        __syncthreads();
    }

    // epilogue
#pragma unroll
    for (int mi = 0; mi < MI; mi++) {
        int gm = m0 + warp_m * (MI * 16) + mi * 16 + (lane >> 2);
#pragma unroll
        for (int ni = 0; ni < 8; ni++) {
            int gn = n0 + warp_n * 64 + ni * 8 + (lane & 3) * 2;
            float2 bv = *(const float2*)(bias + gn);
            float v0 = d[mi][ni][0] + bv.x, v1 = d[mi][ni][1] + bv.y;
            float v2 = d[mi][ni][2] + bv.x, v3 = d[mi][ni][3] + bv.y;
            if (act == 2) {
                v0 = tanhf(v0); v1 = tanhf(v1); v2 = tanhf(v2); v3 = tanhf(v3);
                __half* r0 = outsplit + (size_t)gm * 512;
                __half* r1 = outsplit + (size_t)(gm + 8) * 512;
                *(__half2*)(r0 + gn) = __halves2half2(__float2half_rn(v0),
                                                      __float2half_rn(v1));
                *(__half2*)(r1 + gn) = __halves2half2(__float2half_rn(v2),
                                                      __float2half_rn(v3));
            } else {
                float2 o0, o1;
                o0.x = v0; o0.y = v1; o1.x = v2; o1.y = v3;
                *(float2*)(out + (size_t)gm * ldc + gn) = o0;
                *(float2*)(out + (size_t)(gm + 8) * ldc + gn) = o1;
            }
        }
    }
}

// ---------------- persistent GRU scan (COLS h-cols per block) ---------------
struct ScanProb {
    const float* gx;
    const float* seed;
    const float* whh;
    const float* bhh;
    float*       outs;
    int          dir;
};

template<int COLS>
__global__ __launch_bounds__(256)
void gru_scan_kernel(ScanProb pa, ScanProb pb, int bpp, int nsteps,
                     unsigned* bar)
{
    constexpr int KSEG = 64 * COLS;
    constexpr int NW = 3 * COLS;
    extern __shared__ float w_s[];
    const int prob = (blockIdx.x < bpp) ? 0 : 1;
    ScanProb p = prob ? pb : pa;
    unsigned* mybar = bar + prob;
    const int blk = blockIdx.x % bpp;
    const int h0  = blk * COLS;
    const int tid = threadIdx.x;
    const int b    = tid >> 3;
    const int slot = tid & 7;
    const int col  = slot % COLS;
    const int kh   = slot / COLS;
    const int koff = kh * KSEG;

    for (int id = tid; id < NW * 128; id += 256) {
        int row = id >> 7, c4 = (id & 127) * 4;
        int g = row / COLS, cc = row % COLS;
        *(float4*)&w_s[row * 516 + c4] =
            *(const float4*)(p.whh + (size_t)(g * H + h0 + cc) * H + c4);
    }
    __syncthreads();

    const ull* wr2 = (const ull*)&w_s[col * 516 + koff];
    const ull* wz2 = (const ull*)&w_s[(COLS + col) * 516 + koff];
    const ull* wn2 = (const ull*)&w_s[(2 * COLS + col) * 516 + koff];

    const int h = h0 + col;
    const float br = p.bhh[h], bz = p.bhh[H + h], bn = p.bhh[2 * H + h];

    for (int i = 0; i < nsteps; i++) {
        const int t = p.dir ? (nsteps - 1 - i) : i;
        const float* hprev = (i == 0) ? p.seed
                           : p.outs + (size_t)(p.dir ? t + 1 : t - 1) * B * H;
        ull ar2 = 0, az2 = 0, an2 = 0;
        if (hprev) {
            const float4* hp4 = (const float4*)(hprev + b * H + koff);
#pragma unroll 8
            for (int c = 0; c < KSEG / 4; c++) {
                float4 hv = __ldg(&hp4[c]);
                ull h01 = pk2(hv.x, hv.y), h23 = pk2(hv.z, hv.w);
                fma2(ar2, h01, wr2[2*c]); fma2(ar2, h23, wr2[2*c+1]);
                fma2(az2, h01, wz2[2*c]); fma2(az2, h23, wz2[2*c+1]);
                fma2(an2, h01, wn2[2*c]); fma2(an2, h23, wn2[2*c+1]);
            }
        }
        float2 fr = upk(ar2), fz = upk(az2), fn = upk(an2);
        float ar = fr.x + fr.y, az = fz.x + fz.y, an = fn.x + fn.y;
        if (COLS == 4) {
            ar += __shfl_xor_sync(0xffffffffu, ar, 4);
            az += __shfl_xor_sync(0xffffffffu, az, 4);
            an += __shfl_xor_sync(0xffffffffu, an, 4);
        }
        if (kh == 0) {
            float hp_val = hprev ? __ldg(hprev + b * H + h) : 0.f;
            const float* gx = p.gx + ((size_t)t * B + b) * H3;
            float r = 1.f / (1.f + expf(-(gx[h]       + ar + br)));
            float z = 1.f / (1.f + expf(-(gx[H + h]   + az + bz)));
            float n = tanhf(gx[2 * H + h] + r * (an + bn));
            p.outs[((size_t)t * B + b) * H + h] = (1.f - z) * n + z * hp_val;
        }
        if (i < nsteps - 1) grid_bar(mybar, (unsigned)bpp * (unsigned)(i + 1));
    }
}

// ---------------- batched attention ----------------
__global__ __launch_bounds__(256)
void attn_kernel(const float* __restrict__ Hdec, const float* __restrict__ enc,
                 float* __restrict__ Ctx)
{
    const int t = blockIdx.x / B;
    const int b = blockIdx.x % B;
    const float* h2 = Hdec + ((size_t)t * B + b) * H;
    const int tid = threadIdx.x;
    const int lane = tid & 31, w = tid >> 5;
    __shared__ float h2_s[H];
    __shared__ float sc[S];

    h2_s[tid]       = h2[tid];
    h2_s[tid + 256] = h2[tid + 256];
    __syncthreads();

    for (int s = w; s < S; s += 8) {
        const float4* e  = (const float4*)(enc + (size_t)(s * B + b) * H);
        const float4* h4 = (const float4*)h2_s;
        float p = 0.f;
#pragma unroll
        for (int j = 0; j < 4; j++) {
            float4 ev = e[lane + j * 32];
            float4 hv = h4[lane + j * 32];
            p = fmaf(ev.x, hv.x, p); p = fmaf(ev.y, hv.y, p);
            p = fmaf(ev.z, hv.z, p); p = fmaf(ev.w, hv.w, p);
        }
#pragma unroll
        for (int o = 16; o > 0; o >>= 1) p += __shfl_xor_sync(0xffffffffu, p, o);
        if (lane == 0) sc[s] = p;
    }
    __syncthreads();

    if (w == 0) {
        float a  = sc[lane];
        float b2 = (lane < 16) ? sc[32 + lane] : -1e30f;
        float m = fmaxf(a, b2);
#pragma unroll
        for (int o = 16; o > 0; o >>= 1) m = fmaxf(m, __shfl_xor_sync(0xffffffffu, m, o));
        float ea = expf(a - m);
        float eb = (lane < 16) ? expf(b2 - m) : 0.f;
        float ss = ea + eb;
#pragma unroll
        for (int o = 16; o > 0; o >>= 1) ss += __shfl_xor_sync(0xffffffffu, ss, o);
        float inv = 1.f / ss;
        sc[lane] = ea * inv;
        if (lane < 16) sc[32 + lane] = eb * inv;
    }
    __syncthreads();

    float a0 = 0.f, a1 = 0.f;
    for (int s = 0; s < S; s++) {
        float at = sc[s];
        const float* e = enc + (size_t)(s * B + b) * H;
        a0 = fmaf(at, e[tid], a0);
        a1 = fmaf(at, e[tid + 256], a1);
    }
    float* co = Ctx + ((size_t)t * B + b) * H;
    co[tid]       = a0;
    co[tid + 256] = a1;
}

// ---------------- small utilities ----------------
__global__ void combine_kernel(float* __restrict__ out, const float* __restrict__ a,
                               const float* __restrict__ b, int n)
{
    int i = blockIdx.x * blockDim.x + threadIdx.x;
    if (i < n) out[i] = a[i] + b[i];
}

__global__ void init_kernel(int* __restrict__ out, const int* __restrict__ target,
                            unsigned* __restrict__ bars)
{
    int i = blockIdx.x * blockDim.x + threadIdx.x;
    if (i < 4) bars[i] = 0u;
    if (i < T * B) out[i] = (i < B) ? 1 /*SOS*/ : target[i - B];
}

// ---------------- launch ------------------------------------------------------
extern "C" void kernel_launch(void* const* d_in, const int* in_sizes, int n_in,
                              void* d_out, int out_size)
{
    const int*   input_batches  = (const int*)d_in[0];
    const int*   target_batches = (const int*)d_in[1];
    const float* enc_emb   = (const float*)d_in[2];
    const float* enc_Wih_f = (const float*)d_in[3];
    const float* enc_Whh_f = (const float*)d_in[4];
    const float* enc_bih_f = (const float*)d_in[5];
    const float* enc_bhh_f = (const float*)d_in[6];
    const float* enc_Wih_b = (const float*)d_in[7];
    const float* enc_Whh_b = (const float*)d_in[8];
    const float* enc_bih_b = (const float*)d_in[9];
    const float* enc_bhh_b = (const float*)d_in[10];
    const float* dec_emb   = (const float*)d_in[11];
    const float* dec_Wih   = (const float*)d_in[12];
    const float* dec_Whh   = (const float*)d_in[13];
    const float* dec_bih   = (const float*)d_in[14];
    const float* dec_bhh   = (const float*)d_in[15];
    const float* Wc        = (const float*)d_in[16];
    const float* bc        = (const float*)d_in[17];
    const float* Wo        = (const float*)d_in[18];
    const float* bo        = (const float*)d_in[19];
    float* out = (float*)d_out;

    float *Gall, *outs_f, *outs_b, *enc_out, *Hdec, *Ctx;
    int* dectok; unsigned* bars;
    __nv_bfloat16 *A3e, *A3d, *B3f, *B3b_, *B3d_, *B3c, *A3c;
    __half *A2v, *B2o;
    cudaGetSymbolAddress((void**)&Gall,   g_Gall);
    cudaGetSymbolAddress((void**)&outs_f, g_outs_f);
    cudaGetSymbolAddress((void**)&outs_b, g_outs_b);
    cudaGetSymbolAddress((void**)&enc_out,g_enc_out);
    cudaGetSymbolAddress((void**)&Hdec,   g_Hdec);
    cudaGetSymbolAddress((void**)&Ctx,    g_Ctx);
    cudaGetSymbolAddress((void**)&dectok, g_dectok);
    cudaGetSymbolAddress((void**)&bars,   g_bars);
    cudaGetSymbolAddress((void**)&A3e,    g_A3e);
    cudaGetSymbolAddress((void**)&A3d,    g_A3d);
    cudaGetSymbolAddress((void**)&B3f,    g_B3f);
    cudaGetSymbolAddress((void**)&B3b_,   g_B3b);
    cudaGetSymbolAddress((void**)&B3d_,   g_B3d);
    cudaGetSymbolAddress((void**)&B3c,    g_B3c);
    cudaGetSymbolAddress((void**)&A3c,    g_A3c);
    cudaGetSymbolAddress((void**)&A2v,    g_A2v);
    cudaGetSymbolAddress((void**)&B2o,    g_B2o);

    float* Gx_f = Gall;
    float* Gx_b = Gall + (size_t)S * B * H3;
    float* Gd   = Gall + (size_t)2 * S * B * H3;

    const int WSMEM8 = 24 * 516 * 4;
    const int WSMEM4 = 12 * 516 * 4;
    cudaFuncSetAttribute(gru_scan_kernel<8>,
                         cudaFuncAttributeMaxDynamicSharedMemorySize, WSMEM8);
    cudaFuncSetAttribute(gru_scan_kernel<4>,
                         cudaFuncAttributeMaxDynamicSharedMemorySize, WSMEM4);
    cudaFuncSetAttribute((const void*)gemm_mma_kernel<128,false>,
                         cudaFuncAttributeMaxDynamicSharedMemorySize, 98304);
    cudaFuncSetAttribute((const void*)gemm_mma_kernel<128,true>,
                         cudaFuncAttributeMaxDynamicSharedMemorySize, 98304);

    init_kernel<<<(T * B + 255) / 256, 256>>>(dectok, target_batches, bars);

    // splits
    split3_kernel<<<(S*B*128 + 255)/256, 256>>>(enc_emb, nullptr, input_batches, A3e, S*B, 512, 0);
    split3_kernel<<<(T*B*128 + 255)/256, 256>>>(dec_emb, nullptr, dectok,        A3d, T*B, 512, 0);
    split3_kernel<<<(H3*128 + 255)/256, 256>>>(enc_Wih_f, nullptr, nullptr, B3f,  H3, 512, 1);
    split3_kernel<<<(H3*128 + 255)/256, 256>>>(enc_Wih_b, nullptr, nullptr, B3b_, H3, 512, 1);
    split3_kernel<<<(H3*128 + 255)/256, 256>>>(dec_Wih,   nullptr, nullptr, B3d_, H3, 512, 1);
    split3_kernel<<<(VOUT*128 + 255)/256, 256>>>(Wo, nullptr, nullptr,
                                                 (__nv_bfloat16*)B2o, VOUT, 512, 2);
    split3_kernel<<<(H*256 + 255)/256, 256>>>(Wc, nullptr, nullptr, B3c, H, 1024, 1);

    // all three input-gate GEMMs in one launch (z selects)
    gemm_mma_kernel<128,false><<<dim3(S*B/128, H3/128, 3), 256, 98304>>>(
        A3e, A3d, B3f, B3b_, B3d_, enc_bih_f, enc_bih_b, dec_bih,
        Gx_f, Gx_b, Gd, nullptr, H3, H3, H3, 0);

    // encoder scans (fwd + bwd fused), 8 cols/block, per-problem barriers
    ScanProb pf { Gx_f, nullptr, enc_Whh_f, enc_bhh_f, outs_f, 0 };
    ScanProb pk { Gx_b, nullptr, enc_Whh_b, enc_bhh_b, outs_b, 1 };
    gru_scan_kernel<8><<<128, 256, WSMEM8>>>(pf, pk, 64, S, bars + 0);

    combine_kernel<<<(S * B * H + 255) / 256, 256>>>(enc_out, outs_f, outs_b, S * B * H);

    // decoder GRU chain, 4 cols/block + 2-way K split (128 CTAs)
    ScanProb pd { Gd, outs_f + (size_t)(S - 1) * B * H, dec_Whh, dec_bhh, Hdec, 0 };
    gru_scan_kernel<4><<<128, 256, WSMEM4>>>(pd, pd, 128, T, bars + 2);

    // batched attention
    attn_kernel<<<T * B, 256>>>(Hdec, enc_out, Ctx);

    // split [Hdec | Ctx] for the Wc GEMM
    split3_kernel<<<(T*B*256 + 255)/256, 256>>>(Hdec, Ctx, nullptr, A3c, T*B, 1024, 0);

    // c = tanh([h2,ctx] @ Wc^T + bc), fused plain-fp16 store into A2v
    gemm_mma_kernel<128,false><<<dim3(T*B/128, H/128, 1), 256, 98304>>>(
        A3c, A3c, B3c, B3c, B3c, bc, bc, bc,
        nullptr, nullptr, nullptr, A2v, 3*1024, H, H, 2);

    // vocab projection plain fp16, K=512: out = A2v @ B2o^T + bo
    gemm_mma_kernel<128,true><<<dim3(T*B/128, VOUT/128, 1), 256, 98304>>>(
        (const __nv_bfloat16*)A2v, (const __nv_bfloat16*)A2v,
        (const __nv_bfloat16*)B2o, (const __nv_bfloat16*)B2o, (const __nv_bfloat16*)B2o,
        bo, bo, bo, out, out, out, nullptr, 512, VOUT, VOUT, 0);
}